// round 3
// baseline (speedup 1.0000x reference)
#include <cuda_runtime.h>
#include <math.h>

#define BB 8
#define CC 256
#define CI 128
#define HH 64
#define WWID 64
#define NN 4096
#define NK 1024

// ---------------- scratch (device globals: allocation-free rule) ----------------
// __align__(16): we cast float4* into these.
__device__ __align__(16) float d_theta[BB * NN * CI];   // [B][N][CI]
__device__ __align__(16) float d_phi[BB * NK * CI];     // [B][Nk][CI]
__device__ __align__(16) float d_g[BB * NK * CI];       // [B][Nk][CI]
__device__ __align__(16) float d_y[BB * NN * CI];       // [B][N][CI]

// =====================================================================
// Kernel 1: fused projections theta/phi/g.  grid (32, B, 3), block 256.
// Tile: 128 pixels (2 image rows, pool-group permuted) x 128 ci, K=256.
// proj 0 = theta (full res), 1 = phi (maxpool2), 2 = g (maxpool2).
// =====================================================================
__global__ __launch_bounds__(256, 2)
void proj_kernel(const float* __restrict__ x,
                 const float* __restrict__ g_w,  const float* __restrict__ g_b,
                 const float* __restrict__ th_w, const float* __restrict__ th_b,
                 const float* __restrict__ ph_w, const float* __restrict__ ph_b)
{
    const int r    = blockIdx.x;   // row pair: image rows 2r, 2r+1
    const int b    = blockIdx.y;
    const int proj = blockIdx.z;

    const float* w;
    const float* bias;
    if (proj == 0)      { w = th_w; bias = th_b; }
    else if (proj == 1) { w = ph_w; bias = ph_b; }
    else                { w = g_w;  bias = g_b;  }

    __shared__ __align__(16) float xs[32][128];    // [k][pixel-perm]
    __shared__ __align__(16) float ws[32][132];    // [k][ci], pad 4 (132*4B = 528, 16-aligned rows)

    const int tid = threadIdx.x;
    const int ty  = tid >> 4;        // 0..15 -> pixel group
    const int tx  = tid & 15;        // 0..15 -> ci group

    float acc[8][8];
#pragma unroll
    for (int i = 0; i < 8; i++)
#pragma unroll
        for (int j = 0; j < 8; j++) acc[i][j] = 0.f;

    const float* xb = x + ((size_t)b * CC) * NN + (2 * r) * WWID;

    for (int k0 = 0; k0 < CC; k0 += 32) {
        // load x tile: 32 channels x 128 pixels, permuted so each 2x2 pool
        // group occupies 4 consecutive smem slots
#pragma unroll
        for (int i = 0; i < 16; i++) {
            int l    = tid + i * 256;
            int chn  = l >> 7;
            int p    = l & 127;
            int row  = p >> 6;
            int wcol = p & 63;
            int perm = ((wcol >> 1) << 2) | (row << 1) | (wcol & 1);
            xs[chn][perm] = xb[(size_t)(k0 + chn) * NN + row * WWID + wcol];
        }
        // load weight tile transposed: ws[k][ci]
#pragma unroll
        for (int i = 0; i < 16; i++) {
            int l  = tid + i * 256;
            int ci = l >> 5;
            int kk = l & 31;
            ws[kk][ci] = w[ci * CC + k0 + kk];
        }
        __syncthreads();

#pragma unroll
        for (int kk = 0; kk < 32; kk++) {
            float a[8], bv[8];
            *(float4*)&a[0]  = *(const float4*)&xs[kk][ty * 8];
            *(float4*)&a[4]  = *(const float4*)&xs[kk][ty * 8 + 4];
            *(float4*)&bv[0] = *(const float4*)&ws[kk][tx * 8];
            *(float4*)&bv[4] = *(const float4*)&ws[kk][tx * 8 + 4];
#pragma unroll
            for (int i = 0; i < 8; i++)
#pragma unroll
                for (int j = 0; j < 8; j++) acc[i][j] += a[i] * bv[j];
        }
        __syncthreads();
    }

    float bb[8];
    *(float4*)&bb[0] = *(const float4*)&bias[tx * 8];
    *(float4*)&bb[4] = *(const float4*)&bias[tx * 8 + 4];

    if (proj == 0) {
        // theta: full resolution, de-permute pixel index
#pragma unroll
        for (int i = 0; i < 8; i++) {
            int pm    = ty * 8 + i;
            int group = pm >> 2;
            int pos   = pm & 3;
            int row   = pos >> 1;
            int wcol  = (group << 1) | (pos & 1);
            int n     = (2 * r + row) * WWID + wcol;
            float* dst = d_theta + ((size_t)(b * NN + n)) * CI + tx * 8;
            *(float4*)dst       = make_float4(acc[i][0] + bb[0], acc[i][1] + bb[1],
                                              acc[i][2] + bb[2], acc[i][3] + bb[3]);
            *(float4*)(dst + 4) = make_float4(acc[i][4] + bb[4], acc[i][5] + bb[5],
                                              acc[i][6] + bb[6], acc[i][7] + bb[7]);
        }
    } else {
        float* basep = (proj == 1) ? d_phi : d_g;
#pragma unroll
        for (int gg = 0; gg < 2; gg++) {
            int k = r * 32 + ty * 2 + gg;   // pooled index: row r, col group
            float v[8];
#pragma unroll
            for (int j = 0; j < 8; j++) {
                float m = fmaxf(fmaxf(acc[gg * 4 + 0][j], acc[gg * 4 + 1][j]),
                                fmaxf(acc[gg * 4 + 2][j], acc[gg * 4 + 3][j]));
                v[j] = m + bb[j];   // bias constant over pool window: legal after max
            }
            float* dst = basep + ((size_t)(b * NK + k)) * CI + tx * 8;
            *(float4*)dst       = make_float4(v[0], v[1], v[2], v[3]);
            *(float4*)(dst + 4) = make_float4(v[4], v[5], v[6], v[7]);
        }
    }
}

// =====================================================================
// Kernel 2: flash attention. grid (N/64, B), block 256, dynamic smem.
// 64 queries/CTA; 16 key chunks of 64; fp32 logits; online softmax.
// QPAD=68: row stride 272 B — 16B-aligned rows for float4, bank-staggered.
// smem: qsT 128x68 + ksT 128x68 + gs 64x128 + psT 64x68  = ~119 KB
// =====================================================================
#define QPAD 68
#define ATTN_SMEM_FLOATS (128 * QPAD + 128 * QPAD + 64 * 128 + 64 * QPAD)

__global__ __launch_bounds__(256, 1)
void attn_kernel()
{
    extern __shared__ float sm[];
    float* qsT = sm;                            // [ci][q]  128 x 68
    float* ksT = qsT + 128 * QPAD;              // [ci][k]  128 x 68
    float* gs  = ksT + 128 * QPAD;              // [k][ci]  64 x 128
    float* psT = gs  + 64 * 128;                // [k][q]   64 x 68

    const int b  = blockIdx.y;
    const int q0 = blockIdx.x * 64;
    const int tid = threadIdx.x;
    const int ty = tid >> 4;    // query group (q = q0 + 4*ty + i)
    const int tx = tid & 15;    // key group / d group

    // load query tile transposed
    {
        const float* thp = d_theta + ((size_t)b * NN + q0) * CI;
#pragma unroll
        for (int i = 0; i < 32; i++) {
            int l = tid + i * 256;
            int q = l >> 7;
            int c = l & 127;
            qsT[c * QPAD + q] = thp[q * CI + c];
        }
    }

    float m_prev[4], l_run[4], yacc[4][8];
#pragma unroll
    for (int i = 0; i < 4; i++) {
        m_prev[i] = -1e30f;
        l_run[i]  = 0.f;
#pragma unroll
        for (int j = 0; j < 8; j++) yacc[i][j] = 0.f;
    }

    for (int c0 = 0; c0 < NK; c0 += 64) {
        __syncthreads();  // protect ksT/gs/psT (and qsT on first iter) before reuse
        {
            const float* php = d_phi + ((size_t)b * NK + c0) * CI;
            const float* gp  = d_g   + ((size_t)b * NK + c0) * CI;
#pragma unroll
            for (int i = 0; i < 32; i++) {
                int l = tid + i * 256;
                int k = l >> 7;
                int c = l & 127;
                ksT[c * QPAD + k] = php[k * CI + c];
                gs[k * 128 + c]   = gp[k * CI + c];
            }
        }
        __syncthreads();

        // S = theta . phi^T  (64x64, K=128)
        float s[4][4];
#pragma unroll
        for (int i = 0; i < 4; i++)
#pragma unroll
            for (int j = 0; j < 4; j++) s[i][j] = 0.f;

#pragma unroll 4
        for (int c = 0; c < 128; c++) {
            float4 a  = *(const float4*)&qsT[c * QPAD + ty * 4];
            float4 kk = *(const float4*)&ksT[c * QPAD + tx * 4];
            const float av[4] = {a.x, a.y, a.z, a.w};
            const float kv[4] = {kk.x, kk.y, kk.z, kk.w};
#pragma unroll
            for (int i = 0; i < 4; i++)
#pragma unroll
                for (int j = 0; j < 4; j++) s[i][j] += av[i] * kv[j];
        }

        // online softmax; row reduction via shuffle over the 16 tx lanes
#pragma unroll
        for (int i = 0; i < 4; i++) {
            float m = fmaxf(fmaxf(s[i][0], s[i][1]), fmaxf(s[i][2], s[i][3]));
#pragma unroll
            for (int off = 1; off < 16; off <<= 1)
                m = fmaxf(m, __shfl_xor_sync(0xffffffffu, m, off));
            float mnew  = fmaxf(m_prev[i], m);
            float scale = __expf(m_prev[i] - mnew);
            float ssum = 0.f;
#pragma unroll
            for (int j = 0; j < 4; j++) {
                s[i][j] = __expf(s[i][j] - mnew);
                ssum += s[i][j];
            }
#pragma unroll
            for (int off = 1; off < 16; off <<= 1)
                ssum += __shfl_xor_sync(0xffffffffu, ssum, off);
            l_run[i] = l_run[i] * scale + ssum;
            m_prev[i] = mnew;
#pragma unroll
            for (int j = 0; j < 8; j++) yacc[i][j] *= scale;
        }

        // store P transposed for PV gemm
#pragma unroll
        for (int j = 0; j < 4; j++)
#pragma unroll
            for (int i = 0; i < 4; i++)
                psT[(tx * 4 + j) * QPAD + ty * 4 + i] = s[i][j];
        __syncthreads();

        // y += P . g   (64q x 128d, K=64)
#pragma unroll 4
        for (int k = 0; k < 64; k++) {
            float4 p  = *(const float4*)&psT[k * QPAD + ty * 4];
            float4 g0 = *(const float4*)&gs[k * 128 + tx * 8];
            float4 g1 = *(const float4*)&gs[k * 128 + tx * 8 + 4];
            const float pv[4] = {p.x, p.y, p.z, p.w};
            const float gv[8] = {g0.x, g0.y, g0.z, g0.w, g1.x, g1.y, g1.z, g1.w};
#pragma unroll
            for (int i = 0; i < 4; i++)
#pragma unroll
                for (int j = 0; j < 8; j++) yacc[i][j] += pv[i] * gv[j];
        }
    }

    // finalize
#pragma unroll
    for (int i = 0; i < 4; i++) {
        float invl = 1.f / l_run[i];
        int q = q0 + ty * 4 + i;
        float* dst = d_y + ((size_t)b * NN + q) * CI + tx * 8;
        *(float4*)dst = make_float4(yacc[i][0] * invl, yacc[i][1] * invl,
                                    yacc[i][2] * invl, yacc[i][3] * invl);
        *(float4*)(dst + 4) = make_float4(yacc[i][4] * invl, yacc[i][5] * invl,
                                          yacc[i][6] * invl, yacc[i][7] * invl);
    }
}

// =====================================================================
// Kernel 3: z = BN(conv1x1(y, W)) + fuse, written into concat band 1.
// grid (N/64, C/64, B), block 256, dynamic smem.
// microtile: c = c0 + 4*ty + i, n = n0 + 4*tx + j  (float4 stores along n)
// =====================================================================
#define WZ_SMEM_FLOATS (128 * QPAD * 2)

__global__ __launch_bounds__(256, 2)
void wz_kernel(const float* __restrict__ fuse,
               const float* __restrict__ W_w,  const float* __restrict__ W_b,
               const float* __restrict__ gamma, const float* __restrict__ beta,
               const float* __restrict__ mean,  const float* __restrict__ var,
               float* __restrict__ out)
{
    extern __shared__ float sm2[];
    float* ysT = sm2;                 // [ci][n] 128 x 68
    float* wsT = sm2 + 128 * QPAD;    // [ci][c] 128 x 68

    const int b  = blockIdx.z;
    const int c0 = blockIdx.y * 64;
    const int n0 = blockIdx.x * 64;
    const int tid = threadIdx.x;
    const int ty = tid >> 4;
    const int tx = tid & 15;

    {
        const float* yp = d_y + ((size_t)b * NN + n0) * CI;
#pragma unroll
        for (int i = 0; i < 32; i++) {
            int l = tid + i * 256;
            int n = l >> 7;    // tile-local index (pixel for ysT, out-chan for wsT)
            int c = l & 127;   // ci
            ysT[c * QPAD + n] = yp[n * CI + c];
            wsT[c * QPAD + n] = W_w[(c0 + n) * CI + c];
        }
    }
    __syncthreads();

    float acc[4][4];
#pragma unroll
    for (int i = 0; i < 4; i++)
#pragma unroll
        for (int j = 0; j < 4; j++) acc[i][j] = 0.f;

#pragma unroll 4
    for (int c = 0; c < 128; c++) {
        float4 wv4 = *(const float4*)&wsT[c * QPAD + ty * 4];
        float4 yv4 = *(const float4*)&ysT[c * QPAD + tx * 4];
        const float wv[4] = {wv4.x, wv4.y, wv4.z, wv4.w};
        const float yv[4] = {yv4.x, yv4.y, yv4.z, yv4.w};
#pragma unroll
        for (int i = 0; i < 4; i++)
#pragma unroll
            for (int j = 0; j < 4; j++) acc[i][j] += wv[i] * yv[j];
    }

#pragma unroll
    for (int i = 0; i < 4; i++) {
        int c = c0 + ty * 4 + i;
        float inv = gamma[c] * rsqrtf(var[c] + 1e-5f);
        float be  = (W_b[c] - mean[c]) * inv + beta[c];
        const float4 f4 = *(const float4*)&fuse[((size_t)b * CC + c) * NN + n0 + tx * 4];
        float4 z;
        z.x = acc[i][0] * inv + be + f4.x;
        z.y = acc[i][1] * inv + be + f4.y;
        z.z = acc[i][2] * inv + be + f4.z;
        z.w = acc[i][3] * inv + be + f4.w;
        *(float4*)&out[((size_t)b * 768 + 256 + c) * NN + n0 + tx * 4] = z;
    }
}

// =====================================================================
// Kernel 4: copy lc / gc into concat bands 0 and 2 (float4, grid-stride).
// =====================================================================
__global__ void copy_kernel(const float4* __restrict__ lc,
                            const float4* __restrict__ gc,
                            float4* __restrict__ out)
{
    const size_t PER_B = 262144;   // float4 per (batch, 256ch, 4096px)
    const size_t TOT   = BB * PER_B;
    const size_t OUT_B = 786432;   // float4 per batch in out (768ch)
    const size_t stride = (size_t)gridDim.x * blockDim.x;
    for (size_t i = (size_t)blockIdx.x * blockDim.x + threadIdx.x;
         i < TOT; i += stride) {
        size_t bidx = i / PER_B, rem = i % PER_B;
        out[bidx * OUT_B + rem]               = lc[i];
        out[bidx * OUT_B + 2 * PER_B + rem]   = gc[i];
    }
}

// =====================================================================
extern "C" void kernel_launch(void* const* d_in, const int* in_sizes, int n_in,
                              void* d_out, int out_size)
{
    const float* lc      = (const float*)d_in[0];
    const float* fuse    = (const float*)d_in[1];
    const float* gc      = (const float*)d_in[2];
    const float* g_w     = (const float*)d_in[3];
    const float* g_b     = (const float*)d_in[4];
    const float* theta_w = (const float*)d_in[5];
    const float* theta_b = (const float*)d_in[6];
    const float* phi_w   = (const float*)d_in[7];
    const float* phi_b   = (const float*)d_in[8];
    const float* W_w     = (const float*)d_in[9];
    const float* W_b     = (const float*)d_in[10];
    const float* bn_g    = (const float*)d_in[11];
    const float* bn_b    = (const float*)d_in[12];
    const float* bn_m    = (const float*)d_in[13];
    const float* bn_v    = (const float*)d_in[14];
    float* out = (float*)d_out;

    (void)in_sizes; (void)n_in; (void)out_size;

    const int ATTN_SMEM = ATTN_SMEM_FLOATS * 4;  // ~119 KB
    const int WZ_SMEM   = WZ_SMEM_FLOATS * 4;    // ~69.6 KB
    cudaFuncSetAttribute(attn_kernel, cudaFuncAttributeMaxDynamicSharedMemorySize, ATTN_SMEM);
    cudaFuncSetAttribute(wz_kernel,   cudaFuncAttributeMaxDynamicSharedMemorySize, WZ_SMEM);

    // independent copies of lc/gc bands (pure HBM; overlaps with compute below)
    copy_kernel<<<2048, 256>>>((const float4*)lc, (const float4*)gc, (float4*)out);

    // projections
    proj_kernel<<<dim3(32, BB, 3), 256>>>(fuse, g_w, g_b, theta_w, theta_b, phi_w, phi_b);

    // attention
    attn_kernel<<<dim3(NN / 64, BB), 256, ATTN_SMEM>>>();

    // W conv + BN + residual into band 1
    wz_kernel<<<dim3(NN / 64, CC / 64, BB), 256, WZ_SMEM>>>(
        fuse, W_w, W_b, bn_g, bn_b, bn_m, bn_v, out);
}

// round 5
// speedup vs baseline: 1.2348x; 1.2348x over previous
#include <cuda_runtime.h>
#include <math.h>

#define BB 8
#define CC 256
#define CI 128
#define HH 64
#define WWID 64
#define NN 4096
#define NK 1024

typedef unsigned long long u64;

// ---------------- packed fp32x2 helpers (Blackwell FFMA2) ----------------
__device__ __forceinline__ u64 pk2(float lo, float hi) {
    u64 r; asm("mov.b64 %0, {%1, %2};" : "=l"(r) : "f"(lo), "f"(hi)); return r;
}
__device__ __forceinline__ u64 dup2(float v) { return pk2(v, v); }
__device__ __forceinline__ void up2(float& lo, float& hi, u64 v) {
    asm("mov.b64 {%0, %1}, %2;" : "=f"(lo), "=f"(hi) : "l"(v));
}
__device__ __forceinline__ void fma2(u64& d, u64 a, u64 b) {
    asm("fma.rn.f32x2 %0, %1, %2, %0;" : "+l"(d) : "l"(a), "l"(b));
}
__device__ __forceinline__ u64 mul2(u64 a, u64 b) {
    u64 d; asm("mul.rn.f32x2 %0, %1, %2;" : "=l"(d) : "l"(a), "l"(b)); return d;
}

// ---------------- scratch (device globals: allocation-free rule) ----------------
// channel-major layouts so every consumer smem-fill is coalesced + conflict-free
__device__ __align__(16) float d_theta[BB * CI * NN];   // [B][CI][N]
__device__ __align__(16) float d_phi[BB * CI * NK];     // [B][CI][Nk]
__device__ __align__(16) float d_g[BB * NK * CI];       // [B][Nk][CI]
__device__ __align__(16) float d_y[BB * CI * NN];       // [B][CI][N]
__device__ __align__(16) float d_wT[CI * CC];           // [CI][C]  (W_w transposed)

// =====================================================================
// Kernel 0: transpose W_w [C][CI] -> d_wT [CI][C].  Tiny (32K floats).
// =====================================================================
__global__ void wt_kernel(const float* __restrict__ Ww)
{
    int idx = blockIdx.x * 256 + threadIdx.x;   // 8192 float4 reads
    if (idx < CC * (CI / 4)) {
        int c  = idx >> 5;          // 0..255
        int g4 = idx & 31;          // ci group
        float4 v = ((const float4*)Ww)[idx];
        int ci = g4 * 4;
        d_wT[(ci + 0) * CC + c] = v.x;
        d_wT[(ci + 1) * CC + c] = v.y;
        d_wT[(ci + 2) * CC + c] = v.z;
        d_wT[(ci + 3) * CC + c] = v.w;
    }
}

// =====================================================================
// Kernel 1: fused projections theta/phi/g.  grid (32, B, 3), block 256.
// Tile: 128 pixels (2 image rows, pool-group permuted) x 128 ci, K=256.
// proj 0 = theta (c-major out), 1 = phi (pooled, c-major out),
// proj 2 = g (pooled, k-major out).
// Microtile 8px x 8ci; ci split lo(tx*4+j) / hi(64+tx*4+j) for 16B lane stride.
// =====================================================================
__global__ __launch_bounds__(256, 2)
void proj_kernel(const float* __restrict__ x,
                 const float* __restrict__ g_w,  const float* __restrict__ g_b,
                 const float* __restrict__ th_w, const float* __restrict__ th_b,
                 const float* __restrict__ ph_w, const float* __restrict__ ph_b)
{
    const int r    = blockIdx.x;   // row pair: image rows 2r, 2r+1
    const int b    = blockIdx.y;
    const int proj = blockIdx.z;

    const float* w;
    const float* bias;
    if (proj == 0)      { w = th_w; bias = th_b; }
    else if (proj == 1) { w = ph_w; bias = ph_b; }
    else                { w = g_w;  bias = g_b;  }

    // pool: mainloop uses xs(32x128=4096) + ws(32x132=4224); staging needs 64x132=8448
    __shared__ __align__(16) float pool[8448];
    float* xs = pool;                // [k][pixel-perm]  32 x 128
    float* ws = pool + 4096;         // [k][ci]          32 x 132

    const int tid = threadIdx.x;
    const int ty  = tid >> 4;        // 0..15 -> pixel group (8 px each)
    const int tx  = tid & 15;        // 0..15 -> ci group (4 lo + 4 hi)

    u64 acc2[8][4];
#pragma unroll
    for (int i = 0; i < 8; i++)
#pragma unroll
        for (int j = 0; j < 4; j++) acc2[i][j] = 0ull;

    const float* xb = x + ((size_t)b * CC) * NN + (2 * r) * WWID;

    for (int k0 = 0; k0 < CC; k0 += 32) {
        // x tile: 32 channels x 128 pixels, pool-group permuted
#pragma unroll
        for (int i = 0; i < 16; i++) {
            int l    = tid + i * 256;
            int chn  = l >> 7;
            int p    = l & 127;
            int row  = p >> 6;
            int wcol = p & 63;
            int perm = ((wcol >> 1) << 2) | (row << 1) | (wcol & 1);
            xs[chn * 128 + perm] = xb[(size_t)(k0 + chn) * NN + row * WWID + wcol];
        }
        // weight tile transposed: ws[k][ci]
#pragma unroll
        for (int i = 0; i < 16; i++) {
            int l  = tid + i * 256;
            int ci = l >> 5;
            int kk = l & 31;
            ws[kk * 132 + ci] = w[ci * CC + k0 + kk];
        }
        __syncthreads();

#pragma unroll
        for (int kk = 0; kk < 32; kk++) {
            float a[8];
            *(float4*)&a[0] = *(const float4*)&xs[kk * 128 + ty * 8];
            *(float4*)&a[4] = *(const float4*)&xs[kk * 128 + ty * 8 + 4];
            float4 blo = *(const float4*)&ws[kk * 132 + tx * 4];
            float4 bhi = *(const float4*)&ws[kk * 132 + 64 + tx * 4];
            u64 bp[4] = {pk2(blo.x, blo.y), pk2(blo.z, blo.w),
                         pk2(bhi.x, bhi.y), pk2(bhi.z, bhi.w)};
#pragma unroll
            for (int i = 0; i < 8; i++) {
                u64 ad = dup2(a[i]);
#pragma unroll
                for (int j = 0; j < 4; j++) fma2(acc2[i][j], ad, bp[j]);
            }
        }
        __syncthreads();
    }

    // unpack: accf[i][j] j<4 -> ci = tx*4+j ; j>=4 -> ci = 64+tx*4+(j-4)
    float accf[8][8];
#pragma unroll
    for (int i = 0; i < 8; i++) {
        up2(accf[i][0], accf[i][1], acc2[i][0]);
        up2(accf[i][2], accf[i][3], acc2[i][1]);
        up2(accf[i][4], accf[i][5], acc2[i][2]);
        up2(accf[i][6], accf[i][7], acc2[i][3]);
    }

    float blov[4], bhiv[4];
    *(float4*)blov = *(const float4*)&bias[tx * 4];
    *(float4*)bhiv = *(const float4*)&bias[64 + tx * 4];

    if (proj == 0) {
        // theta -> c-major via smem staging, de-permuted, two ci halves
#pragma unroll
        for (int h = 0; h < 2; h++) {
            __syncthreads();
            const float* bv = h ? bhiv : blov;
#pragma unroll
            for (int i = 0; i < 8; i++) {
                int pm    = ty * 8 + i;
                int group = pm >> 2;
                int pos   = pm & 3;
                int nl    = ((pos >> 1) << 6) | (group << 1) | (pos & 1); // row*64+col
#pragma unroll
                for (int j = 0; j < 4; j++)
                    pool[(tx * 4 + j) * 132 + nl] = accf[i][h * 4 + j] + bv[j];
            }
            __syncthreads();
            // write out 64 ci-rows x 128 px, float4 coalesced
            float* dstb = d_theta + ((size_t)b * CI + h * 64) * NN + (2 * r) * WWID;
#pragma unroll
            for (int p = 0; p < 8; p++) {
                int idx = p * 256 + tid;
                int cil = idx >> 5;
                int p4  = idx & 31;
                *(float4*)&dstb[(size_t)cil * NN + p4 * 4] =
                    *(const float4*)&pool[cil * 132 + p4 * 4];
            }
        }
    } else if (proj == 1) {
        // phi: pool then stage [ci][k_local] (128 x 36), write c-major
        __syncthreads();
#pragma unroll
        for (int gg = 0; gg < 2; gg++) {
            int kl = ty * 2 + gg;
#pragma unroll
            for (int j = 0; j < 4; j++) {
                float mlo = fmaxf(fmaxf(accf[gg*4+0][j],   accf[gg*4+1][j]),
                                  fmaxf(accf[gg*4+2][j],   accf[gg*4+3][j]));
                float mhi = fmaxf(fmaxf(accf[gg*4+0][4+j], accf[gg*4+1][4+j]),
                                  fmaxf(accf[gg*4+2][4+j], accf[gg*4+3][4+j]));
                pool[(tx * 4 + j) * 36 + kl]      = mlo + blov[j];
                pool[(64 + tx * 4 + j) * 36 + kl] = mhi + bhiv[j];
            }
        }
        __syncthreads();
        // 128 ci x 32 k = 1024 float4
        float* dstb = d_phi + (size_t)b * CI * NK + r * 32;
#pragma unroll
        for (int p = 0; p < 4; p++) {
            int idx = p * 256 + tid;
            int ci  = idx >> 3;
            int k4  = idx & 7;
            *(float4*)&dstb[(size_t)ci * NK + k4 * 4] =
                *(const float4*)&pool[ci * 36 + k4 * 4];
        }
    } else {
        // g: pooled, k-major direct float4 stores
#pragma unroll
        for (int gg = 0; gg < 2; gg++) {
            int k = r * 32 + ty * 2 + gg;
            float vlo[4], vhi[4];
#pragma unroll
            for (int j = 0; j < 4; j++) {
                vlo[j] = fmaxf(fmaxf(accf[gg*4+0][j],   accf[gg*4+1][j]),
                               fmaxf(accf[gg*4+2][j],   accf[gg*4+3][j])) + blov[j];
                vhi[j] = fmaxf(fmaxf(accf[gg*4+0][4+j], accf[gg*4+1][4+j]),
                               fmaxf(accf[gg*4+2][4+j], accf[gg*4+3][4+j])) + bhiv[j];
            }
            float* dst = d_g + ((size_t)(b * NK + k)) * CI;
            *(float4*)&dst[tx * 4]      = *(float4*)vlo;
            *(float4*)&dst[64 + tx * 4] = *(float4*)vhi;
        }
    }
}

// =====================================================================
// Kernel 2: flash attention. grid (N/64, B), block 256, dynamic smem.
// 64 queries/CTA; 8 key chunks of 128; fp32 logits; online softmax.
// Microtiles: S 4q x 8k, PV 4q x 8d; all lane strides 16B (conflict-free).
// smem: qsT 128x68 + ksT 128x132 + gs 128x128 + psT 128x68 = 202,752 B
// =====================================================================
#define ATTN_SMEM_BYTES ((128*68 + 128*132 + 128*128 + 128*68) * 4)

__global__ __launch_bounds__(256, 1)
void attn_kernel()
{
    extern __shared__ float sm[];
    float* qsT = sm;                    // [c][q]   128 x 68
    float* ksT = qsT + 128 * 68;        // [c][k]   128 x 132
    float* gs  = ksT + 128 * 132;       // [k][d]   128 x 128
    float* psT = gs  + 128 * 128;       // [k][q]   128 x 68   (also y-staging)

    const int b  = blockIdx.y;
    const int q0 = blockIdx.x * 64;
    const int tid = threadIdx.x;
    const int ty = tid >> 4;    // query group (q = q0 + 4*ty + i)
    const int tx = tid & 15;    // k/d group: lo tx*4+j, hi 64+tx*4+j

    // load query tile [c][q] from c-major theta: coalesced, conflict-free
    {
        const float* thp = d_theta + (size_t)b * CI * NN + q0;
#pragma unroll
        for (int p = 0; p < 8; p++) {
            int idx = p * 256 + tid;
            int c   = idx >> 4;
            int q4  = idx & 15;
            *(float4*)&qsT[c * 68 + q4 * 4] =
                *(const float4*)&thp[(size_t)c * NN + q4 * 4];
        }
    }

    float m_prev[4], l_run[4];
    u64 yacc2[4][4];
#pragma unroll
    for (int i = 0; i < 4; i++) {
        m_prev[i] = -1e30f;
        l_run[i]  = 0.f;
#pragma unroll
        for (int j = 0; j < 4; j++) yacc2[i][j] = 0ull;
    }

    for (int c0 = 0; c0 < NK; c0 += 128) {
        __syncthreads();  // protect ksT/gs/psT before refill
        {
            const float* php = d_phi + (size_t)b * CI * NK + c0;
            const float* gp  = d_g + ((size_t)b * NK + c0) * CI;
#pragma unroll
            for (int p = 0; p < 16; p++) {
                int idx = p * 256 + tid;
                int rr  = idx >> 5;
                int c4  = idx & 31;
                *(float4*)&ksT[rr * 132 + c4 * 4] =
                    *(const float4*)&php[(size_t)rr * NK + c4 * 4];
                *(float4*)&gs[rr * 128 + c4 * 4] =
                    *(const float4*)&gp[(size_t)rr * CI + c4 * 4];
            }
        }
        __syncthreads();

        // S = theta . phi^T  (64q x 128k, K=128)
        u64 s2[4][4];
#pragma unroll
        for (int i = 0; i < 4; i++)
#pragma unroll
            for (int j = 0; j < 4; j++) s2[i][j] = 0ull;

#pragma unroll 2
        for (int c = 0; c < 128; c++) {
            float4 a   = *(const float4*)&qsT[c * 68 + ty * 4];
            float4 klo = *(const float4*)&ksT[c * 132 + tx * 4];
            float4 khi = *(const float4*)&ksT[c * 132 + 64 + tx * 4];
            u64 kp[4] = {pk2(klo.x, klo.y), pk2(klo.z, klo.w),
                         pk2(khi.x, khi.y), pk2(khi.z, khi.w)};
            const float av[4] = {a.x, a.y, a.z, a.w};
#pragma unroll
            for (int i = 0; i < 4; i++) {
                u64 ad = dup2(av[i]);
#pragma unroll
                for (int j = 0; j < 4; j++) fma2(s2[i][j], ad, kp[j]);
            }
        }

        // online softmax (rows spread over 16 tx lanes)
#pragma unroll
        for (int i = 0; i < 4; i++) {
            float s[8];
            up2(s[0], s[1], s2[i][0]); up2(s[2], s[3], s2[i][1]);
            up2(s[4], s[5], s2[i][2]); up2(s[6], s[7], s2[i][3]);
            float m = s[0];
#pragma unroll
            for (int j = 1; j < 8; j++) m = fmaxf(m, s[j]);
#pragma unroll
            for (int off = 1; off < 16; off <<= 1)
                m = fmaxf(m, __shfl_xor_sync(0xffffffffu, m, off));
            float mnew  = fmaxf(m_prev[i], m);
            float scale = __expf(m_prev[i] - mnew);
            float ssum = 0.f;
#pragma unroll
            for (int j = 0; j < 8; j++) {
                s[j] = __expf(s[j] - mnew);
                ssum += s[j];
            }
#pragma unroll
            for (int off = 1; off < 16; off <<= 1)
                ssum += __shfl_xor_sync(0xffffffffu, ssum, off);
            l_run[i] = l_run[i] * scale + ssum;
            m_prev[i] = mnew;
            u64 sd = dup2(scale);
#pragma unroll
            for (int j = 0; j < 4; j++) yacc2[i][j] = mul2(yacc2[i][j], sd);
            // store P transposed: k-lo and k-hi halves
            int q = ty * 4 + i;
#pragma unroll
            for (int j = 0; j < 4; j++) {
                psT[(tx * 4 + j) * 68 + q]      = s[j];
                psT[(64 + tx * 4 + j) * 68 + q] = s[4 + j];
            }
        }
        __syncthreads();

        // y += P . g   (64q x 128d, K=128)
#pragma unroll 2
        for (int k = 0; k < 128; k++) {
            float4 p   = *(const float4*)&psT[k * 68 + ty * 4];
            float4 glo = *(const float4*)&gs[k * 128 + tx * 4];
            float4 ghi = *(const float4*)&gs[k * 128 + 64 + tx * 4];
            u64 gp4[4] = {pk2(glo.x, glo.y), pk2(glo.z, glo.w),
                          pk2(ghi.x, ghi.y), pk2(ghi.z, ghi.w)};
            const float pv[4] = {p.x, p.y, p.z, p.w};
#pragma unroll
            for (int i = 0; i < 4; i++) {
                u64 pd = dup2(pv[i]);
#pragma unroll
                for (int j = 0; j < 4; j++) fma2(yacc2[i][j], pd, gp4[j]);
            }
        }
    }

    // finalize: normalize, stage [d][q] in psT, write c-major d_y coalesced
    __syncthreads();
#pragma unroll
    for (int i = 0; i < 4; i++) {
        float invl = 1.f / l_run[i];
        int q = ty * 4 + i;
        float y[8];
        up2(y[0], y[1], yacc2[i][0]); up2(y[2], y[3], yacc2[i][1]);
        up2(y[4], y[5], yacc2[i][2]); up2(y[6], y[7], yacc2[i][3]);
#pragma unroll
        for (int j = 0; j < 4; j++) {
            psT[(tx * 4 + j) * 68 + q]      = y[j] * invl;
            psT[(64 + tx * 4 + j) * 68 + q] = y[4 + j] * invl;
        }
    }
    __syncthreads();
    {
        float* yp = d_y + (size_t)b * CI * NN + q0;
#pragma unroll
        for (int p = 0; p < 8; p++) {
            int idx = p * 256 + tid;
            int d   = idx >> 4;
            int q4  = idx & 15;
            *(float4*)&yp[(size_t)d * NN + q4 * 4] =
                *(const float4*)&psT[d * 68 + q4 * 4];
        }
    }
}

// =====================================================================
// Kernel 3: z = BN(conv1x1(y, W)) + fuse -> concat band 1.
// grid (N/128, C/128, B), block 256.  Tile 128c x 128n, K=128 by 32.
// Microtile 8c x 8n; c/n split lo/hi for 16B lane strides.
// =====================================================================
__global__ __launch_bounds__(256, 2)
void wz_kernel(const float* __restrict__ fuse,
               const float* __restrict__ W_b,
               const float* __restrict__ gamma, const float* __restrict__ beta,
               const float* __restrict__ mean,  const float* __restrict__ var,
               float* __restrict__ out)
{
    __shared__ __align__(16) float ys[32 * 132];   // [ci][n]
    __shared__ __align__(16) float wsm[32 * 132];  // [ci][c]

    const int b  = blockIdx.z;
    const int c0 = blockIdx.y * 128;
    const int n0 = blockIdx.x * 128;
    const int tid = threadIdx.x;
    const int ty = tid >> 4;   // c group
    const int tx = tid & 15;   // n group

    u64 acc2[8][4];
#pragma unroll
    for (int i = 0; i < 8; i++)
#pragma unroll
        for (int j = 0; j < 4; j++) acc2[i][j] = 0ull;

    for (int k0 = 0; k0 < CI; k0 += 32) {
        __syncthreads();
#pragma unroll
        for (int p = 0; p < 4; p++) {
            int idx = p * 256 + tid;
            int ci  = idx >> 5;
            int g4  = idx & 31;
            *(float4*)&ys[ci * 132 + g4 * 4] =
                *(const float4*)&d_y[((size_t)b * CI + k0 + ci) * NN + n0 + g4 * 4];
            *(float4*)&wsm[ci * 132 + g4 * 4] =
                *(const float4*)&d_wT[(size_t)(k0 + ci) * CC + c0 + g4 * 4];
        }
        __syncthreads();

#pragma unroll
        for (int cc = 0; cc < 32; cc++) {
            float4 wlo = *(const float4*)&wsm[cc * 132 + ty * 4];
            float4 whi = *(const float4*)&wsm[cc * 132 + 64 + ty * 4];
            float4 ylo = *(const float4*)&ys[cc * 132 + tx * 4];
            float4 yhi = *(const float4*)&ys[cc * 132 + 64 + tx * 4];
            u64 yp[4] = {pk2(ylo.x, ylo.y), pk2(ylo.z, ylo.w),
                         pk2(yhi.x, yhi.y), pk2(yhi.z, yhi.w)};
            const float wv[8] = {wlo.x, wlo.y, wlo.z, wlo.w,
                                 whi.x, whi.y, whi.z, whi.w};
#pragma unroll
            for (int i = 0; i < 8; i++) {
                u64 wd = dup2(wv[i]);
#pragma unroll
                for (int j = 0; j < 4; j++) fma2(acc2[i][j], wd, yp[j]);
            }
        }
    }

#pragma unroll
    for (int i = 0; i < 8; i++) {
        int c = c0 + ((i < 4) ? (ty * 4 + i) : (64 + ty * 4 + i - 4));
        float inv = gamma[c] * rsqrtf(var[c] + 1e-5f);
        float be  = (W_b[c] - mean[c]) * inv + beta[c];
        float a[8];
        up2(a[0], a[1], acc2[i][0]); up2(a[2], a[3], acc2[i][1]);
        up2(a[4], a[5], acc2[i][2]); up2(a[6], a[7], acc2[i][3]);
        const float* fr = &fuse[((size_t)b * CC + c) * NN + n0];
        float* orow = &out[((size_t)b * 768 + 256 + c) * NN + n0];
        float4 f0 = *(const float4*)&fr[tx * 4];
        float4 f1 = *(const float4*)&fr[64 + tx * 4];
        *(float4*)&orow[tx * 4] = make_float4(a[0]*inv + be + f0.x, a[1]*inv + be + f0.y,
                                              a[2]*inv + be + f0.z, a[3]*inv + be + f0.w);
        *(float4*)&orow[64 + tx * 4] = make_float4(a[4]*inv + be + f1.x, a[5]*inv + be + f1.y,
                                                   a[6]*inv + be + f1.z, a[7]*inv + be + f1.w);
    }
}

// =====================================================================
// Kernel 4: copy lc / gc into concat bands 0 and 2 (float4, grid-stride).
// =====================================================================
__global__ void copy_kernel(const float4* __restrict__ lc,
                            const float4* __restrict__ gc,
                            float4* __restrict__ out)
{
    const size_t PER_B = 262144;   // float4 per (batch, 256ch, 4096px)
    const size_t TOT   = BB * PER_B;
    const size_t OUT_B = 786432;   // float4 per batch in out (768ch)
    const size_t stride = (size_t)gridDim.x * blockDim.x;
    for (size_t i = (size_t)blockIdx.x * blockDim.x + threadIdx.x;
         i < TOT; i += stride) {
        size_t bidx = i / PER_B, rem = i % PER_B;
        out[bidx * OUT_B + rem]             = lc[i];
        out[bidx * OUT_B + 2 * PER_B + rem] = gc[i];
    }
}

// =====================================================================
extern "C" void kernel_launch(void* const* d_in, const int* in_sizes, int n_in,
                              void* d_out, int out_size)
{
    const float* lc      = (const float*)d_in[0];
    const float* fuse    = (const float*)d_in[1];
    const float* gc      = (const float*)d_in[2];
    const float* g_w     = (const float*)d_in[3];
    const float* g_b     = (const float*)d_in[4];
    const float* theta_w = (const float*)d_in[5];
    const float* theta_b = (const float*)d_in[6];
    const float* phi_w   = (const float*)d_in[7];
    const float* phi_b   = (const float*)d_in[8];
    const float* W_w     = (const float*)d_in[9];
    const float* W_b     = (const float*)d_in[10];
    const float* bn_g    = (const float*)d_in[11];
    const float* bn_b    = (const float*)d_in[12];
    const float* bn_m    = (const float*)d_in[13];
    const float* bn_v    = (const float*)d_in[14];
    float* out = (float*)d_out;

    (void)in_sizes; (void)n_in; (void)out_size;

    cudaFuncSetAttribute(attn_kernel, cudaFuncAttributeMaxDynamicSharedMemorySize,
                         ATTN_SMEM_BYTES);

    // W transpose (tiny) + lc/gc band copies
    wt_kernel<<<32, 256>>>(W_w);
    copy_kernel<<<2048, 256>>>((const float4*)lc, (const float4*)gc, (float4*)out);

    // projections
    proj_kernel<<<dim3(32, BB, 3), 256>>>(fuse, g_w, g_b, theta_w, theta_b, phi_w, phi_b);

    // attention
    attn_kernel<<<dim3(NN / 64, BB), 256, ATTN_SMEM_BYTES>>>();

    // W conv + BN + residual into band 1
    wz_kernel<<<dim3(NN / 128, CC / 128, BB), 256>>>(
        fuse, W_b, bn_g, bn_b, bn_m, bn_v, out);
}

// round 6
// speedup vs baseline: 1.4083x; 1.1405x over previous
#include <cuda_runtime.h>
#include <math.h>

#define BB 8
#define CC 256
#define CI 128
#define HH 64
#define WWID 64
#define NN 4096
#define NK 1024

typedef unsigned long long u64;

// ---------------- packed fp32x2 helpers (Blackwell FFMA2) ----------------
__device__ __forceinline__ u64 pk2(float lo, float hi) {
    u64 r; asm("mov.b64 %0, {%1, %2};" : "=l"(r) : "f"(lo), "f"(hi)); return r;
}
__device__ __forceinline__ u64 dup2(float v) { return pk2(v, v); }
__device__ __forceinline__ void up2(float& lo, float& hi, u64 v) {
    asm("mov.b64 {%0, %1}, %2;" : "=f"(lo), "=f"(hi) : "l"(v));
}
__device__ __forceinline__ void fma2(u64& d, u64 a, u64 b) {
    asm("fma.rn.f32x2 %0, %1, %2, %0;" : "+l"(d) : "l"(a), "l"(b));
}
__device__ __forceinline__ u64 mul2(u64 a, u64 b) {
    u64 d; asm("mul.rn.f32x2 %0, %1, %2;" : "=l"(d) : "l"(a), "l"(b)); return d;
}

// ---------------- scratch (device globals: allocation-free rule) ----------------
__device__ __align__(16) float d_theta[BB * CI * NN];   // [B][CI][N]   c-major
__device__ __align__(16) float d_phi[BB * CI * NK];     // [B][CI][Nk]  c-major
__device__ __align__(16) float d_g[BB * NK * CI];       // [B][Nk][CI]  k-major
__device__ __align__(16) float d_y[BB * NN * CI];       // [B][N][CI]   n-major
__device__ __align__(16) float d_wT[CI * CC];           // [CI][C]  (W_w transposed)

// =====================================================================
// Kernel 0: transpose W_w [C][CI] -> d_wT [CI][C].  Tiny (32K floats).
// =====================================================================
__global__ void wt_kernel(const float* __restrict__ Ww)
{
    int idx = blockIdx.x * 256 + threadIdx.x;   // 8192 float4 reads
    if (idx < CC * (CI / 4)) {
        int c  = idx >> 5;          // 0..255
        int g4 = idx & 31;          // ci group
        float4 v = ((const float4*)Ww)[idx];
        int ci = g4 * 4;
        d_wT[(ci + 0) * CC + c] = v.x;
        d_wT[(ci + 1) * CC + c] = v.y;
        d_wT[(ci + 2) * CC + c] = v.z;
        d_wT[(ci + 3) * CC + c] = v.w;
    }
}

// =====================================================================
// Kernel 1: fused projections theta/phi/g.  grid (32, B, 3), block 256.
// (unchanged from R5 — verified correct; leave untouched this round)
// =====================================================================
__global__ __launch_bounds__(256, 2)
void proj_kernel(const float* __restrict__ x,
                 const float* __restrict__ g_w,  const float* __restrict__ g_b,
                 const float* __restrict__ th_w, const float* __restrict__ th_b,
                 const float* __restrict__ ph_w, const float* __restrict__ ph_b)
{
    const int r    = blockIdx.x;
    const int b    = blockIdx.y;
    const int proj = blockIdx.z;

    const float* w;
    const float* bias;
    if (proj == 0)      { w = th_w; bias = th_b; }
    else if (proj == 1) { w = ph_w; bias = ph_b; }
    else                { w = g_w;  bias = g_b;  }

    __shared__ __align__(16) float pool[8448];
    float* xs = pool;                // [k][pixel-perm]  32 x 128
    float* ws = pool + 4096;         // [k][ci]          32 x 132

    const int tid = threadIdx.x;
    const int ty  = tid >> 4;
    const int tx  = tid & 15;

    u64 acc2[8][4];
#pragma unroll
    for (int i = 0; i < 8; i++)
#pragma unroll
        for (int j = 0; j < 4; j++) acc2[i][j] = 0ull;

    const float* xb = x + ((size_t)b * CC) * NN + (2 * r) * WWID;

    for (int k0 = 0; k0 < CC; k0 += 32) {
#pragma unroll
        for (int i = 0; i < 16; i++) {
            int l    = tid + i * 256;
            int chn  = l >> 7;
            int p    = l & 127;
            int row  = p >> 6;
            int wcol = p & 63;
            int perm = ((wcol >> 1) << 2) | (row << 1) | (wcol & 1);
            xs[chn * 128 + perm] = xb[(size_t)(k0 + chn) * NN + row * WWID + wcol];
        }
#pragma unroll
        for (int i = 0; i < 16; i++) {
            int l  = tid + i * 256;
            int ci = l >> 5;
            int kk = l & 31;
            ws[kk * 132 + ci] = w[ci * CC + k0 + kk];
        }
        __syncthreads();

#pragma unroll
        for (int kk = 0; kk < 32; kk++) {
            float a[8];
            *(float4*)&a[0] = *(const float4*)&xs[kk * 128 + ty * 8];
            *(float4*)&a[4] = *(const float4*)&xs[kk * 128 + ty * 8 + 4];
            float4 blo = *(const float4*)&ws[kk * 132 + tx * 4];
            float4 bhi = *(const float4*)&ws[kk * 132 + 64 + tx * 4];
            u64 bp[4] = {pk2(blo.x, blo.y), pk2(blo.z, blo.w),
                         pk2(bhi.x, bhi.y), pk2(bhi.z, bhi.w)};
#pragma unroll
            for (int i = 0; i < 8; i++) {
                u64 ad = dup2(a[i]);
#pragma unroll
                for (int j = 0; j < 4; j++) fma2(acc2[i][j], ad, bp[j]);
            }
        }
        __syncthreads();
    }

    float accf[8][8];
#pragma unroll
    for (int i = 0; i < 8; i++) {
        up2(accf[i][0], accf[i][1], acc2[i][0]);
        up2(accf[i][2], accf[i][3], acc2[i][1]);
        up2(accf[i][4], accf[i][5], acc2[i][2]);
        up2(accf[i][6], accf[i][7], acc2[i][3]);
    }

    float blov[4], bhiv[4];
    *(float4*)blov = *(const float4*)&bias[tx * 4];
    *(float4*)bhiv = *(const float4*)&bias[64 + tx * 4];

    if (proj == 0) {
#pragma unroll
        for (int h = 0; h < 2; h++) {
            __syncthreads();
            const float* bv = h ? bhiv : blov;
#pragma unroll
            for (int i = 0; i < 8; i++) {
                int pm    = ty * 8 + i;
                int group = pm >> 2;
                int pos   = pm & 3;
                int nl    = ((pos >> 1) << 6) | (group << 1) | (pos & 1);
#pragma unroll
                for (int j = 0; j < 4; j++)
                    pool[(tx * 4 + j) * 132 + nl] = accf[i][h * 4 + j] + bv[j];
            }
            __syncthreads();
            float* dstb = d_theta + ((size_t)b * CI + h * 64) * NN + (2 * r) * WWID;
#pragma unroll
            for (int p = 0; p < 8; p++) {
                int idx = p * 256 + tid;
                int cil = idx >> 5;
                int p4  = idx & 31;
                *(float4*)&dstb[(size_t)cil * NN + p4 * 4] =
                    *(const float4*)&pool[cil * 132 + p4 * 4];
            }
        }
    } else if (proj == 1) {
        __syncthreads();
#pragma unroll
        for (int gg = 0; gg < 2; gg++) {
            int kl = ty * 2 + gg;
#pragma unroll
            for (int j = 0; j < 4; j++) {
                float mlo = fmaxf(fmaxf(accf[gg*4+0][j],   accf[gg*4+1][j]),
                                  fmaxf(accf[gg*4+2][j],   accf[gg*4+3][j]));
                float mhi = fmaxf(fmaxf(accf[gg*4+0][4+j], accf[gg*4+1][4+j]),
                                  fmaxf(accf[gg*4+2][4+j], accf[gg*4+3][4+j]));
                pool[(tx * 4 + j) * 36 + kl]      = mlo + blov[j];
                pool[(64 + tx * 4 + j) * 36 + kl] = mhi + bhiv[j];
            }
        }
        __syncthreads();
        float* dstb = d_phi + (size_t)b * CI * NK + r * 32;
#pragma unroll
        for (int p = 0; p < 4; p++) {
            int idx = p * 256 + tid;
            int ci  = idx >> 3;
            int k4  = idx & 7;
            *(float4*)&dstb[(size_t)ci * NK + k4 * 4] =
                *(const float4*)&pool[ci * 36 + k4 * 4];
        }
    } else {
#pragma unroll
        for (int gg = 0; gg < 2; gg++) {
            int k = r * 32 + ty * 2 + gg;
            float vlo[4], vhi[4];
#pragma unroll
            for (int j = 0; j < 4; j++) {
                vlo[j] = fmaxf(fmaxf(accf[gg*4+0][j],   accf[gg*4+1][j]),
                               fmaxf(accf[gg*4+2][j],   accf[gg*4+3][j])) + blov[j];
                vhi[j] = fmaxf(fmaxf(accf[gg*4+0][4+j], accf[gg*4+1][4+j]),
                               fmaxf(accf[gg*4+2][4+j], accf[gg*4+3][4+j])) + bhiv[j];
            }
            float* dst = d_g + ((size_t)(b * NK + k)) * CI;
            *(float4*)&dst[tx * 4]      = *(float4*)vlo;
            *(float4*)&dst[64 + tx * 4] = *(float4*)vhi;
        }
    }
}

// =====================================================================
// Kernel 2: flash attention v2.  grid (N/64, B), block 256, 2 CTAs/SM.
// 64 q/CTA; 16 key chunks of 64.  S microtile 4q x 4k; PV 4q x 8d.
// P stored q-major (float4, conflict-free); y written straight to global.
// smem: qsT 128x64 + ksT 128x64 + gs 64x128 + psQ 64x64 = 114688 B
// =====================================================================
#define ATTN_SMEM_BYTES ((128*64 + 128*64 + 64*128 + 64*64) * 4)

__global__ __launch_bounds__(256, 2)
void attn_kernel()
{
    extern __shared__ float sm[];
    float* qsT = sm;                  // [c][q]  128 x 64
    float* ksT = qsT + 128 * 64;      // [c][k]  128 x 64
    float* gs  = ksT + 128 * 64;      // [k][d]  64 x 128
    float* psQ = gs  + 64 * 128;      // [q][k]  64 x 64

    const int b  = blockIdx.y;
    const int q0 = blockIdx.x * 64;
    const int tid = threadIdx.x;
    const int ty = tid >> 4;    // query group: q = q0 + 4*ty + i
    const int tx = tid & 15;    // k group (4k) / d group (4 lo + 4 hi)

    // qsT fill: coalesced float4, 4-phase optimal stores
    {
        const float* thp = d_theta + (size_t)b * CI * NN + q0;
#pragma unroll
        for (int p = 0; p < 8; p++) {
            int idx = p * 256 + tid;
            int c   = idx >> 4;
            int q4  = idx & 15;
            *(float4*)&qsT[c * 64 + q4 * 4] =
                *(const float4*)&thp[(size_t)c * NN + q4 * 4];
        }
    }

    float m_prev[4], l_run[4];
    u64 yacc2[4][4];
#pragma unroll
    for (int i = 0; i < 4; i++) {
        m_prev[i] = -1e30f;
        l_run[i]  = 0.f;
#pragma unroll
        for (int j = 0; j < 4; j++) yacc2[i][j] = 0ull;
    }

    for (int c0 = 0; c0 < NK; c0 += 64) {
        __syncthreads();   // protect ksT/gs reads of prev chunk (and qsT fill, 1st iter)
        {
            const float* php = d_phi + (size_t)b * CI * NK + c0;
            const float* gp  = d_g + ((size_t)b * NK + c0) * CI;
#pragma unroll
            for (int p = 0; p < 8; p++) {
                int idx = p * 256 + tid;
                int c   = idx >> 4;
                int k4  = idx & 15;
                *(float4*)&ksT[c * 64 + k4 * 4] =
                    *(const float4*)&php[(size_t)c * NK + k4 * 4];
                int k  = idx >> 5;
                int c4 = idx & 31;
                *(float4*)&gs[k * 128 + c4 * 4] =
                    *(const float4*)&gp[(size_t)k * CI + c4 * 4];
            }
        }
        __syncthreads();

        // S = theta . phi^T  (64q x 64k, K=128), microtile 4q x 4k
        u64 s2[4][2];
#pragma unroll
        for (int i = 0; i < 4; i++) { s2[i][0] = 0ull; s2[i][1] = 0ull; }

#pragma unroll 4
        for (int c = 0; c < 128; c++) {
            float4 a  = *(const float4*)&qsT[c * 64 + ty * 4];
            float4 kk = *(const float4*)&ksT[c * 64 + tx * 4];
            u64 kp0 = pk2(kk.x, kk.y), kp1 = pk2(kk.z, kk.w);
            const float av[4] = {a.x, a.y, a.z, a.w};
#pragma unroll
            for (int i = 0; i < 4; i++) {
                u64 ad = dup2(av[i]);
                fma2(s2[i][0], ad, kp0);
                fma2(s2[i][1], ad, kp1);
            }
        }

        // online softmax; row spread across the 16 tx lanes of a half-warp
#pragma unroll
        for (int i = 0; i < 4; i++) {
            float s[4];
            up2(s[0], s[1], s2[i][0]);
            up2(s[2], s[3], s2[i][1]);
            float m = fmaxf(fmaxf(s[0], s[1]), fmaxf(s[2], s[3]));
#pragma unroll
            for (int off = 1; off < 16; off <<= 1)
                m = fmaxf(m, __shfl_xor_sync(0xffffffffu, m, off));
            float mnew  = fmaxf(m_prev[i], m);
            float scale = __expf(m_prev[i] - mnew);
            float ssum = 0.f;
#pragma unroll
            for (int j = 0; j < 4; j++) {
                s[j] = __expf(s[j] - mnew);
                ssum += s[j];
            }
#pragma unroll
            for (int off = 1; off < 16; off <<= 1)
                ssum += __shfl_xor_sync(0xffffffffu, ssum, off);
            l_run[i] = l_run[i] * scale + ssum;
            m_prev[i] = mnew;
            u64 sd = dup2(scale);
#pragma unroll
            for (int j = 0; j < 4; j++) yacc2[i][j] = mul2(yacc2[i][j], sd);
            // P store q-major, one float4 per row: conflict-free, 4-phase optimal
            *(float4*)&psQ[(ty * 4 + i) * 64 + tx * 4] = make_float4(s[0], s[1], s[2], s[3]);
        }
        // P producer == consumer half-warp: warp-level sync is sufficient
        __syncwarp();

        // y += P . g   (64q x 128d, K=64)
#pragma unroll 2
        for (int kb = 0; kb < 16; kb++) {
            float4 p0 = *(const float4*)&psQ[(ty * 4 + 0) * 64 + kb * 4];
            float4 p1 = *(const float4*)&psQ[(ty * 4 + 1) * 64 + kb * 4];
            float4 p2 = *(const float4*)&psQ[(ty * 4 + 2) * 64 + kb * 4];
            float4 p3 = *(const float4*)&psQ[(ty * 4 + 3) * 64 + kb * 4];
            const float pr[4][4] = {{p0.x, p0.y, p0.z, p0.w},
                                    {p1.x, p1.y, p1.z, p1.w},
                                    {p2.x, p2.y, p2.z, p2.w},
                                    {p3.x, p3.y, p3.z, p3.w}};
#pragma unroll
            for (int e = 0; e < 4; e++) {
                int k = kb * 4 + e;
                float4 glo = *(const float4*)&gs[k * 128 + tx * 4];
                float4 ghi = *(const float4*)&gs[k * 128 + 64 + tx * 4];
                u64 gp4[4] = {pk2(glo.x, glo.y), pk2(glo.z, glo.w),
                              pk2(ghi.x, ghi.y), pk2(ghi.z, ghi.w)};
#pragma unroll
                for (int i = 0; i < 4; i++) {
                    u64 pd = dup2(pr[i][e]);
#pragma unroll
                    for (int j = 0; j < 4; j++) fma2(yacc2[i][j], pd, gp4[j]);
                }
            }
        }
    }

    // finalize: normalize + direct coalesced float4 writes (d_y n-major)
#pragma unroll
    for (int i = 0; i < 4; i++) {
        float invl = 1.f / l_run[i];
        int q = q0 + ty * 4 + i;
        float y[8];
        up2(y[0], y[1], yacc2[i][0]); up2(y[2], y[3], yacc2[i][1]);
        up2(y[4], y[5], yacc2[i][2]); up2(y[6], y[7], yacc2[i][3]);
        float* dst = d_y + ((size_t)b * NN + q) * CI;
        *(float4*)&dst[tx * 4]      = make_float4(y[0]*invl, y[1]*invl, y[2]*invl, y[3]*invl);
        *(float4*)&dst[64 + tx * 4] = make_float4(y[4]*invl, y[5]*invl, y[6]*invl, y[7]*invl);
    }
}

// =====================================================================
// Kernel 3: z = BN(conv1x1(y, W)) + fuse -> concat band 1.
// grid (N/128, C/128, B), block 256.  Tile 128c x 128n, K=128 by 32.
// d_y is n-major now: fill transposes via smem (coalesced LDG, scalar STS).
// =====================================================================
__global__ __launch_bounds__(256, 2)
void wz_kernel(const float* __restrict__ fuse,
               const float* __restrict__ W_b,
               const float* __restrict__ gamma, const float* __restrict__ beta,
               const float* __restrict__ mean,  const float* __restrict__ var,
               float* __restrict__ out)
{
    __shared__ __align__(16) float ys[32 * 132];   // [ci][n]
    __shared__ __align__(16) float wsm[32 * 132];  // [ci][c]

    const int b  = blockIdx.z;
    const int c0 = blockIdx.y * 128;
    const int n0 = blockIdx.x * 128;
    const int tid = threadIdx.x;
    const int ty = tid >> 4;   // c group
    const int tx = tid & 15;   // n group

    u64 acc2[8][4];
#pragma unroll
    for (int i = 0; i < 8; i++)
#pragma unroll
        for (int j = 0; j < 4; j++) acc2[i][j] = 0ull;

    for (int k0 = 0; k0 < CI; k0 += 32) {
        __syncthreads();
#pragma unroll
        for (int p = 0; p < 4; p++) {
            int idx = p * 256 + tid;
            // y: read [n][ci] coalesced float4, store transposed [ci][n]
            int n  = idx >> 3;    // 0..127
            int c4 = idx & 7;     // 0..7
            float4 v = *(const float4*)&d_y[((size_t)b * NN + n0 + n) * CI + k0 + c4 * 4];
            ys[(c4 * 4 + 0) * 132 + n] = v.x;
            ys[(c4 * 4 + 1) * 132 + n] = v.y;
            ys[(c4 * 4 + 2) * 132 + n] = v.z;
            ys[(c4 * 4 + 3) * 132 + n] = v.w;
            // w: already [ci][C], plain float4 tile copy
            int ci = idx >> 5;    // 0..31
            int g4 = idx & 31;    // 0..31
            *(float4*)&wsm[ci * 132 + g4 * 4] =
                *(const float4*)&d_wT[(size_t)(k0 + ci) * CC + c0 + g4 * 4];
        }
        __syncthreads();

#pragma unroll
        for (int cc = 0; cc < 32; cc++) {
            float4 wlo = *(const float4*)&wsm[cc * 132 + ty * 4];
            float4 whi = *(const float4*)&wsm[cc * 132 + 64 + ty * 4];
            float4 ylo = *(const float4*)&ys[cc * 132 + tx * 4];
            float4 yhi = *(const float4*)&ys[cc * 132 + 64 + tx * 4];
            u64 yp[4] = {pk2(ylo.x, ylo.y), pk2(ylo.z, ylo.w),
                         pk2(yhi.x, yhi.y), pk2(yhi.z, yhi.w)};
            const float wv[8] = {wlo.x, wlo.y, wlo.z, wlo.w,
                                 whi.x, whi.y, whi.z, whi.w};
#pragma unroll
            for (int i = 0; i < 8; i++) {
                u64 wd = dup2(wv[i]);
#pragma unroll
                for (int j = 0; j < 4; j++) fma2(acc2[i][j], wd, yp[j]);
            }
        }
    }

#pragma unroll
    for (int i = 0; i < 8; i++) {
        int c = c0 + ((i < 4) ? (ty * 4 + i) : (64 + ty * 4 + i - 4));
        float inv = gamma[c] * rsqrtf(var[c] + 1e-5f);
        float be  = (W_b[c] - mean[c]) * inv + beta[c];
        float a[8];
        up2(a[0], a[1], acc2[i][0]); up2(a[2], a[3], acc2[i][1]);
        up2(a[4], a[5], acc2[i][2]); up2(a[6], a[7], acc2[i][3]);
        const float* fr = &fuse[((size_t)b * CC + c) * NN + n0];
        float* orow = &out[((size_t)b * 768 + 256 + c) * NN + n0];
        float4 f0 = *(const float4*)&fr[tx * 4];
        float4 f1 = *(const float4*)&fr[64 + tx * 4];
        *(float4*)&orow[tx * 4] = make_float4(a[0]*inv + be + f0.x, a[1]*inv + be + f0.y,
                                              a[2]*inv + be + f0.z, a[3]*inv + be + f0.w);
        *(float4*)&orow[64 + tx * 4] = make_float4(a[4]*inv + be + f1.x, a[5]*inv + be + f1.y,
                                                   a[6]*inv + be + f1.z, a[7]*inv + be + f1.w);
    }
}

// =====================================================================
// Kernel 4: copy lc / gc into concat bands 0 and 2 (float4, grid-stride).
// =====================================================================
__global__ void copy_kernel(const float4* __restrict__ lc,
                            const float4* __restrict__ gc,
                            float4* __restrict__ out)
{
    const size_t PER_B = 262144;
    const size_t TOT   = BB * PER_B;
    const size_t OUT_B = 786432;
    const size_t stride = (size_t)gridDim.x * blockDim.x;
    for (size_t i = (size_t)blockIdx.x * blockDim.x + threadIdx.x;
         i < TOT; i += stride) {
        size_t bidx = i / PER_B, rem = i % PER_B;
        out[bidx * OUT_B + rem]             = lc[i];
        out[bidx * OUT_B + 2 * PER_B + rem] = gc[i];
    }
}

// =====================================================================
extern "C" void kernel_launch(void* const* d_in, const int* in_sizes, int n_in,
                              void* d_out, int out_size)
{
    const float* lc      = (const float*)d_in[0];
    const float* fuse    = (const float*)d_in[1];
    const float* gc      = (const float*)d_in[2];
    const float* g_w     = (const float*)d_in[3];
    const float* g_b     = (const float*)d_in[4];
    const float* theta_w = (const float*)d_in[5];
    const float* theta_b = (const float*)d_in[6];
    const float* phi_w   = (const float*)d_in[7];
    const float* phi_b   = (const float*)d_in[8];
    const float* W_w     = (const float*)d_in[9];
    const float* W_b     = (const float*)d_in[10];
    const float* bn_g    = (const float*)d_in[11];
    const float* bn_b    = (const float*)d_in[12];
    const float* bn_m    = (const float*)d_in[13];
    const float* bn_v    = (const float*)d_in[14];
    float* out = (float*)d_out;

    (void)in_sizes; (void)n_in; (void)out_size;

    cudaFuncSetAttribute(attn_kernel, cudaFuncAttributeMaxDynamicSharedMemorySize,
                         ATTN_SMEM_BYTES);

    wt_kernel<<<32, 256>>>(W_w);
    copy_kernel<<<2048, 256>>>((const float4*)lc, (const float4*)gc, (float4*)out);

    proj_kernel<<<dim3(32, BB, 3), 256>>>(fuse, g_w, g_b, theta_w, theta_b, phi_w, phi_b);

    attn_kernel<<<dim3(NN / 64, BB), 256, ATTN_SMEM_BYTES>>>();

    wz_kernel<<<dim3(NN / 128, CC / 128, BB), 256>>>(
        fuse, W_b, bn_g, bn_b, bn_m, bn_v, out);
}

// round 7
// speedup vs baseline: 1.4121x; 1.0027x over previous
#include <cuda_runtime.h>
#include <math.h>

#define BB 8
#define CC 256
#define CI 128
#define HH 64
#define WWID 64
#define NN 4096
#define NK 1024

typedef unsigned long long u64;

// ---------------- packed fp32x2 helpers (Blackwell FFMA2) ----------------
__device__ __forceinline__ u64 pk2(float lo, float hi) {
    u64 r; asm("mov.b64 %0, {%1, %2};" : "=l"(r) : "f"(lo), "f"(hi)); return r;
}
__device__ __forceinline__ u64 dup2(float v) { return pk2(v, v); }
__device__ __forceinline__ void up2(float& lo, float& hi, u64 v) {
    asm("mov.b64 {%0, %1}, %2;" : "=f"(lo), "=f"(hi) : "l"(v));
}
__device__ __forceinline__ void fma2(u64& d, u64 a, u64 b) {
    asm("fma.rn.f32x2 %0, %1, %2, %0;" : "+l"(d) : "l"(a), "l"(b));
}
__device__ __forceinline__ u64 mul2(u64 a, u64 b) {
    u64 d; asm("mul.rn.f32x2 %0, %1, %2;" : "=l"(d) : "l"(a), "l"(b)); return d;
}

// ---------------- scratch (device globals: allocation-free rule) ----------------
__device__ __align__(16) float d_theta[BB * CI * NN];   // [B][CI][N]   c-major
__device__ __align__(16) float d_phi[BB * CI * NK];     // [B][CI][Nk]  c-major
__device__ __align__(16) float d_g[BB * NK * CI];       // [B][Nk][CI]  k-major
__device__ __align__(16) float d_y[BB * NN * CI];       // [B][N][CI]   n-major
__device__ __align__(16) float d_wT[CI * CC];           // [CI][C]  (W_w transposed)

// =====================================================================
// Kernel 0: transpose W_w [C][CI] -> d_wT [CI][C].  Tiny (32K floats).
// =====================================================================
__global__ void wt_kernel(const float* __restrict__ Ww)
{
    int idx = blockIdx.x * 256 + threadIdx.x;
    if (idx < CC * (CI / 4)) {
        int c  = idx >> 5;
        int g4 = idx & 31;
        float4 v = ((const float4*)Ww)[idx];
        int ci = g4 * 4;
        d_wT[(ci + 0) * CC + c] = v.x;
        d_wT[(ci + 1) * CC + c] = v.y;
        d_wT[(ci + 2) * CC + c] = v.z;
        d_wT[(ci + 3) * CC + c] = v.w;
    }
}

// =====================================================================
// Kernel 1: fused projections theta/phi/g + lc/gc band copy prologue.
// grid (32, B, 3), block 256.
// =====================================================================
__global__ __launch_bounds__(256, 2)
void proj_kernel(const float* __restrict__ x,
                 const float* __restrict__ g_w,  const float* __restrict__ g_b,
                 const float* __restrict__ th_w, const float* __restrict__ th_b,
                 const float* __restrict__ ph_w, const float* __restrict__ ph_b,
                 const float4* __restrict__ lc4, const float4* __restrict__ gc4,
                 float4* __restrict__ out4)
{
    const int r    = blockIdx.x;
    const int b    = blockIdx.y;
    const int proj = blockIdx.z;
    const int tid  = threadIdx.x;

    // ---- folded copy of lc/gc into concat bands 0 and 2 (DRAM overlaps compute)
    {
        int cta = blockIdx.x + 32 * (blockIdx.y + 8 * blockIdx.z);  // 0..767
        const size_t PER_B = 262144, TOT = (size_t)BB * PER_B, OUT_B = 786432;
        const size_t stride = (size_t)768 * 256;
        for (size_t i = (size_t)cta * 256 + tid; i < TOT; i += stride) {
            size_t bidx = i / PER_B, rem = i % PER_B;
            out4[bidx * OUT_B + rem]             = lc4[i];
            out4[bidx * OUT_B + 2 * PER_B + rem] = gc4[i];
        }
    }

    const float* w;
    const float* bias;
    if (proj == 0)      { w = th_w; bias = th_b; }
    else if (proj == 1) { w = ph_w; bias = ph_b; }
    else                { w = g_w;  bias = g_b;  }

    __shared__ __align__(16) float pool[8448];
    float* xs = pool;                // [k][pixel-perm]  32 x 128
    float* ws = pool + 4096;         // [k][ci]          32 x 132

    const int ty  = tid >> 4;
    const int tx  = tid & 15;

    u64 acc2[8][4];
#pragma unroll
    for (int i = 0; i < 8; i++)
#pragma unroll
        for (int j = 0; j < 4; j++) acc2[i][j] = 0ull;

    const float* xb = x + ((size_t)b * CC) * NN + (2 * r) * WWID;

    for (int k0 = 0; k0 < CC; k0 += 32) {
#pragma unroll
        for (int i = 0; i < 16; i++) {
            int l    = tid + i * 256;
            int chn  = l >> 7;
            int p    = l & 127;
            int row  = p >> 6;
            int wcol = p & 63;
            int perm = ((wcol >> 1) << 2) | (row << 1) | (wcol & 1);
            xs[chn * 128 + perm] = xb[(size_t)(k0 + chn) * NN + row * WWID + wcol];
        }
#pragma unroll
        for (int i = 0; i < 16; i++) {
            int l  = tid + i * 256;
            int ci = l >> 5;
            int kk = l & 31;
            ws[kk * 132 + ci] = w[ci * CC + k0 + kk];
        }
        __syncthreads();

#pragma unroll
        for (int kk = 0; kk < 32; kk++) {
            float a[8];
            *(float4*)&a[0] = *(const float4*)&xs[kk * 128 + ty * 8];
            *(float4*)&a[4] = *(const float4*)&xs[kk * 128 + ty * 8 + 4];
            float4 blo = *(const float4*)&ws[kk * 132 + tx * 4];
            float4 bhi = *(const float4*)&ws[kk * 132 + 64 + tx * 4];
            u64 bp[4] = {pk2(blo.x, blo.y), pk2(blo.z, blo.w),
                         pk2(bhi.x, bhi.y), pk2(bhi.z, bhi.w)};
#pragma unroll
            for (int i = 0; i < 8; i++) {
                u64 ad = dup2(a[i]);
#pragma unroll
                for (int j = 0; j < 4; j++) fma2(acc2[i][j], ad, bp[j]);
            }
        }
        __syncthreads();
    }

    float accf[8][8];
#pragma unroll
    for (int i = 0; i < 8; i++) {
        up2(accf[i][0], accf[i][1], acc2[i][0]);
        up2(accf[i][2], accf[i][3], acc2[i][1]);
        up2(accf[i][4], accf[i][5], acc2[i][2]);
        up2(accf[i][6], accf[i][7], acc2[i][3]);
    }

    float blov[4], bhiv[4];
    *(float4*)blov = *(const float4*)&bias[tx * 4];
    *(float4*)bhiv = *(const float4*)&bias[64 + tx * 4];

    if (proj == 0) {
#pragma unroll
        for (int h = 0; h < 2; h++) {
            __syncthreads();
            const float* bv = h ? bhiv : blov;
#pragma unroll
            for (int i = 0; i < 8; i++) {
                int pm    = ty * 8 + i;
                int group = pm >> 2;
                int pos   = pm & 3;
                int nl    = ((pos >> 1) << 6) | (group << 1) | (pos & 1);
#pragma unroll
                for (int j = 0; j < 4; j++)
                    pool[(tx * 4 + j) * 132 + nl] = accf[i][h * 4 + j] + bv[j];
            }
            __syncthreads();
            float* dstb = d_theta + ((size_t)b * CI + h * 64) * NN + (2 * r) * WWID;
#pragma unroll
            for (int p = 0; p < 8; p++) {
                int idx = p * 256 + tid;
                int cil = idx >> 5;
                int p4  = idx & 31;
                *(float4*)&dstb[(size_t)cil * NN + p4 * 4] =
                    *(const float4*)&pool[cil * 132 + p4 * 4];
            }
        }
    } else if (proj == 1) {
        __syncthreads();
#pragma unroll
        for (int gg = 0; gg < 2; gg++) {
            int kl = ty * 2 + gg;
#pragma unroll
            for (int j = 0; j < 4; j++) {
                float mlo = fmaxf(fmaxf(accf[gg*4+0][j],   accf[gg*4+1][j]),
                                  fmaxf(accf[gg*4+2][j],   accf[gg*4+3][j]));
                float mhi = fmaxf(fmaxf(accf[gg*4+0][4+j], accf[gg*4+1][4+j]),
                                  fmaxf(accf[gg*4+2][4+j], accf[gg*4+3][4+j]));
                pool[(tx * 4 + j) * 36 + kl]      = mlo + blov[j];
                pool[(64 + tx * 4 + j) * 36 + kl] = mhi + bhiv[j];
            }
        }
        __syncthreads();
        float* dstb = d_phi + (size_t)b * CI * NK + r * 32;
#pragma unroll
        for (int p = 0; p < 4; p++) {
            int idx = p * 256 + tid;
            int ci  = idx >> 3;
            int k4  = idx & 7;
            *(float4*)&dstb[(size_t)ci * NK + k4 * 4] =
                *(const float4*)&pool[ci * 36 + k4 * 4];
        }
    } else {
#pragma unroll
        for (int gg = 0; gg < 2; gg++) {
            int k = r * 32 + ty * 2 + gg;
            float vlo[4], vhi[4];
#pragma unroll
            for (int j = 0; j < 4; j++) {
                vlo[j] = fmaxf(fmaxf(accf[gg*4+0][j],   accf[gg*4+1][j]),
                               fmaxf(accf[gg*4+2][j],   accf[gg*4+3][j])) + blov[j];
                vhi[j] = fmaxf(fmaxf(accf[gg*4+0][4+j], accf[gg*4+1][4+j]),
                               fmaxf(accf[gg*4+2][4+j], accf[gg*4+3][4+j])) + bhiv[j];
            }
            float* dst = d_g + ((size_t)(b * NK + k)) * CI;
            *(float4*)&dst[tx * 4]      = *(float4*)vlo;
            *(float4*)&dst[64 + tx * 4] = *(float4*)vhi;
        }
    }
}

// =====================================================================
// Kernel 2: flash attention v4.  grid (N/64, B), block 256, 2 CTAs/SM.
// 64 q/CTA; 8 key chunks of 128.  S microtile 4q x 8k (16 fma2 : 3 LDS).
// ksT channel-split (64c x 128k, 2 fills/chunk); gs d-split (128k x 64d,
// 2 fills/chunk); psQ (64q x 132, padded) aliases the ksT buffer.
// smem: qsT 128x64 + kps 8448 + gs 128x64 = 99,328 B  -> occ 2.
// =====================================================================
#define ATTN_SMEM_BYTES ((128 * 64 + 8448 + 128 * 64) * 4)

__global__ __launch_bounds__(256, 2)
void attn_kernel()
{
    extern __shared__ float sm[];
    float* qsT = sm;                   // [c][q]      128 x 64
    float* kps = sm + 8192;            // ksT [c64][k128] | psQ [q64][132]
    float* gs  = sm + 8192 + 8448;     // [k][d-half] 128 x 64

    const int b  = blockIdx.y;
    const int q0 = blockIdx.x * 64;
    const int tid = threadIdx.x;
    const int ty = tid >> 4;   // q group: q = q0 + 4*ty + i
    const int tx = tid & 15;   // k group: klo tx*4+j, khi 64+tx*4+j

    {
        const float* thp = d_theta + (size_t)b * CI * NN + q0;
#pragma unroll
        for (int p = 0; p < 8; p++) {
            int idx = p * 256 + tid;
            int c = idx >> 4, q4 = idx & 15;
            *(float4*)&qsT[c * 64 + q4 * 4] =
                *(const float4*)&thp[(size_t)c * NN + q4 * 4];
        }
    }

    float m_prev[4], l_run[4];
    u64 yacc2[4][4];
#pragma unroll
    for (int i = 0; i < 4; i++) {
        m_prev[i] = -1e30f;
        l_run[i]  = 0.f;
#pragma unroll
        for (int j = 0; j < 4; j++) yacc2[i][j] = 0ull;
    }

    for (int c0 = 0; c0 < NK; c0 += 128) {
        const float* php = d_phi + (size_t)b * CI * NK + c0;   // [c][key]
        const float* gp  = d_g + ((size_t)b * NK + c0) * CI;   // [key][d]

        u64 s2[4][4];
#pragma unroll
        for (int i = 0; i < 4; i++)
#pragma unroll
            for (int j = 0; j < 4; j++) s2[i][j] = 0ull;

        __syncthreads();
#pragma unroll
        for (int p = 0; p < 8; p++) {
            int idx = p * 256 + tid;
            int c = idx >> 5, k4 = idx & 31;
            *(float4*)&kps[c * 128 + k4 * 4] =
                *(const float4*)&php[(size_t)c * NK + k4 * 4];
            int k = idx >> 4, d4 = idx & 15;
            *(float4*)&gs[k * 64 + d4 * 4] =
                *(const float4*)&gp[(size_t)k * CI + d4 * 4];
        }
        __syncthreads();

#pragma unroll 4
        for (int c = 0; c < 64; c++) {
            float4 a   = *(const float4*)&qsT[c * 64 + ty * 4];
            float4 klo = *(const float4*)&kps[c * 128 + tx * 4];
            float4 khi = *(const float4*)&kps[c * 128 + 64 + tx * 4];
            u64 kp[4] = {pk2(klo.x, klo.y), pk2(klo.z, klo.w),
                         pk2(khi.x, khi.y), pk2(khi.z, khi.w)};
            const float av[4] = {a.x, a.y, a.z, a.w};
#pragma unroll
            for (int i = 0; i < 4; i++) {
                u64 ad = dup2(av[i]);
#pragma unroll
                for (int j = 0; j < 4; j++) fma2(s2[i][j], ad, kp[j]);
            }
        }
        __syncthreads();
#pragma unroll
        for (int p = 0; p < 8; p++) {
            int idx = p * 256 + tid;
            int c = idx >> 5, k4 = idx & 31;
            *(float4*)&kps[c * 128 + k4 * 4] =
                *(const float4*)&php[(size_t)(64 + c) * NK + k4 * 4];
        }
        __syncthreads();
#pragma unroll 4
        for (int c = 0; c < 64; c++) {
            float4 a   = *(const float4*)&qsT[(64 + c) * 64 + ty * 4];
            float4 klo = *(const float4*)&kps[c * 128 + tx * 4];
            float4 khi = *(const float4*)&kps[c * 128 + 64 + tx * 4];
            u64 kp[4] = {pk2(klo.x, klo.y), pk2(klo.z, klo.w),
                         pk2(khi.x, khi.y), pk2(khi.z, khi.w)};
            const float av[4] = {a.x, a.y, a.z, a.w};
#pragma unroll
            for (int i = 0; i < 4; i++) {
                u64 ad = dup2(av[i]);
#pragma unroll
                for (int j = 0; j < 4; j++) fma2(s2[i][j], ad, kp[j]);
            }
        }

        __syncthreads();   // ksT dead -> buffer becomes psQ

        // online softmax + psQ stores
#pragma unroll
        for (int i = 0; i < 4; i++) {
            float s[8];
            up2(s[0], s[1], s2[i][0]); up2(s[2], s[3], s2[i][1]);
            up2(s[4], s[5], s2[i][2]); up2(s[6], s[7], s2[i][3]);
            float m = s[0];
#pragma unroll
            for (int j = 1; j < 8; j++) m = fmaxf(m, s[j]);
#pragma unroll
            for (int off = 1; off < 16; off <<= 1)
                m = fmaxf(m, __shfl_xor_sync(0xffffffffu, m, off));
            float mnew  = fmaxf(m_prev[i], m);
            float scale = __expf(m_prev[i] - mnew);
            float ssum = 0.f;
#pragma unroll
            for (int j = 0; j < 8; j++) {
                s[j] = __expf(s[j] - mnew);
                ssum += s[j];
            }
#pragma unroll
            for (int off = 1; off < 16; off <<= 1)
                ssum += __shfl_xor_sync(0xffffffffu, ssum, off);
            l_run[i] = l_run[i] * scale + ssum;
            m_prev[i] = mnew;
            u64 sd = dup2(scale);
#pragma unroll
            for (int j = 0; j < 4; j++) yacc2[i][j] = mul2(yacc2[i][j], sd);
            int q = ty * 4 + i;
            *(float4*)&kps[q * 132 + tx * 4]      = make_float4(s[0], s[1], s[2], s[3]);
            *(float4*)&kps[q * 132 + 64 + tx * 4] = make_float4(s[4], s[5], s[6], s[7]);
        }
        __syncwarp();

        // PV half 0 (d = tx*4..)
#pragma unroll 2
        for (int kb = 0; kb < 32; kb++) {
            float4 p0 = *(const float4*)&kps[(ty * 4 + 0) * 132 + kb * 4];
            float4 p1 = *(const float4*)&kps[(ty * 4 + 1) * 132 + kb * 4];
            float4 p2 = *(const float4*)&kps[(ty * 4 + 2) * 132 + kb * 4];
            float4 p3 = *(const float4*)&kps[(ty * 4 + 3) * 132 + kb * 4];
            const float pr[4][4] = {{p0.x, p0.y, p0.z, p0.w},
                                    {p1.x, p1.y, p1.z, p1.w},
                                    {p2.x, p2.y, p2.z, p2.w},
                                    {p3.x, p3.y, p3.z, p3.w}};
#pragma unroll
            for (int e = 0; e < 4; e++) {
                float4 g = *(const float4*)&gs[(kb * 4 + e) * 64 + tx * 4];
                u64 gp0 = pk2(g.x, g.y), gp1 = pk2(g.z, g.w);
#pragma unroll
                for (int i = 0; i < 4; i++) {
                    u64 pd = dup2(pr[i][e]);
                    fma2(yacc2[i][0], pd, gp0);
                    fma2(yacc2[i][1], pd, gp1);
                }
            }
        }
        __syncthreads();
#pragma unroll
        for (int p = 0; p < 8; p++) {
            int idx = p * 256 + tid;
            int k = idx >> 4, d4 = idx & 15;
            *(float4*)&gs[k * 64 + d4 * 4] =
                *(const float4*)&gp[(size_t)k * CI + 64 + d4 * 4];
        }
        __syncthreads();
        // PV half 1 (d = 64 + tx*4..)
#pragma unroll 2
        for (int kb = 0; kb < 32; kb++) {
            float4 p0 = *(const float4*)&kps[(ty * 4 + 0) * 132 + kb * 4];
            float4 p1 = *(const float4*)&kps[(ty * 4 + 1) * 132 + kb * 4];
            float4 p2 = *(const float4*)&kps[(ty * 4 + 2) * 132 + kb * 4];
            float4 p3 = *(const float4*)&kps[(ty * 4 + 3) * 132 + kb * 4];
            const float pr[4][4] = {{p0.x, p0.y, p0.z, p0.w},
                                    {p1.x, p1.y, p1.z, p1.w},
                                    {p2.x, p2.y, p2.z, p2.w},
                                    {p3.x, p3.y, p3.z, p3.w}};
#pragma unroll
            for (int e = 0; e < 4; e++) {
                float4 g = *(const float4*)&gs[(kb * 4 + e) * 64 + tx * 4];
                u64 gp0 = pk2(g.x, g.y), gp1 = pk2(g.z, g.w);
#pragma unroll
                for (int i = 0; i < 4; i++) {
                    u64 pd = dup2(pr[i][e]);
                    fma2(yacc2[i][2], pd, gp0);
                    fma2(yacc2[i][3], pd, gp1);
                }
            }
        }
    }

#pragma unroll
    for (int i = 0; i < 4; i++) {
        float invl = 1.f / l_run[i];
        int q = q0 + ty * 4 + i;
        float y[8];
        up2(y[0], y[1], yacc2[i][0]); up2(y[2], y[3], yacc2[i][1]);
        up2(y[4], y[5], yacc2[i][2]); up2(y[6], y[7], yacc2[i][3]);
        float* dst = d_y + ((size_t)b * NN + q) * CI;
        *(float4*)&dst[tx * 4]      = make_float4(y[0]*invl, y[1]*invl, y[2]*invl, y[3]*invl);
        *(float4*)&dst[64 + tx * 4] = make_float4(y[4]*invl, y[5]*invl, y[6]*invl, y[7]*invl);
    }
}

// =====================================================================
// Kernel 3: z = BN(conv1x1(y, W)) + fuse -> concat band 1.
// =====================================================================
__global__ __launch_bounds__(256, 2)
void wz_kernel(const float* __restrict__ fuse,
               const float* __restrict__ W_b,
               const float* __restrict__ gamma, const float* __restrict__ beta,
               const float* __restrict__ mean,  const float* __restrict__ var,
               float* __restrict__ out)
{
    __shared__ __align__(16) float ys[32 * 132];
    __shared__ __align__(16) float wsm[32 * 132];

    const int b  = blockIdx.z;
    const int c0 = blockIdx.y * 128;
    const int n0 = blockIdx.x * 128;
    const int tid = threadIdx.x;
    const int ty = tid >> 4;
    const int tx = tid & 15;

    u64 acc2[8][4];
#pragma unroll
    for (int i = 0; i < 8; i++)
#pragma unroll
        for (int j = 0; j < 4; j++) acc2[i][j] = 0ull;

    for (int k0 = 0; k0 < CI; k0 += 32) {
        __syncthreads();
#pragma unroll
        for (int p = 0; p < 4; p++) {
            int idx = p * 256 + tid;
            int n  = idx >> 3;
            int c4 = idx & 7;
            float4 v = *(const float4*)&d_y[((size_t)b * NN + n0 + n) * CI + k0 + c4 * 4];
            ys[(c4 * 4 + 0) * 132 + n] = v.x;
            ys[(c4 * 4 + 1) * 132 + n] = v.y;
            ys[(c4 * 4 + 2) * 132 + n] = v.z;
            ys[(c4 * 4 + 3) * 132 + n] = v.w;
            int ci = idx >> 5;
            int g4 = idx & 31;
            *(float4*)&wsm[ci * 132 + g4 * 4] =
                *(const float4*)&d_wT[(size_t)(k0 + ci) * CC + c0 + g4 * 4];
        }
        __syncthreads();

#pragma unroll
        for (int cc = 0; cc < 32; cc++) {
            float4 wlo = *(const float4*)&wsm[cc * 132 + ty * 4];
            float4 whi = *(const float4*)&wsm[cc * 132 + 64 + ty * 4];
            float4 ylo = *(const float4*)&ys[cc * 132 + tx * 4];
            float4 yhi = *(const float4*)&ys[cc * 132 + 64 + tx * 4];
            u64 yp[4] = {pk2(ylo.x, ylo.y), pk2(ylo.z, ylo.w),
                         pk2(yhi.x, yhi.y), pk2(yhi.z, yhi.w)};
            const float wv[8] = {wlo.x, wlo.y, wlo.z, wlo.w,
                                 whi.x, whi.y, whi.z, whi.w};
#pragma unroll
            for (int i = 0; i < 8; i++) {
                u64 wd = dup2(wv[i]);
#pragma unroll
                for (int j = 0; j < 4; j++) fma2(acc2[i][j], wd, yp[j]);
            }
        }
    }

#pragma unroll
    for (int i = 0; i < 8; i++) {
        int c = c0 + ((i < 4) ? (ty * 4 + i) : (64 + ty * 4 + i - 4));
        float inv = gamma[c] * rsqrtf(var[c] + 1e-5f);
        float be  = (W_b[c] - mean[c]) * inv + beta[c];
        float a[8];
        up2(a[0], a[1], acc2[i][0]); up2(a[2], a[3], acc2[i][1]);
        up2(a[4], a[5], acc2[i][2]); up2(a[6], a[7], acc2[i][3]);
        const float* fr = &fuse[((size_t)b * CC + c) * NN + n0];
        float* orow = &out[((size_t)b * 768 + 256 + c) * NN + n0];
        float4 f0 = *(const float4*)&fr[tx * 4];
        float4 f1 = *(const float4*)&fr[64 + tx * 4];
        *(float4*)&orow[tx * 4] = make_float4(a[0]*inv + be + f0.x, a[1]*inv + be + f0.y,
                                              a[2]*inv + be + f0.z, a[3]*inv + be + f0.w);
        *(float4*)&orow[64 + tx * 4] = make_float4(a[4]*inv + be + f1.x, a[5]*inv + be + f1.y,
                                                   a[6]*inv + be + f1.z, a[7]*inv + be + f1.w);
    }
}

// =====================================================================
extern "C" void kernel_launch(void* const* d_in, const int* in_sizes, int n_in,
                              void* d_out, int out_size)
{
    const float* lc      = (const float*)d_in[0];
    const float* fuse    = (const float*)d_in[1];
    const float* gc      = (const float*)d_in[2];
    const float* g_w     = (const float*)d_in[3];
    const float* g_b     = (const float*)d_in[4];
    const float* theta_w = (const float*)d_in[5];
    const float* theta_b = (const float*)d_in[6];
    const float* phi_w   = (const float*)d_in[7];
    const float* phi_b   = (const float*)d_in[8];
    const float* W_w     = (const float*)d_in[9];
    const float* W_b     = (const float*)d_in[10];
    const float* bn_g    = (const float*)d_in[11];
    const float* bn_b    = (const float*)d_in[12];
    const float* bn_m    = (const float*)d_in[13];
    const float* bn_v    = (const float*)d_in[14];
    float* out = (float*)d_out;

    (void)in_sizes; (void)n_in; (void)out_size;

    cudaFuncSetAttribute(attn_kernel, cudaFuncAttributeMaxDynamicSharedMemorySize,
                         ATTN_SMEM_BYTES);

    wt_kernel<<<32, 256>>>(W_w);

    // projections + folded lc/gc band copies
    proj_kernel<<<dim3(32, BB, 3), 256>>>(fuse, g_w, g_b, theta_w, theta_b,
                                          phi_w, phi_b,
                                          (const float4*)lc, (const float4*)gc,
                                          (float4*)out);

    attn_kernel<<<dim3(NN / 64, BB), 256, ATTN_SMEM_BYTES>>>();

    wz_kernel<<<dim3(NN / 128, CC / 128, BB), 256>>>(
        fuse, W_b, bn_g, bn_b, bn_m, bn_v, out);
}

// round 10
// speedup vs baseline: 2.4160x; 1.7110x over previous
#include <cuda_runtime.h>
#include <cuda_bf16.h>
#include <math.h>
#include <cstdint>

#define BB 8
#define CC 256
#define CI 128
#define HH 64
#define WWID 64
#define NN 4096
#define NK 1024

typedef unsigned long long u64;

// ---------------- packed fp32x2 helpers (FFMA2) ----------------
__device__ __forceinline__ u64 pk2(float lo, float hi) {
    u64 r; asm("mov.b64 %0, {%1, %2};" : "=l"(r) : "f"(lo), "f"(hi)); return r;
}
__device__ __forceinline__ u64 dup2(float v) { return pk2(v, v); }
__device__ __forceinline__ void up2(float& lo, float& hi, u64 v) {
    asm("mov.b64 {%0, %1}, %2;" : "=f"(lo), "=f"(hi) : "l"(v));
}
__device__ __forceinline__ void fma2(u64& d, u64 a, u64 b) {
    asm("fma.rn.f32x2 %0, %1, %2, %0;" : "+l"(d) : "l"(a), "l"(b));
}

// ---------------- warp-MMA helpers (sm_80-era path; valid on plain sm_100) ----
__device__ __forceinline__ uint32_t smem_u32(const void* p) {
    uint32_t a;
    asm("{ .reg .u64 t; cvta.to.shared.u64 t, %1; cvt.u32.u64 %0, t; }" : "=r"(a) : "l"(p));
    return a;
}
// res = {lo=a, hi=b} packed bf16x2
#define CVT_BF16X2(res, a, b) \
    asm("cvt.rn.satfinite.bf16x2.f32 %0, %1, %2;" : "=r"(res) : "f"(b), "f"(a))

__device__ __forceinline__ void ldsm_x4(uint32_t& a0, uint32_t& a1, uint32_t& a2,
                                        uint32_t& a3, uint32_t addr) {
    asm volatile("ldmatrix.sync.aligned.m8n8.x4.shared.b16 {%0,%1,%2,%3}, [%4];"
                 : "=r"(a0), "=r"(a1), "=r"(a2), "=r"(a3) : "r"(addr));
}
__device__ __forceinline__ void ldsm_x2(uint32_t& b0, uint32_t& b1, uint32_t addr) {
    asm volatile("ldmatrix.sync.aligned.m8n8.x2.shared.b16 {%0,%1}, [%2];"
                 : "=r"(b0), "=r"(b1) : "r"(addr));
}
__device__ __forceinline__ void mma_bf16(float* c, uint32_t a0, uint32_t a1,
                                         uint32_t a2, uint32_t a3,
                                         uint32_t b0, uint32_t b1) {
    asm volatile("mma.sync.aligned.m16n8k16.row.col.f32.bf16.bf16.f32 "
                 "{%0,%1,%2,%3}, {%4,%5,%6,%7}, {%8,%9}, {%0,%1,%2,%3};"
                 : "+f"(c[0]), "+f"(c[1]), "+f"(c[2]), "+f"(c[3])
                 : "r"(a0), "r"(a1), "r"(a2), "r"(a3), "r"(b0), "r"(b1));
}

// ---------------- scratch (device globals) ----------------
__device__ __align__(16) float d_theta[BB * NN * CI];   // [B][N][CI]
__device__ __align__(16) float d_phi[BB * NK * CI];     // [B][Nk][CI]
__device__ __align__(16) float d_g[BB * CI * NK];       // [B][CI][Nk] (d-major)
__device__ __align__(16) float d_y[BB * NN * CI];       // [B][N][CI]
__device__ __align__(16) float d_wT[CI * CC];
__device__ __align__(16) __nv_bfloat16 d_thh[BB * NN * CI];
__device__ __align__(16) __nv_bfloat16 d_thl[BB * NN * CI];
__device__ __align__(16) __nv_bfloat16 d_phh[BB * NK * CI];
__device__ __align__(16) __nv_bfloat16 d_phl[BB * NK * CI];
__device__ __align__(16) __nv_bfloat16 d_gh[BB * CI * NK];
__device__ __align__(16) __nv_bfloat16 d_gl[BB * CI * NK];

// =====================================================================
// Kernel 0: transpose W_w -> d_wT
// =====================================================================
__global__ void wt_kernel(const float* __restrict__ Ww)
{
    int idx = blockIdx.x * 256 + threadIdx.x;
    if (idx < CC * (CI / 4)) {
        int c  = idx >> 5;
        int g4 = idx & 31;
        float4 v = ((const float4*)Ww)[idx];
        int ci = g4 * 4;
        d_wT[(ci + 0) * CC + c] = v.x;
        d_wT[(ci + 1) * CC + c] = v.y;
        d_wT[(ci + 2) * CC + c] = v.z;
        d_wT[(ci + 3) * CC + c] = v.w;
    }
}

// =====================================================================
// Kernel 1: fused projections + lc/gc copy.  grid (32, B, 3), block 256.
// theta -> [B][N][CI], phi -> [B][Nk][CI], g -> [B][CI][Nk].
// =====================================================================
__global__ __launch_bounds__(256, 2)
void proj_kernel(const float* __restrict__ x,
                 const float* __restrict__ g_w,  const float* __restrict__ g_b,
                 const float* __restrict__ th_w, const float* __restrict__ th_b,
                 const float* __restrict__ ph_w, const float* __restrict__ ph_b,
                 const float4* __restrict__ lc4, const float4* __restrict__ gc4,
                 float4* __restrict__ out4)
{
    const int r    = blockIdx.x;
    const int b    = blockIdx.y;
    const int proj = blockIdx.z;
    const int tid  = threadIdx.x;

    {   // folded lc/gc band copy
        int cta = blockIdx.x + 32 * (blockIdx.y + 8 * blockIdx.z);
        const size_t PER_B = 262144, TOT = (size_t)BB * PER_B, OUT_B = 786432;
        const size_t stride = (size_t)768 * 256;
        for (size_t i = (size_t)cta * 256 + tid; i < TOT; i += stride) {
            size_t bidx = i / PER_B, rem = i % PER_B;
            out4[bidx * OUT_B + rem]             = lc4[i];
            out4[bidx * OUT_B + 2 * PER_B + rem] = gc4[i];
        }
    }

    const float* w;  const float* bias;
    if (proj == 0)      { w = th_w; bias = th_b; }
    else if (proj == 1) { w = ph_w; bias = ph_b; }
    else                { w = g_w;  bias = g_b;  }

    __shared__ __align__(16) float pool[8448];
    float* xs = pool;
    float* ws = pool + 4096;

    const int ty = tid >> 4;
    const int tx = tid & 15;

    u64 acc2[8][4];
#pragma unroll
    for (int i = 0; i < 8; i++)
#pragma unroll
        for (int j = 0; j < 4; j++) acc2[i][j] = 0ull;

    const float* xb = x + ((size_t)b * CC) * NN + (2 * r) * WWID;

    for (int k0 = 0; k0 < CC; k0 += 32) {
#pragma unroll
        for (int i = 0; i < 16; i++) {
            int l = tid + i * 256;
            int chn = l >> 7, p = l & 127;
            int row = p >> 6, wcol = p & 63;
            int perm = ((wcol >> 1) << 2) | (row << 1) | (wcol & 1);
            xs[chn * 128 + perm] = xb[(size_t)(k0 + chn) * NN + row * WWID + wcol];
        }
#pragma unroll
        for (int i = 0; i < 16; i++) {
            int l = tid + i * 256;
            int ci = l >> 5, kk = l & 31;
            ws[kk * 132 + ci] = w[ci * CC + k0 + kk];
        }
        __syncthreads();
#pragma unroll
        for (int kk = 0; kk < 32; kk++) {
            float a[8];
            *(float4*)&a[0] = *(const float4*)&xs[kk * 128 + ty * 8];
            *(float4*)&a[4] = *(const float4*)&xs[kk * 128 + ty * 8 + 4];
            float4 blo = *(const float4*)&ws[kk * 132 + tx * 4];
            float4 bhi = *(const float4*)&ws[kk * 132 + 64 + tx * 4];
            u64 bp[4] = {pk2(blo.x, blo.y), pk2(blo.z, blo.w),
                         pk2(bhi.x, bhi.y), pk2(bhi.z, bhi.w)};
#pragma unroll
            for (int i = 0; i < 8; i++) {
                u64 ad = dup2(a[i]);
#pragma unroll
                for (int j = 0; j < 4; j++) fma2(acc2[i][j], ad, bp[j]);
            }
        }
        __syncthreads();
    }

    float accf[8][8];
#pragma unroll
    for (int i = 0; i < 8; i++) {
        up2(accf[i][0], accf[i][1], acc2[i][0]);
        up2(accf[i][2], accf[i][3], acc2[i][1]);
        up2(accf[i][4], accf[i][5], acc2[i][2]);
        up2(accf[i][6], accf[i][7], acc2[i][3]);
    }
    float blov[4], bhiv[4];
    *(float4*)blov = *(const float4*)&bias[tx * 4];
    *(float4*)bhiv = *(const float4*)&bias[64 + tx * 4];

    if (proj == 0) {
#pragma unroll
        for (int i = 0; i < 8; i++) {
            int pm = ty * 8 + i, group = pm >> 2, pos = pm & 3;
            int n = (2 * r + (pos >> 1)) * WWID + ((group << 1) | (pos & 1));
            float vlo[4], vhi[4];
#pragma unroll
            for (int j = 0; j < 4; j++) {
                vlo[j] = accf[i][j] + blov[j];
                vhi[j] = accf[i][4 + j] + bhiv[j];
            }
            float* dst = d_theta + ((size_t)(b * NN + n)) * CI;
            *(float4*)&dst[tx * 4]      = *(float4*)vlo;
            *(float4*)&dst[64 + tx * 4] = *(float4*)vhi;
        }
    } else if (proj == 1) {
#pragma unroll
        for (int gg = 0; gg < 2; gg++) {
            int k = r * 32 + ty * 2 + gg;
            float vlo[4], vhi[4];
#pragma unroll
            for (int j = 0; j < 4; j++) {
                vlo[j] = fmaxf(fmaxf(accf[gg*4+0][j],   accf[gg*4+1][j]),
                               fmaxf(accf[gg*4+2][j],   accf[gg*4+3][j])) + blov[j];
                vhi[j] = fmaxf(fmaxf(accf[gg*4+0][4+j], accf[gg*4+1][4+j]),
                               fmaxf(accf[gg*4+2][4+j], accf[gg*4+3][4+j])) + bhiv[j];
            }
            float* dst = d_phi + ((size_t)(b * NK + k)) * CI;
            *(float4*)&dst[tx * 4]      = *(float4*)vlo;
            *(float4*)&dst[64 + tx * 4] = *(float4*)vhi;
        }
    } else {
        __syncthreads();
#pragma unroll
        for (int gg = 0; gg < 2; gg++) {
            int kl = ty * 2 + gg;
#pragma unroll
            for (int j = 0; j < 4; j++) {
                float mlo = fmaxf(fmaxf(accf[gg*4+0][j],   accf[gg*4+1][j]),
                                  fmaxf(accf[gg*4+2][j],   accf[gg*4+3][j]));
                float mhi = fmaxf(fmaxf(accf[gg*4+0][4+j], accf[gg*4+1][4+j]),
                                  fmaxf(accf[gg*4+2][4+j], accf[gg*4+3][4+j]));
                pool[(tx * 4 + j) * 36 + kl]      = mlo + blov[j];
                pool[(64 + tx * 4 + j) * 36 + kl] = mhi + bhiv[j];
            }
        }
        __syncthreads();
        float* dstb = d_g + (size_t)b * CI * NK + r * 32;
#pragma unroll
        for (int p = 0; p < 4; p++) {
            int idx = p * 256 + tid;
            int ci = idx >> 3, k4 = idx & 7;
            *(float4*)&dstb[(size_t)ci * NK + k4 * 4] =
                *(const float4*)&pool[ci * 36 + k4 * 4];
        }
    }
}

// =====================================================================
// Kernel 1b: fp32 -> bf16 hi/lo split of theta/phi/g.
// =====================================================================
__global__ void split_kernel()
{
    const size_t T_TH = (size_t)BB * NN * CI / 4;
    const size_t T_PH = (size_t)BB * NK * CI / 4;
    size_t i = (size_t)blockIdx.x * 256 + threadIdx.x;

    const float4* src; uint2* dh; uint2* dl; size_t off;
    if (i < T_TH)              { src = (const float4*)d_theta; dh = (uint2*)d_thh; dl = (uint2*)d_thl; off = i; }
    else if (i < T_TH + T_PH)  { src = (const float4*)d_phi;   dh = (uint2*)d_phh; dl = (uint2*)d_phl; off = i - T_TH; }
    else                       { src = (const float4*)d_g;     dh = (uint2*)d_gh;  dl = (uint2*)d_gl;  off = i - T_TH - T_PH; }

    float4 v = src[off];
    float hx = __bfloat162float(__float2bfloat16(v.x));
    float hy = __bfloat162float(__float2bfloat16(v.y));
    float hz = __bfloat162float(__float2bfloat16(v.z));
    float hw = __bfloat162float(__float2bfloat16(v.w));
    uint32_t h01, h23, l01, l23;
    CVT_BF16X2(h01, v.x, v.y);
    CVT_BF16X2(h23, v.z, v.w);
    CVT_BF16X2(l01, v.x - hx, v.y - hy);
    CVT_BF16X2(l23, v.z - hz, v.w - hw);
    dh[off] = make_uint2(h01, h23);
    dl[off] = make_uint2(l01, l23);
}

// =====================================================================
// Kernel 2: warp-MMA bf16 split-precision flash attention (FA2 style).
// grid (NN/128, BB), block 256 (8 warps x 16 q).  16 key chunks of 64.
// S = th_h*ph_h + th_h*ph_l + th_l*ph_h; online softmax (reg-resident Y);
// PV = P_h*g_h + P_l*g_h + P_h*g_l.  P stays in registers (C-frag == A-frag).
// smem rows padded to 272B (Q,K) / 144B (G^T): all ldmatrix phases
// conflict-free.  Total smem 141,312 B -> 1 CTA/SM.
// =====================================================================
#define SM_QH 0
#define SM_QL 34816
#define SM_KH 69632
#define SM_KL 87040
#define SM_GH 104448
#define SM_GL 122880
#define ATTN_SMEM_BYTES 141312

__global__ __launch_bounds__(256, 1)
void attn_kernel()
{
    extern __shared__ char smc[];
    const uint32_t sb = smem_u32(smc);
    const int tid  = threadIdx.x;
    const int wid  = tid >> 5;
    const int lane = tid & 31;
    const int b    = blockIdx.y;
    const int q0   = blockIdx.x * 128;

    // ---- Q tiles (once per CTA): rows q0..q0+127, 128 bf16 each, pad 272B
    {
        const __nv_bfloat16* qh = d_thh + (size_t)(b * NN + q0) * CI;
        const __nv_bfloat16* ql = d_thl + (size_t)(b * NN + q0) * CI;
#pragma unroll
        for (int it = 0; it < 8; it++) {
            int idx = it * 256 + tid;
            int row = idx >> 4, c8 = (idx & 15) * 8;
            *(uint4*)(smc + SM_QH + row * 272 + c8 * 2) =
                *(const uint4*)(qh + (size_t)row * CI + c8);
            *(uint4*)(smc + SM_QL + row * 272 + c8 * 2) =
                *(const uint4*)(ql + (size_t)row * CI + c8);
        }
    }

    // ldmatrix lane-address components
    const int a_row = (lane & 7) + 8 * ((lane >> 3) & 1);   // A x4
    const int a_col = 8 * (lane >> 4);
    const int b_row = lane & 7;                             // B x2
    const int b_col = 8 * ((lane >> 3) & 1);
    const int Rbase = wid * 16;

    float yacc[16][4];
#pragma unroll
    for (int dt = 0; dt < 16; dt++)
#pragma unroll
        for (int j = 0; j < 4; j++) yacc[dt][j] = 0.f;
    float m0 = -1e30f, m1 = -1e30f, l0 = 0.f, l1 = 0.f;

#pragma unroll 1
    for (int c0 = 0; c0 < NK; c0 += 64) {
        __syncthreads();   // prev chunk done reading K/G tiles
        {
            const __nv_bfloat16* kh = d_phh + (size_t)(b * NK + c0) * CI;
            const __nv_bfloat16* kl = d_phl + (size_t)(b * NK + c0) * CI;
            const __nv_bfloat16* gh = d_gh + (size_t)b * CI * NK + c0;
            const __nv_bfloat16* gl = d_gl + (size_t)b * CI * NK + c0;
#pragma unroll
            for (int it = 0; it < 4; it++) {
                int idx = it * 256 + tid;
                int krow = idx >> 4, c8 = (idx & 15) * 8;
                *(uint4*)(smc + SM_KH + krow * 272 + c8 * 2) =
                    *(const uint4*)(kh + (size_t)krow * CI + c8);
                *(uint4*)(smc + SM_KL + krow * 272 + c8 * 2) =
                    *(const uint4*)(kl + (size_t)krow * CI + c8);
                int drow = idx >> 3, k8 = (idx & 7) * 8;
                *(uint4*)(smc + SM_GH + drow * 144 + k8 * 2) =
                    *(const uint4*)(gh + (size_t)drow * NK + k8);
                *(uint4*)(smc + SM_GL + drow * 144 + k8 * 2) =
                    *(const uint4*)(gl + (size_t)drow * NK + k8);
            }
        }
        __syncthreads();

        // ---- S = theta . phi^T  (16q x 64k per warp), 3 split products ----
        float sacc[8][4];
#pragma unroll
        for (int n = 0; n < 8; n++)
#pragma unroll
            for (int j = 0; j < 4; j++) sacc[n][j] = 0.f;

#pragma unroll
        for (int m = 0; m < 8; m++) {
            int cb = m * 16;
            uint32_t ah0, ah1, ah2, ah3, al0, al1, al2, al3;
            ldsm_x4(ah0, ah1, ah2, ah3,
                    sb + SM_QH + (Rbase + a_row) * 272 + (cb + a_col) * 2);
            ldsm_x4(al0, al1, al2, al3,
                    sb + SM_QL + (Rbase + a_row) * 272 + (cb + a_col) * 2);
#pragma unroll
            for (int n = 0; n < 8; n++) {
                uint32_t bh0, bh1, bl0, bl1;
                ldsm_x2(bh0, bh1, sb + SM_KH + (n * 8 + b_row) * 272 + (cb + b_col) * 2);
                ldsm_x2(bl0, bl1, sb + SM_KL + (n * 8 + b_row) * 272 + (cb + b_col) * 2);
                mma_bf16(sacc[n], ah0, ah1, ah2, ah3, bh0, bh1);
                mma_bf16(sacc[n], ah0, ah1, ah2, ah3, bl0, bl1);
                mma_bf16(sacc[n], al0, al1, al2, al3, bh0, bh1);
            }
        }

        // ---- online softmax (rows r0 = lane>>2 and r0+8; quad-spread) ----
        float mc0 = -1e30f, mc1 = -1e30f;
#pragma unroll
        for (int n = 0; n < 8; n++) {
            mc0 = fmaxf(mc0, fmaxf(sacc[n][0], sacc[n][1]));
            mc1 = fmaxf(mc1, fmaxf(sacc[n][2], sacc[n][3]));
        }
        mc0 = fmaxf(mc0, __shfl_xor_sync(0xffffffffu, mc0, 1));
        mc0 = fmaxf(mc0, __shfl_xor_sync(0xffffffffu, mc0, 2));
        mc1 = fmaxf(mc1, __shfl_xor_sync(0xffffffffu, mc1, 1));
        mc1 = fmaxf(mc1, __shfl_xor_sync(0xffffffffu, mc1, 2));
        float mn0 = fmaxf(m0, mc0), mn1 = fmaxf(m1, mc1);
        float sc0 = __expf(m0 - mn0), sc1 = __expf(m1 - mn1);
        m0 = mn0; m1 = mn1;
        l0 *= sc0; l1 *= sc1;
#pragma unroll
        for (int dt = 0; dt < 16; dt++) {
            yacc[dt][0] *= sc0; yacc[dt][1] *= sc0;
            yacc[dt][2] *= sc1; yacc[dt][3] *= sc1;
        }

        // p = exp(s - m); convert to PV A-fragments (hi/lo), all in registers
        uint32_t pa_h[4][4], pa_l[4][4];
#pragma unroll
        for (int n = 0; n < 8; n++) {
            float p0 = __expf(sacc[n][0] - mn0);
            float p1 = __expf(sacc[n][1] - mn0);
            float p2 = __expf(sacc[n][2] - mn1);
            float p3 = __expf(sacc[n][3] - mn1);
            l0 += p0 + p1;
            l1 += p2 + p3;
            float h0 = __bfloat162float(__float2bfloat16(p0));
            float h1 = __bfloat162float(__float2bfloat16(p1));
            float h2 = __bfloat162float(__float2bfloat16(p2));
            float h3 = __bfloat162float(__float2bfloat16(p3));
            uint32_t h01, h23, lo01, lo23;
            CVT_BF16X2(h01, p0, p1);
            CVT_BF16X2(h23, p2, p3);
            CVT_BF16X2(lo01, p0 - h0, p1 - h1);
            CVT_BF16X2(lo23, p2 - h2, p3 - h3);
            int m2 = n >> 1;
            if ((n & 1) == 0) {
                pa_h[m2][0] = h01;  pa_h[m2][1] = h23;
                pa_l[m2][0] = lo01; pa_l[m2][1] = lo23;
            } else {
                pa_h[m2][2] = h01;  pa_h[m2][3] = h23;
                pa_l[m2][2] = lo01; pa_l[m2][3] = lo23;
            }
        }

        // ---- Y += P . g  (16q x 128d per warp), 3 split products ----
#pragma unroll
        for (int m2 = 0; m2 < 4; m2++) {
            int kb = m2 * 16;
#pragma unroll
            for (int dt = 0; dt < 16; dt++) {
                uint32_t bh0, bh1, bl0, bl1;
                ldsm_x2(bh0, bh1, sb + SM_GH + (dt * 8 + b_row) * 144 + (kb + b_col) * 2);
                ldsm_x2(bl0, bl1, sb + SM_GL + (dt * 8 + b_row) * 144 + (kb + b_col) * 2);
                mma_bf16(yacc[dt], pa_h[m2][0], pa_h[m2][1], pa_h[m2][2], pa_h[m2][3], bh0, bh1);
                mma_bf16(yacc[dt], pa_l[m2][0], pa_l[m2][1], pa_l[m2][2], pa_l[m2][3], bh0, bh1);
                mma_bf16(yacc[dt], pa_h[m2][0], pa_h[m2][1], pa_h[m2][2], pa_h[m2][3], bl0, bl1);
            }
        }
    }

    // ---- finalize ----
    l0 += __shfl_xor_sync(0xffffffffu, l0, 1);
    l0 += __shfl_xor_sync(0xffffffffu, l0, 2);
    l1 += __shfl_xor_sync(0xffffffffu, l1, 1);
    l1 += __shfl_xor_sync(0xffffffffu, l1, 2);
    float inv0 = 1.f / l0, inv1 = 1.f / l1;

    int r0 = lane >> 2;
    int cofs = (lane & 3) * 2;
    float* dst0 = d_y + ((size_t)(b * NN + q0 + Rbase + r0)) * CI;
    float* dst1 = d_y + ((size_t)(b * NN + q0 + Rbase + r0 + 8)) * CI;
#pragma unroll
    for (int dt = 0; dt < 16; dt++) {
        *(float2*)&dst0[dt * 8 + cofs] = make_float2(yacc[dt][0] * inv0, yacc[dt][1] * inv0);
        *(float2*)&dst1[dt * 8 + cofs] = make_float2(yacc[dt][2] * inv1, yacc[dt][3] * inv1);
    }
}

// =====================================================================
// Kernel 3: z = BN(conv1x1(y, W)) + fuse -> concat band 1.
// =====================================================================
__global__ __launch_bounds__(256, 2)
void wz_kernel(const float* __restrict__ fuse,
               const float* __restrict__ W_b,
               const float* __restrict__ gamma, const float* __restrict__ beta,
               const float* __restrict__ mean,  const float* __restrict__ var,
               float* __restrict__ out)
{
    __shared__ __align__(16) float ys[32 * 132];
    __shared__ __align__(16) float wsm[32 * 132];

    const int b  = blockIdx.z;
    const int c0 = blockIdx.y * 128;
    const int n0 = blockIdx.x * 128;
    const int tid = threadIdx.x;
    const int ty = tid >> 4;
    const int tx = tid & 15;

    u64 acc2[8][4];
#pragma unroll
    for (int i = 0; i < 8; i++)
#pragma unroll
        for (int j = 0; j < 4; j++) acc2[i][j] = 0ull;

    for (int k0 = 0; k0 < CI; k0 += 32) {
        __syncthreads();
#pragma unroll
        for (int p = 0; p < 4; p++) {
            int idx = p * 256 + tid;
            int n = idx >> 3, c4 = idx & 7;
            float4 v = *(const float4*)&d_y[((size_t)b * NN + n0 + n) * CI + k0 + c4 * 4];
            ys[(c4 * 4 + 0) * 132 + n] = v.x;
            ys[(c4 * 4 + 1) * 132 + n] = v.y;
            ys[(c4 * 4 + 2) * 132 + n] = v.z;
            ys[(c4 * 4 + 3) * 132 + n] = v.w;
            int ci = idx >> 5, g4 = idx & 31;
            *(float4*)&wsm[ci * 132 + g4 * 4] =
                *(const float4*)&d_wT[(size_t)(k0 + ci) * CC + c0 + g4 * 4];
        }
        __syncthreads();
#pragma unroll
        for (int cc = 0; cc < 32; cc++) {
            float4 wlo = *(const float4*)&wsm[cc * 132 + ty * 4];
            float4 whi = *(const float4*)&wsm[cc * 132 + 64 + ty * 4];
            float4 ylo = *(const float4*)&ys[cc * 132 + tx * 4];
            float4 yhi = *(const float4*)&ys[cc * 132 + 64 + tx * 4];
            u64 yp[4] = {pk2(ylo.x, ylo.y), pk2(ylo.z, ylo.w),
                         pk2(yhi.x, yhi.y), pk2(yhi.z, yhi.w)};
            const float wv[8] = {wlo.x, wlo.y, wlo.z, wlo.w,
                                 whi.x, whi.y, whi.z, whi.w};
#pragma unroll
            for (int i = 0; i < 8; i++) {
                u64 wd = dup2(wv[i]);
#pragma unroll
                for (int j = 0; j < 4; j++) fma2(acc2[i][j], wd, yp[j]);
            }
        }
    }

#pragma unroll
    for (int i = 0; i < 8; i++) {
        int c = c0 + ((i < 4) ? (ty * 4 + i) : (64 + ty * 4 + i - 4));
        float inv = gamma[c] * rsqrtf(var[c] + 1e-5f);
        float be  = (W_b[c] - mean[c]) * inv + beta[c];
        float a[8];
        up2(a[0], a[1], acc2[i][0]); up2(a[2], a[3], acc2[i][1]);
        up2(a[4], a[5], acc2[i][2]); up2(a[6], a[7], acc2[i][3]);
        const float* fr = &fuse[((size_t)b * CC + c) * NN + n0];
        float* orow = &out[((size_t)b * 768 + 256 + c) * NN + n0];
        float4 f0 = *(const float4*)&fr[tx * 4];
        float4 f1 = *(const float4*)&fr[64 + tx * 4];
        *(float4*)&orow[tx * 4] = make_float4(a[0]*inv + be + f0.x, a[1]*inv + be + f0.y,
                                              a[2]*inv + be + f0.z, a[3]*inv + be + f0.w);
        *(float4*)&orow[64 + tx * 4] = make_float4(a[4]*inv + be + f1.x, a[5]*inv + be + f1.y,
                                                   a[6]*inv + be + f1.z, a[7]*inv + be + f1.w);
    }
}

// =====================================================================
extern "C" void kernel_launch(void* const* d_in, const int* in_sizes, int n_in,
                              void* d_out, int out_size)
{
    const float* lc      = (const float*)d_in[0];
    const float* fuse    = (const float*)d_in[1];
    const float* gc      = (const float*)d_in[2];
    const float* g_w     = (const float*)d_in[3];
    const float* g_b     = (const float*)d_in[4];
    const float* theta_w = (const float*)d_in[5];
    const float* theta_b = (const float*)d_in[6];
    const float* phi_w   = (const float*)d_in[7];
    const float* phi_b   = (const float*)d_in[8];
    const float* W_w     = (const float*)d_in[9];
    const float* W_b     = (const float*)d_in[10];
    const float* bn_g    = (const float*)d_in[11];
    const float* bn_b    = (const float*)d_in[12];
    const float* bn_m    = (const float*)d_in[13];
    const float* bn_v    = (const float*)d_in[14];
    float* out = (float*)d_out;

    (void)in_sizes; (void)n_in; (void)out_size;

    cudaFuncSetAttribute(attn_kernel, cudaFuncAttributeMaxDynamicSharedMemorySize,
                         ATTN_SMEM_BYTES);

    wt_kernel<<<32, 256>>>(W_w);

    proj_kernel<<<dim3(32, BB, 3), 256>>>(fuse, g_w, g_b, theta_w, theta_b,
                                          phi_w, phi_b,
                                          (const float4*)lc, (const float4*)gc,
                                          (float4*)out);

    split_kernel<<<6144, 256>>>();

    attn_kernel<<<dim3(NN / 128, BB), 256, ATTN_SMEM_BYTES>>>();

    wz_kernel<<<dim3(NN / 128, CC / 128, BB), 256>>>(
        fuse, W_b, bn_g, bn_b, bn_m, bn_v, out);
}

// round 11
// speedup vs baseline: 2.4814x; 1.0271x over previous
#include <cuda_runtime.h>
#include <cuda_bf16.h>
#include <math.h>
#include <cstdint>

#define BB 8
#define CC 256
#define CI 128
#define HH 64
#define WWID 64
#define NN 4096
#define NK 1024

typedef unsigned long long u64;

// ---------------- packed fp32x2 helpers (FFMA2) ----------------
__device__ __forceinline__ u64 pk2(float lo, float hi) {
    u64 r; asm("mov.b64 %0, {%1, %2};" : "=l"(r) : "f"(lo), "f"(hi)); return r;
}
__device__ __forceinline__ u64 dup2(float v) { return pk2(v, v); }
__device__ __forceinline__ void up2(float& lo, float& hi, u64 v) {
    asm("mov.b64 {%0, %1}, %2;" : "=f"(lo), "=f"(hi) : "l"(v));
}
__device__ __forceinline__ void fma2(u64& d, u64 a, u64 b) {
    asm("fma.rn.f32x2 %0, %1, %2, %0;" : "+l"(d) : "l"(a), "l"(b));
}

// ---------------- warp-MMA / async-copy helpers (sm_80-era PTX) ----------------
__device__ __forceinline__ uint32_t smem_u32(const void* p) {
    uint32_t a;
    asm("{ .reg .u64 t; cvta.to.shared.u64 t, %1; cvt.u32.u64 %0, t; }" : "=r"(a) : "l"(p));
    return a;
}
// res = {lo=a, hi=b} packed bf16x2
#define CVT_BF16X2(res, a, b) \
    asm("cvt.rn.satfinite.bf16x2.f32 %0, %1, %2;" : "=r"(res) : "f"(b), "f"(a))

__device__ __forceinline__ void ldsm_x4(uint32_t& a0, uint32_t& a1, uint32_t& a2,
                                        uint32_t& a3, uint32_t addr) {
    asm volatile("ldmatrix.sync.aligned.m8n8.x4.shared.b16 {%0,%1,%2,%3}, [%4];"
                 : "=r"(a0), "=r"(a1), "=r"(a2), "=r"(a3) : "r"(addr));
}
__device__ __forceinline__ void mma_bf16(float* c, uint32_t a0, uint32_t a1,
                                         uint32_t a2, uint32_t a3,
                                         uint32_t b0, uint32_t b1) {
    asm volatile("mma.sync.aligned.m16n8k16.row.col.f32.bf16.bf16.f32 "
                 "{%0,%1,%2,%3}, {%4,%5,%6,%7}, {%8,%9}, {%0,%1,%2,%3};"
                 : "+f"(c[0]), "+f"(c[1]), "+f"(c[2]), "+f"(c[3])
                 : "r"(a0), "r"(a1), "r"(a2), "r"(a3), "r"(b0), "r"(b1));
}
__device__ __forceinline__ void cp_async16(uint32_t s, const void* g) {
    asm volatile("cp.async.ca.shared.global [%0], [%1], 16;" :: "r"(s), "l"(g));
}
#define CP_COMMIT() asm volatile("cp.async.commit_group;" ::: "memory")
#define CP_WAIT(n)  asm volatile("cp.async.wait_group %0;" :: "n"(n) : "memory")

// split a float into bf16 hi + bf16 lo residue, 4-wide packers
__device__ __forceinline__ void split4(const float* v, uint2& h, uint2& l) {
    float h0 = __bfloat162float(__float2bfloat16(v[0]));
    float h1 = __bfloat162float(__float2bfloat16(v[1]));
    float h2 = __bfloat162float(__float2bfloat16(v[2]));
    float h3 = __bfloat162float(__float2bfloat16(v[3]));
    CVT_BF16X2(h.x, v[0], v[1]);
    CVT_BF16X2(h.y, v[2], v[3]);
    CVT_BF16X2(l.x, v[0] - h0, v[1] - h1);
    CVT_BF16X2(l.y, v[2] - h2, v[3] - h3);
}

// ---------------- scratch (device globals) ----------------
__device__ __align__(16) float d_y[BB * NN * CI];       // [B][N][CI]
__device__ __align__(16) float d_wT[CI * CC];
__device__ __align__(16) __nv_bfloat16 d_thh[BB * NN * CI];   // theta [B][N][CI]
__device__ __align__(16) __nv_bfloat16 d_thl[BB * NN * CI];
__device__ __align__(16) __nv_bfloat16 d_phh[BB * NK * CI];   // phi   [B][Nk][CI]
__device__ __align__(16) __nv_bfloat16 d_phl[BB * NK * CI];
__device__ __align__(16) __nv_bfloat16 d_gh[BB * CI * NK];    // g     [B][CI][Nk]
__device__ __align__(16) __nv_bfloat16 d_gl[BB * CI * NK];

// =====================================================================
// Kernel 0: transpose W_w -> d_wT
// =====================================================================
__global__ void wt_kernel(const float* __restrict__ Ww)
{
    int idx = blockIdx.x * 256 + threadIdx.x;
    if (idx < CC * (CI / 4)) {
        int c  = idx >> 5;
        int g4 = idx & 31;
        float4 v = ((const float4*)Ww)[idx];
        int ci = g4 * 4;
        d_wT[(ci + 0) * CC + c] = v.x;
        d_wT[(ci + 1) * CC + c] = v.y;
        d_wT[(ci + 2) * CC + c] = v.z;
        d_wT[(ci + 3) * CC + c] = v.w;
    }
}

// =====================================================================
// Kernel 1: fused projections + lc/gc copy; epilogue writes bf16 hi/lo
// splits directly (no fp32 round-trip, no separate split kernel).
// grid (32, B, 3), block 256.
// =====================================================================
__global__ __launch_bounds__(256, 2)
void proj_kernel(const float* __restrict__ x,
                 const float* __restrict__ g_w,  const float* __restrict__ g_b,
                 const float* __restrict__ th_w, const float* __restrict__ th_b,
                 const float* __restrict__ ph_w, const float* __restrict__ ph_b,
                 const float4* __restrict__ lc4, const float4* __restrict__ gc4,
                 float4* __restrict__ out4)
{
    const int r    = blockIdx.x;
    const int b    = blockIdx.y;
    const int proj = blockIdx.z;
    const int tid  = threadIdx.x;

    {   // folded lc/gc band copy
        int cta = blockIdx.x + 32 * (blockIdx.y + 8 * blockIdx.z);
        const size_t PER_B = 262144, TOT = (size_t)BB * PER_B, OUT_B = 786432;
        const size_t stride = (size_t)768 * 256;
        for (size_t i = (size_t)cta * 256 + tid; i < TOT; i += stride) {
            size_t bidx = i / PER_B, rem = i % PER_B;
            out4[bidx * OUT_B + rem]             = lc4[i];
            out4[bidx * OUT_B + 2 * PER_B + rem] = gc4[i];
        }
    }

    const float* w;  const float* bias;
    if (proj == 0)      { w = th_w; bias = th_b; }
    else if (proj == 1) { w = ph_w; bias = ph_b; }
    else                { w = g_w;  bias = g_b;  }

    __shared__ __align__(16) float pool[8448];
    float* xs = pool;
    float* ws = pool + 4096;

    const int ty = tid >> 4;
    const int tx = tid & 15;

    u64 acc2[8][4];
#pragma unroll
    for (int i = 0; i < 8; i++)
#pragma unroll
        for (int j = 0; j < 4; j++) acc2[i][j] = 0ull;

    const float* xb = x + ((size_t)b * CC) * NN + (2 * r) * WWID;

    for (int k0 = 0; k0 < CC; k0 += 32) {
#pragma unroll
        for (int i = 0; i < 16; i++) {
            int l = tid + i * 256;
            int chn = l >> 7, p = l & 127;
            int row = p >> 6, wcol = p & 63;
            int perm = ((wcol >> 1) << 2) | (row << 1) | (wcol & 1);
            xs[chn * 128 + perm] = xb[(size_t)(k0 + chn) * NN + row * WWID + wcol];
        }
#pragma unroll
        for (int i = 0; i < 16; i++) {
            int l = tid + i * 256;
            int ci = l >> 5, kk = l & 31;
            ws[kk * 132 + ci] = w[ci * CC + k0 + kk];
        }
        __syncthreads();
#pragma unroll
        for (int kk = 0; kk < 32; kk++) {
            float a[8];
            *(float4*)&a[0] = *(const float4*)&xs[kk * 128 + ty * 8];
            *(float4*)&a[4] = *(const float4*)&xs[kk * 128 + ty * 8 + 4];
            float4 blo = *(const float4*)&ws[kk * 132 + tx * 4];
            float4 bhi = *(const float4*)&ws[kk * 132 + 64 + tx * 4];
            u64 bp[4] = {pk2(blo.x, blo.y), pk2(blo.z, blo.w),
                         pk2(bhi.x, bhi.y), pk2(bhi.z, bhi.w)};
#pragma unroll
            for (int i = 0; i < 8; i++) {
                u64 ad = dup2(a[i]);
#pragma unroll
                for (int j = 0; j < 4; j++) fma2(acc2[i][j], ad, bp[j]);
            }
        }
        __syncthreads();
    }

    float accf[8][8];
#pragma unroll
    for (int i = 0; i < 8; i++) {
        up2(accf[i][0], accf[i][1], acc2[i][0]);
        up2(accf[i][2], accf[i][3], acc2[i][1]);
        up2(accf[i][4], accf[i][5], acc2[i][2]);
        up2(accf[i][6], accf[i][7], acc2[i][3]);
    }
    float blov[4], bhiv[4];
    *(float4*)blov = *(const float4*)&bias[tx * 4];
    *(float4*)bhiv = *(const float4*)&bias[64 + tx * 4];

    if (proj == 0) {
        // theta: n-major bf16 hi/lo direct stores
#pragma unroll
        for (int i = 0; i < 8; i++) {
            int pm = ty * 8 + i, group = pm >> 2, pos = pm & 3;
            int n = (2 * r + (pos >> 1)) * WWID + ((group << 1) | (pos & 1));
            float vlo[4], vhi[4];
#pragma unroll
            for (int j = 0; j < 4; j++) {
                vlo[j] = accf[i][j] + blov[j];
                vhi[j] = accf[i][4 + j] + bhiv[j];
            }
            size_t base = ((size_t)(b * NN + n)) * CI;
            uint2 h, l;
            split4(vlo, h, l);
            *(uint2*)(d_thh + base + tx * 4) = h;
            *(uint2*)(d_thl + base + tx * 4) = l;
            split4(vhi, h, l);
            *(uint2*)(d_thh + base + 64 + tx * 4) = h;
            *(uint2*)(d_thl + base + 64 + tx * 4) = l;
        }
    } else if (proj == 1) {
        // phi: pooled, k-major bf16 hi/lo direct stores
#pragma unroll
        for (int gg = 0; gg < 2; gg++) {
            int k = r * 32 + ty * 2 + gg;
            float vlo[4], vhi[4];
#pragma unroll
            for (int j = 0; j < 4; j++) {
                vlo[j] = fmaxf(fmaxf(accf[gg*4+0][j],   accf[gg*4+1][j]),
                               fmaxf(accf[gg*4+2][j],   accf[gg*4+3][j])) + blov[j];
                vhi[j] = fmaxf(fmaxf(accf[gg*4+0][4+j], accf[gg*4+1][4+j]),
                               fmaxf(accf[gg*4+2][4+j], accf[gg*4+3][4+j])) + bhiv[j];
            }
            size_t base = ((size_t)(b * NK + k)) * CI;
            uint2 h, l;
            split4(vlo, h, l);
            *(uint2*)(d_phh + base + tx * 4) = h;
            *(uint2*)(d_phl + base + tx * 4) = l;
            split4(vhi, h, l);
            *(uint2*)(d_phh + base + 64 + tx * 4) = h;
            *(uint2*)(d_phl + base + 64 + tx * 4) = l;
        }
    } else {
        // g: pooled, d-major via fp32 smem staging, bf16 split at copy-out
        __syncthreads();
#pragma unroll
        for (int gg = 0; gg < 2; gg++) {
            int kl = ty * 2 + gg;
#pragma unroll
            for (int j = 0; j < 4; j++) {
                float mlo = fmaxf(fmaxf(accf[gg*4+0][j],   accf[gg*4+1][j]),
                                  fmaxf(accf[gg*4+2][j],   accf[gg*4+3][j]));
                float mhi = fmaxf(fmaxf(accf[gg*4+0][4+j], accf[gg*4+1][4+j]),
                                  fmaxf(accf[gg*4+2][4+j], accf[gg*4+3][4+j]));
                pool[(tx * 4 + j) * 36 + kl]      = mlo + blov[j];
                pool[(64 + tx * 4 + j) * 36 + kl] = mhi + bhiv[j];
            }
        }
        __syncthreads();
        size_t dbase = (size_t)b * CI * NK + r * 32;
#pragma unroll
        for (int p = 0; p < 4; p++) {
            int idx = p * 256 + tid;
            int ci = idx >> 3, k4 = idx & 7;
            float v[4];
            *(float4*)v = *(const float4*)&pool[ci * 36 + k4 * 4];
            uint2 h, l;
            split4(v, h, l);
            *(uint2*)(d_gh + dbase + (size_t)ci * NK + k4 * 4) = h;
            *(uint2*)(d_gl + dbase + (size_t)ci * NK + k4 * 4) = l;
        }
    }
}

// =====================================================================
// Kernel 2: warp-MMA bf16 split flash attention + cp.async double buffer.
// grid (NN/128, BB), block 256 (8 warps x 16 q).  16 key chunks of 64.
// smem: Q(hi/lo) 69,632 + 2 x 71,680 (K hi/lo + G hi/lo) = 212,992 B.
// All B-fragments loaded via ldmatrix.x4 (paired tiles).
// =====================================================================
#define SM_QH 0
#define SM_QL 34816
#define SM_BUF 69632
#define BUF_SZ 71680
#define BUF_KH 0
#define BUF_KL 17408
#define BUF_GH 34816
#define BUF_GL 53248
#define ATTN_SMEM_BYTES (SM_BUF + 2 * BUF_SZ)   // 212,992

__device__ __forceinline__ void prefetch_chunk(uint32_t bufb, int b, int c0, int tid)
{
    const __nv_bfloat16* kh = d_phh + (size_t)(b * NK + c0) * CI;
    const __nv_bfloat16* kl = d_phl + (size_t)(b * NK + c0) * CI;
    const __nv_bfloat16* gh = d_gh + (size_t)b * CI * NK + c0;
    const __nv_bfloat16* gl = d_gl + (size_t)b * CI * NK + c0;
#pragma unroll
    for (int it = 0; it < 4; it++) {
        int idx = it * 256 + tid;
        int krow = idx >> 4, c8 = (idx & 15) * 8;
        cp_async16(bufb + BUF_KH + krow * 272 + c8 * 2, kh + (size_t)krow * CI + c8);
        cp_async16(bufb + BUF_KL + krow * 272 + c8 * 2, kl + (size_t)krow * CI + c8);
        int drow = idx >> 3, k8 = (idx & 7) * 8;
        cp_async16(bufb + BUF_GH + drow * 144 + k8 * 2, gh + (size_t)drow * NK + k8);
        cp_async16(bufb + BUF_GL + drow * 144 + k8 * 2, gl + (size_t)drow * NK + k8);
    }
}

__global__ __launch_bounds__(256, 1)
void attn_kernel()
{
    extern __shared__ char smc[];
    const uint32_t sb = smem_u32(smc);
    const int tid  = threadIdx.x;
    const int wid  = tid >> 5;
    const int lane = tid & 31;
    const int b    = blockIdx.y;
    const int q0   = blockIdx.x * 128;

    // prefetch chunk 0 into buffer 0
    prefetch_chunk(sb + SM_BUF, b, 0, tid);
    CP_COMMIT();

    // ---- Q tiles (once per CTA)
    {
        const __nv_bfloat16* qh = d_thh + (size_t)(b * NN + q0) * CI;
        const __nv_bfloat16* ql = d_thl + (size_t)(b * NN + q0) * CI;
#pragma unroll
        for (int it = 0; it < 8; it++) {
            int idx = it * 256 + tid;
            int row = idx >> 4, c8 = (idx & 15) * 8;
            *(uint4*)(smc + SM_QH + row * 272 + c8 * 2) =
                *(const uint4*)(qh + (size_t)row * CI + c8);
            *(uint4*)(smc + SM_QL + row * 272 + c8 * 2) =
                *(const uint4*)(ql + (size_t)row * CI + c8);
        }
    }

    // ldmatrix lane-address components
    const int a_row = (lane & 7) + 8 * ((lane >> 3) & 1);   // A x4
    const int a_col = 8 * (lane >> 4);
    const int b4_row = 8 * (lane >> 4) + (lane & 7);        // B x4 (paired tiles)
    const int b4_col = 8 * ((lane >> 3) & 1);
    const int Rbase = wid * 16;

    float yacc[16][4];
#pragma unroll
    for (int dt = 0; dt < 16; dt++)
#pragma unroll
        for (int j = 0; j < 4; j++) yacc[dt][j] = 0.f;
    float m0 = -1e30f, m1 = -1e30f, l0 = 0.f, l1 = 0.f;

#pragma unroll 1
    for (int ic = 0; ic < 16; ic++) {
        const uint32_t cb_buf = sb + SM_BUF + (uint32_t)(ic & 1) * BUF_SZ;

        if (ic < 15) {
            prefetch_chunk(sb + SM_BUF + (uint32_t)((ic + 1) & 1) * BUF_SZ,
                           b, (ic + 1) * 64, tid);
            CP_COMMIT();
            CP_WAIT(1);
        } else {
            CP_WAIT(0);
        }
        __syncthreads();   // chunk ic resident for all threads

        // ---- S = theta . phi^T  (16q x 64k per warp), 3 split products ----
        float sacc[8][4];
#pragma unroll
        for (int n = 0; n < 8; n++)
#pragma unroll
            for (int j = 0; j < 4; j++) sacc[n][j] = 0.f;

#pragma unroll
        for (int m = 0; m < 8; m++) {
            int cb = m * 16;
            uint32_t ah0, ah1, ah2, ah3, al0, al1, al2, al3;
            ldsm_x4(ah0, ah1, ah2, ah3,
                    sb + SM_QH + (Rbase + a_row) * 272 + (cb + a_col) * 2);
            ldsm_x4(al0, al1, al2, al3,
                    sb + SM_QL + (Rbase + a_row) * 272 + (cb + a_col) * 2);
#pragma unroll
            for (int n2 = 0; n2 < 4; n2++) {
                uint32_t kh0, kh1, kh2, kh3, kl0, kl1, kl2, kl3;
                uint32_t kaddr = (n2 * 16 + b4_row) * 272 + (cb + b4_col) * 2;
                ldsm_x4(kh0, kh1, kh2, kh3, cb_buf + BUF_KH + kaddr);
                ldsm_x4(kl0, kl1, kl2, kl3, cb_buf + BUF_KL + kaddr);
                mma_bf16(sacc[2*n2],   ah0, ah1, ah2, ah3, kh0, kh1);
                mma_bf16(sacc[2*n2],   ah0, ah1, ah2, ah3, kl0, kl1);
                mma_bf16(sacc[2*n2],   al0, al1, al2, al3, kh0, kh1);
                mma_bf16(sacc[2*n2+1], ah0, ah1, ah2, ah3, kh2, kh3);
                mma_bf16(sacc[2*n2+1], ah0, ah1, ah2, ah3, kl2, kl3);
                mma_bf16(sacc[2*n2+1], al0, al1, al2, al3, kh2, kh3);
            }
        }

        // ---- online softmax (rows r0 = lane>>2 and r0+8; quad-spread) ----
        float mc0 = -1e30f, mc1 = -1e30f;
#pragma unroll
        for (int n = 0; n < 8; n++) {
            mc0 = fmaxf(mc0, fmaxf(sacc[n][0], sacc[n][1]));
            mc1 = fmaxf(mc1, fmaxf(sacc[n][2], sacc[n][3]));
        }
        mc0 = fmaxf(mc0, __shfl_xor_sync(0xffffffffu, mc0, 1));
        mc0 = fmaxf(mc0, __shfl_xor_sync(0xffffffffu, mc0, 2));
        mc1 = fmaxf(mc1, __shfl_xor_sync(0xffffffffu, mc1, 1));
        mc1 = fmaxf(mc1, __shfl_xor_sync(0xffffffffu, mc1, 2));
        float mn0 = fmaxf(m0, mc0), mn1 = fmaxf(m1, mc1);
        float sc0 = __expf(m0 - mn0), sc1 = __expf(m1 - mn1);
        m0 = mn0; m1 = mn1;
        l0 *= sc0; l1 *= sc1;
#pragma unroll
        for (int dt = 0; dt < 16; dt++) {
            yacc[dt][0] *= sc0; yacc[dt][1] *= sc0;
            yacc[dt][2] *= sc1; yacc[dt][3] *= sc1;
        }

        // p = exp(s - m); convert to PV A-fragments (hi/lo), in registers
        uint32_t pa_h[4][4], pa_l[4][4];
#pragma unroll
        for (int n = 0; n < 8; n++) {
            float p0 = __expf(sacc[n][0] - mn0);
            float p1 = __expf(sacc[n][1] - mn0);
            float p2 = __expf(sacc[n][2] - mn1);
            float p3 = __expf(sacc[n][3] - mn1);
            l0 += p0 + p1;
            l1 += p2 + p3;
            float h0 = __bfloat162float(__float2bfloat16(p0));
            float h1 = __bfloat162float(__float2bfloat16(p1));
            float h2 = __bfloat162float(__float2bfloat16(p2));
            float h3 = __bfloat162float(__float2bfloat16(p3));
            uint32_t h01, h23, lo01, lo23;
            CVT_BF16X2(h01, p0, p1);
            CVT_BF16X2(h23, p2, p3);
            CVT_BF16X2(lo01, p0 - h0, p1 - h1);
            CVT_BF16X2(lo23, p2 - h2, p3 - h3);
            int m2 = n >> 1;
            if ((n & 1) == 0) {
                pa_h[m2][0] = h01;  pa_h[m2][1] = h23;
                pa_l[m2][0] = lo01; pa_l[m2][1] = lo23;
            } else {
                pa_h[m2][2] = h01;  pa_h[m2][3] = h23;
                pa_l[m2][2] = lo01; pa_l[m2][3] = lo23;
            }
        }

        // ---- Y += P . g  (16q x 128d per warp), 3 split products ----
#pragma unroll
        for (int m2 = 0; m2 < 4; m2++) {
            int kb = m2 * 16;
#pragma unroll
            for (int dt2 = 0; dt2 < 8; dt2++) {
                uint32_t gh0, gh1, gh2, gh3, gl0, gl1, gl2, gl3;
                uint32_t gaddr = (dt2 * 16 + b4_row) * 144 + (kb + b4_col) * 2;
                ldsm_x4(gh0, gh1, gh2, gh3, cb_buf + BUF_GH + gaddr);
                ldsm_x4(gl0, gl1, gl2, gl3, cb_buf + BUF_GL + gaddr);
                mma_bf16(yacc[2*dt2],   pa_h[m2][0], pa_h[m2][1], pa_h[m2][2], pa_h[m2][3], gh0, gh1);
                mma_bf16(yacc[2*dt2],   pa_l[m2][0], pa_l[m2][1], pa_l[m2][2], pa_l[m2][3], gh0, gh1);
                mma_bf16(yacc[2*dt2],   pa_h[m2][0], pa_h[m2][1], pa_h[m2][2], pa_h[m2][3], gl0, gl1);
                mma_bf16(yacc[2*dt2+1], pa_h[m2][0], pa_h[m2][1], pa_h[m2][2], pa_h[m2][3], gh2, gh3);
                mma_bf16(yacc[2*dt2+1], pa_l[m2][0], pa_l[m2][1], pa_l[m2][2], pa_l[m2][3], gh2, gh3);
                mma_bf16(yacc[2*dt2+1], pa_h[m2][0], pa_h[m2][1], pa_h[m2][2], pa_h[m2][3], gl2, gl3);
            }
        }
        __syncthreads();   // reads of this buffer done before it is re-prefetched
    }

    // ---- finalize ----
    l0 += __shfl_xor_sync(0xffffffffu, l0, 1);
    l0 += __shfl_xor_sync(0xffffffffu, l0, 2);
    l1 += __shfl_xor_sync(0xffffffffu, l1, 1);
    l1 += __shfl_xor_sync(0xffffffffu, l1, 2);
    float inv0 = 1.f / l0, inv1 = 1.f / l1;

    int r0 = lane >> 2;
    int cofs = (lane & 3) * 2;
    float* dst0 = d_y + ((size_t)(b * NN + q0 + Rbase + r0)) * CI;
    float* dst1 = d_y + ((size_t)(b * NN + q0 + Rbase + r0 + 8)) * CI;
#pragma unroll
    for (int dt = 0; dt < 16; dt++) {
        *(float2*)&dst0[dt * 8 + cofs] = make_float2(yacc[dt][0] * inv0, yacc[dt][1] * inv0);
        *(float2*)&dst1[dt * 8 + cofs] = make_float2(yacc[dt][2] * inv1, yacc[dt][3] * inv1);
    }
}

// =====================================================================
// Kernel 3: z = BN(conv1x1(y, W)) + fuse -> concat band 1.
// =====================================================================
__global__ __launch_bounds__(256, 2)
void wz_kernel(const float* __restrict__ fuse,
               const float* __restrict__ W_b,
               const float* __restrict__ gamma, const float* __restrict__ beta,
               const float* __restrict__ mean,  const float* __restrict__ var,
               float* __restrict__ out)
{
    __shared__ __align__(16) float ys[32 * 132];
    __shared__ __align__(16) float wsm[32 * 132];

    const int b  = blockIdx.z;
    const int c0 = blockIdx.y * 128;
    const int n0 = blockIdx.x * 128;
    const int tid = threadIdx.x;
    const int ty = tid >> 4;
    const int tx = tid & 15;

    u64 acc2[8][4];
#pragma unroll
    for (int i = 0; i < 8; i++)
#pragma unroll
        for (int j = 0; j < 4; j++) acc2[i][j] = 0ull;

    for (int k0 = 0; k0 < CI; k0 += 32) {
        __syncthreads();
#pragma unroll
        for (int p = 0; p < 4; p++) {
            int idx = p * 256 + tid;
            int n = idx >> 3, c4 = idx & 7;
            float4 v = *(const float4*)&d_y[((size_t)b * NN + n0 + n) * CI + k0 + c4 * 4];
            ys[(c4 * 4 + 0) * 132 + n] = v.x;
            ys[(c4 * 4 + 1) * 132 + n] = v.y;
            ys[(c4 * 4 + 2) * 132 + n] = v.z;
            ys[(c4 * 4 + 3) * 132 + n] = v.w;
            int ci = idx >> 5, g4 = idx & 31;
            *(float4*)&wsm[ci * 132 + g4 * 4] =
                *(const float4*)&d_wT[(size_t)(k0 + ci) * CC + c0 + g4 * 4];
        }
        __syncthreads();
#pragma unroll
        for (int cc = 0; cc < 32; cc++) {
            float4 wlo = *(const float4*)&wsm[cc * 132 + ty * 4];
            float4 whi = *(const float4*)&wsm[cc * 132 + 64 + ty * 4];
            float4 ylo = *(const float4*)&ys[cc * 132 + tx * 4];
            float4 yhi = *(const float4*)&ys[cc * 132 + 64 + tx * 4];
            u64 yp[4] = {pk2(ylo.x, ylo.y), pk2(ylo.z, ylo.w),
                         pk2(yhi.x, yhi.y), pk2(yhi.z, yhi.w)};
            const float wv[8] = {wlo.x, wlo.y, wlo.z, wlo.w,
                                 whi.x, whi.y, whi.z, whi.w};
#pragma unroll
            for (int i = 0; i < 8; i++) {
                u64 wd = dup2(wv[i]);
#pragma unroll
                for (int j = 0; j < 4; j++) fma2(acc2[i][j], wd, yp[j]);
            }
        }
    }

#pragma unroll
    for (int i = 0; i < 8; i++) {
        int c = c0 + ((i < 4) ? (ty * 4 + i) : (64 + ty * 4 + i - 4));
        float inv = gamma[c] * rsqrtf(var[c] + 1e-5f);
        float be  = (W_b[c] - mean[c]) * inv + beta[c];
        float a[8];
        up2(a[0], a[1], acc2[i][0]); up2(a[2], a[3], acc2[i][1]);
        up2(a[4], a[5], acc2[i][2]); up2(a[6], a[7], acc2[i][3]);
        const float* fr = &fuse[((size_t)b * CC + c) * NN + n0];
        float* orow = &out[((size_t)b * 768 + 256 + c) * NN + n0];
        float4 f0 = *(const float4*)&fr[tx * 4];
        float4 f1 = *(const float4*)&fr[64 + tx * 4];
        *(float4*)&orow[tx * 4] = make_float4(a[0]*inv + be + f0.x, a[1]*inv + be + f0.y,
                                              a[2]*inv + be + f0.z, a[3]*inv + be + f0.w);
        *(float4*)&orow[64 + tx * 4] = make_float4(a[4]*inv + be + f1.x, a[5]*inv + be + f1.y,
                                                   a[6]*inv + be + f1.z, a[7]*inv + be + f1.w);
    }
}

// =====================================================================
extern "C" void kernel_launch(void* const* d_in, const int* in_sizes, int n_in,
                              void* d_out, int out_size)
{
    const float* lc      = (const float*)d_in[0];
    const float* fuse    = (const float*)d_in[1];
    const float* gc      = (const float*)d_in[2];
    const float* g_w     = (const float*)d_in[3];
    const float* g_b     = (const float*)d_in[4];
    const float* theta_w = (const float*)d_in[5];
    const float* theta_b = (const float*)d_in[6];
    const float* phi_w   = (const float*)d_in[7];
    const float* phi_b   = (const float*)d_in[8];
    const float* W_w     = (const float*)d_in[9];
    const float* W_b     = (const float*)d_in[10];
    const float* bn_g    = (const float*)d_in[11];
    const float* bn_b    = (const float*)d_in[12];
    const float* bn_m    = (const float*)d_in[13];
    const float* bn_v    = (const float*)d_in[14];
    float* out = (float*)d_out;

    (void)in_sizes; (void)n_in; (void)out_size;

    cudaFuncSetAttribute(attn_kernel, cudaFuncAttributeMaxDynamicSharedMemorySize,
                         ATTN_SMEM_BYTES);

    wt_kernel<<<32, 256>>>(W_w);

    proj_kernel<<<dim3(32, BB, 3), 256>>>(fuse, g_w, g_b, theta_w, theta_b,
                                          phi_w, phi_b,
                                          (const float4*)lc, (const float4*)gc,
                                          (float4*)out);

    attn_kernel<<<dim3(NN / 128, BB), 256, ATTN_SMEM_BYTES>>>();

    wz_kernel<<<dim3(NN / 128, CC / 128, BB), 256>>>(
        fuse, W_b, bn_g, bn_b, bn_m, bn_v, out);
}

// round 12
// speedup vs baseline: 2.6086x; 1.0513x over previous
#include <cuda_runtime.h>
#include <cuda_bf16.h>
#include <math.h>
#include <cstdint>

#define BB 8
#define CC 256
#define CI 128
#define HH 64
#define WWID 64
#define NN 4096
#define NK 1024

typedef unsigned long long u64;

// ---------------- packed fp32x2 helpers (FFMA2) ----------------
__device__ __forceinline__ u64 pk2(float lo, float hi) {
    u64 r; asm("mov.b64 %0, {%1, %2};" : "=l"(r) : "f"(lo), "f"(hi)); return r;
}
__device__ __forceinline__ u64 dup2(float v) { return pk2(v, v); }
__device__ __forceinline__ void up2(float& lo, float& hi, u64 v) {
    asm("mov.b64 {%0, %1}, %2;" : "=f"(lo), "=f"(hi) : "l"(v));
}
__device__ __forceinline__ void fma2(u64& d, u64 a, u64 b) {
    asm("fma.rn.f32x2 %0, %1, %2, %0;" : "+l"(d) : "l"(a), "l"(b));
}

// ---------------- warp-MMA / async-copy helpers (sm_80-era PTX) ----------------
__device__ __forceinline__ uint32_t smem_u32(const void* p) {
    uint32_t a;
    asm("{ .reg .u64 t; cvta.to.shared.u64 t, %1; cvt.u32.u64 %0, t; }" : "=r"(a) : "l"(p));
    return a;
}
#define CVT_BF16X2(res, a, b) \
    asm("cvt.rn.satfinite.bf16x2.f32 %0, %1, %2;" : "=r"(res) : "f"(b), "f"(a))

__device__ __forceinline__ void ldsm_x4(uint32_t& a0, uint32_t& a1, uint32_t& a2,
                                        uint32_t& a3, uint32_t addr) {
    asm volatile("ldmatrix.sync.aligned.m8n8.x4.shared.b16 {%0,%1,%2,%3}, [%4];"
                 : "=r"(a0), "=r"(a1), "=r"(a2), "=r"(a3) : "r"(addr));
}
__device__ __forceinline__ void mma_bf16(float* c, uint32_t a0, uint32_t a1,
                                         uint32_t a2, uint32_t a3,
                                         uint32_t b0, uint32_t b1) {
    asm volatile("mma.sync.aligned.m16n8k16.row.col.f32.bf16.bf16.f32 "
                 "{%0,%1,%2,%3}, {%4,%5,%6,%7}, {%8,%9}, {%0,%1,%2,%3};"
                 : "+f"(c[0]), "+f"(c[1]), "+f"(c[2]), "+f"(c[3])
                 : "r"(a0), "r"(a1), "r"(a2), "r"(a3), "r"(b0), "r"(b1));
}
__device__ __forceinline__ void cp_async16(uint32_t s, const void* g) {
    asm volatile("cp.async.ca.shared.global [%0], [%1], 16;" :: "r"(s), "l"(g));
}
#define CP_COMMIT() asm volatile("cp.async.commit_group;" ::: "memory")
#define CP_WAIT(n)  asm volatile("cp.async.wait_group %0;" :: "n"(n) : "memory")

// split helpers (fp32 -> bf16 hi + bf16 residue lo)
__device__ __forceinline__ void split4(const float* v, uint2& h, uint2& l) {
    float h0 = __bfloat162float(__float2bfloat16(v[0]));
    float h1 = __bfloat162float(__float2bfloat16(v[1]));
    float h2 = __bfloat162float(__float2bfloat16(v[2]));
    float h3 = __bfloat162float(__float2bfloat16(v[3]));
    CVT_BF16X2(h.x, v[0], v[1]);
    CVT_BF16X2(h.y, v[2], v[3]);
    CVT_BF16X2(l.x, v[0] - h0, v[1] - h1);
    CVT_BF16X2(l.y, v[2] - h2, v[3] - h3);
}
__device__ __forceinline__ void split2(float a, float b, uint32_t& h, uint32_t& l) {
    float ha = __bfloat162float(__float2bfloat16(a));
    float hb = __bfloat162float(__float2bfloat16(b));
    CVT_BF16X2(h, a, b);
    CVT_BF16X2(l, a - ha, b - hb);
}
__device__ __forceinline__ float qmax(float v) {
    v = fmaxf(v, __shfl_xor_sync(0xffffffffu, v, 4));
    v = fmaxf(v, __shfl_xor_sync(0xffffffffu, v, 8));
    return v;
}

// ---------------- scratch (device globals) ----------------
__device__ __align__(16) float d_y[BB * NN * CI];             // [B][N][CI]
__device__ __align__(16) float d_wT[CI * CC];
__device__ __align__(16) __nv_bfloat16 d_thh[BB * NN * CI];   // theta [B][N][CI]
__device__ __align__(16) __nv_bfloat16 d_thl[BB * NN * CI];
__device__ __align__(16) __nv_bfloat16 d_phh[BB * NK * CI];   // phi   [B][Nk][CI]
__device__ __align__(16) __nv_bfloat16 d_phl[BB * NK * CI];
__device__ __align__(16) __nv_bfloat16 d_gh[BB * CI * NK];    // g     [B][CI][Nk]
__device__ __align__(16) __nv_bfloat16 d_gl[BB * CI * NK];
__device__ __align__(16) __nv_bfloat16 d_xh[BB * NN * CC];    // xT    [B][n_perm][C]
__device__ __align__(16) __nv_bfloat16 d_xl[BB * NN * CC];
__device__ __align__(16) __nv_bfloat16 d_wsh[3 * CI * CC];    // w     [z][CI][C]
__device__ __align__(16) __nv_bfloat16 d_wsl[3 * CI * CC];

// =====================================================================
// Kernel 0a: transpose W_w -> d_wT (for wz)
// =====================================================================
__global__ void wt_kernel(const float* __restrict__ Ww)
{
    int idx = blockIdx.x * 256 + threadIdx.x;
    if (idx < CC * (CI / 4)) {
        int c  = idx >> 5;
        int g4 = idx & 31;
        float4 v = ((const float4*)Ww)[idx];
        int ci = g4 * 4;
        d_wT[(ci + 0) * CC + c] = v.x;
        d_wT[(ci + 1) * CC + c] = v.y;
        d_wT[(ci + 2) * CC + c] = v.z;
        d_wT[(ci + 3) * CC + c] = v.w;
    }
}

// =====================================================================
// Kernel 0b: split projection weights -> bf16 hi/lo.  z: 0=theta,1=phi,2=g
// =====================================================================
__global__ void wsplit_kernel(const float* __restrict__ th_w,
                              const float* __restrict__ ph_w,
                              const float* __restrict__ g_w)
{
    const int PER = CI * CC / 4;   // 8192 float4 per matrix
    int idx = blockIdx.x * 256 + threadIdx.x;
    if (idx >= 3 * PER) return;
    int z = idx / PER, off = idx - z * PER;
    const float* src = (z == 0) ? th_w : (z == 1) ? ph_w : g_w;
    float v[4];
    *(float4*)v = ((const float4*)src)[off];
    uint2 h, l;
    split4(v, h, l);
    ((uint2*)(d_wsh + (size_t)z * CI * CC))[off] = h;
    ((uint2*)(d_wsl + (size_t)z * CI * CC))[off] = l;
}

// =====================================================================
// Kernel 0c: split_x — fuse [B][C][N] -> xT bf16 hi/lo [B][n_perm][C].
// n_perm: within each image-row-pair r, pixels are pool-group permuted
// (perm = (pw<<2)|(row<<1)|(w&1)), so a 2x2 pool = 4 consecutive rows.
// grid (32 rowpairs, 4 c-chunks, B), block 256.
// =====================================================================
__global__ __launch_bounds__(256, 2)
void splitx_kernel(const float* __restrict__ x)
{
    __shared__ float tile[64 * 132];   // [c][perm]
    const int r  = blockIdx.x;
    const int c0 = blockIdx.y * 64;
    const int b  = blockIdx.z;
    const int tid = threadIdx.x;

    const float* xb = x + ((size_t)b * CC + c0) * NN + (2 * r) * WWID;
#pragma unroll
    for (int it = 0; it < 8; it++) {
        int id = it * 256 + tid;
        int c = id >> 5, n4 = id & 31;
        float4 v = *(const float4*)&xb[(size_t)c * NN + ((n4 * 4) >> 6) * WWID + ((n4 * 4) & 63)];
        // 4 consecutive pixels share the same image row (n4*4..n4*4+3, row = n4>=16)
        int row = (n4 * 4) >> 6;
#pragma unroll
        for (int e = 0; e < 4; e++) {
            int wcol = (n4 * 4 + e) & 63;
            int perm = ((wcol >> 1) << 2) | (row << 1) | (wcol & 1);
            tile[c * 132 + perm] = ((const float*)&v)[e];
        }
    }
    __syncthreads();

    __nv_bfloat16* oh = d_xh + ((size_t)b * NN + r * 128) * CC + c0;
    __nv_bfloat16* ol = d_xl + ((size_t)b * NN + r * 128) * CC + c0;
#pragma unroll
    for (int it = 0; it < 8; it++) {
        int id = it * 256 + tid;
        int p = id >> 4, cq = (id & 15) * 4;
        float v[4];
        v[0] = tile[(cq + 0) * 132 + p];
        v[1] = tile[(cq + 1) * 132 + p];
        v[2] = tile[(cq + 2) * 132 + p];
        v[3] = tile[(cq + 3) * 132 + p];
        uint2 h, l;
        split4(v, h, l);
        *(uint2*)(oh + (size_t)p * CC + cq) = h;
        *(uint2*)(ol + (size_t)p * CC + cq) = l;
    }
}

// =====================================================================
// Kernel 1: tensor-core projections + lc/gc copy.
// grid (32 rowpairs, B, 3 proj), block 256 (8 warps x 16 px rows).
// A = xT [128px][K], B = w [128ci][K]; K=256 in 4 cp.async-double-buffered
// chunks of 64.  3-product split-bf16.  Epilogue: bias, de-permute (theta)
// or shfl-maxpool (phi/g), bf16 hi/lo stores in attn's layouts.
// smem: 2 buf x (A hi/lo + B hi/lo) x 128x144B = 147,456 B.
// =====================================================================
#define PJ_AH 0
#define PJ_AL 18432
#define PJ_BH 36864
#define PJ_BL 55296
#define PJ_BUF 73728
#define PROJ_SMEM_BYTES (2 * PJ_BUF)

__device__ __forceinline__ void pj_prefetch(uint32_t bufb,
                                            const __nv_bfloat16* xh,
                                            const __nv_bfloat16* xl,
                                            const __nv_bfloat16* wh,
                                            const __nv_bfloat16* wl,
                                            int k0, int tid)
{
#pragma unroll
    for (int it = 0; it < 4; it++) {
        int idx = it * 256 + tid;              // 0..1023
        int row = idx >> 3, c8 = (idx & 7) * 8;
        uint32_t so = row * 144 + c8 * 2;
        cp_async16(bufb + PJ_AH + so, xh + (size_t)row * CC + k0 + c8);
        cp_async16(bufb + PJ_AL + so, xl + (size_t)row * CC + k0 + c8);
        cp_async16(bufb + PJ_BH + so, wh + (size_t)row * CC + k0 + c8);
        cp_async16(bufb + PJ_BL + so, wl + (size_t)row * CC + k0 + c8);
    }
}

__global__ __launch_bounds__(256, 1)
void proj_mma_kernel(const float* __restrict__ g_b,
                     const float* __restrict__ th_b,
                     const float* __restrict__ ph_b,
                     const float4* __restrict__ lc4, const float4* __restrict__ gc4,
                     float4* __restrict__ out4)
{
    extern __shared__ char smc[];
    const uint32_t sb = smem_u32(smc);
    const int r    = blockIdx.x;
    const int b    = blockIdx.y;
    const int z    = blockIdx.z;   // 0 theta, 1 phi, 2 g
    const int tid  = threadIdx.x;
    const int wid  = tid >> 5;
    const int lane = tid & 31;

    {   // folded lc/gc band copy (tensor-bound kernel: DRAM is free)
        int cta = blockIdx.x + 32 * (blockIdx.y + 8 * blockIdx.z);
        const size_t PER_B = 262144, TOT = (size_t)BB * PER_B, OUT_B = 786432;
        const size_t stride = (size_t)768 * 256;
        for (size_t i = (size_t)cta * 256 + tid; i < TOT; i += stride) {
            size_t bidx = i / PER_B, rem = i % PER_B;
            out4[bidx * OUT_B + rem]             = lc4[i];
            out4[bidx * OUT_B + 2 * PER_B + rem] = gc4[i];
        }
    }

    const __nv_bfloat16* xh = d_xh + ((size_t)b * NN + r * 128) * CC;
    const __nv_bfloat16* xl = d_xl + ((size_t)b * NN + r * 128) * CC;
    const __nv_bfloat16* wh = d_wsh + (size_t)z * CI * CC;
    const __nv_bfloat16* wl = d_wsl + (size_t)z * CI * CC;
    const float* bias = (z == 0) ? th_b : (z == 1) ? ph_b : g_b;

    pj_prefetch(sb, xh, xl, wh, wl, 0, tid);
    CP_COMMIT();

    // fragment lane addressing (identical to attn's validated patterns)
    const int a_row = (lane & 7) + 8 * ((lane >> 3) & 1);
    const int a_col = 8 * (lane >> 4);
    const int b4_row = 8 * (lane >> 4) + (lane & 7);
    const int b4_col = 8 * ((lane >> 3) & 1);
    const int Rbase = wid * 16;

    float cacc[16][4];
#pragma unroll
    for (int nt = 0; nt < 16; nt++)
#pragma unroll
        for (int j = 0; j < 4; j++) cacc[nt][j] = 0.f;

#pragma unroll 1
    for (int ic = 0; ic < 4; ic++) {
        const uint32_t buf = sb + (uint32_t)(ic & 1) * PJ_BUF;
        if (ic < 3) {
            pj_prefetch(sb + (uint32_t)((ic + 1) & 1) * PJ_BUF, xh, xl, wh, wl,
                        (ic + 1) * 64, tid);
            CP_COMMIT();
            CP_WAIT(1);
        } else {
            CP_WAIT(0);
        }
        __syncthreads();

#pragma unroll
        for (int ks = 0; ks < 4; ks++) {
            int cb = ks * 16;
            uint32_t ah0, ah1, ah2, ah3, al0, al1, al2, al3;
            uint32_t aaddr = (Rbase + a_row) * 144 + (cb + a_col) * 2;
            ldsm_x4(ah0, ah1, ah2, ah3, buf + PJ_AH + aaddr);
            ldsm_x4(al0, al1, al2, al3, buf + PJ_AL + aaddr);
#pragma unroll
            for (int n2 = 0; n2 < 8; n2++) {
                uint32_t bh0, bh1, bh2, bh3, bl0, bl1, bl2, bl3;
                uint32_t baddr = (n2 * 16 + b4_row) * 144 + (cb + b4_col) * 2;
                ldsm_x4(bh0, bh1, bh2, bh3, buf + PJ_BH + baddr);
                ldsm_x4(bl0, bl1, bl2, bl3, buf + PJ_BL + baddr);
                mma_bf16(cacc[2*n2],   ah0, ah1, ah2, ah3, bh0, bh1);
                mma_bf16(cacc[2*n2],   ah0, ah1, ah2, ah3, bl0, bl1);
                mma_bf16(cacc[2*n2],   al0, al1, al2, al3, bh0, bh1);
                mma_bf16(cacc[2*n2+1], ah0, ah1, ah2, ah3, bh2, bh3);
                mma_bf16(cacc[2*n2+1], ah0, ah1, ah2, ah3, bl2, bl3);
                mma_bf16(cacc[2*n2+1], al0, al1, al2, al3, bh2, bh3);
            }
        }
        __syncthreads();
    }

    // ---- epilogue ----
    // C layout: rows p0 = Rbase + (lane>>2), p1 = p0+8 (permuted pixels);
    // cols ci = nt*8 + 2*(lane&3) + {0,1}.
    if (z == 0) {
        // theta: de-permute pixels, store [n][ci] bf16 hi/lo
        int p0 = Rbase + (lane >> 2);
        int p1 = p0 + 8;
        int g0 = p0 >> 2, s0 = p0 & 3;
        int g1 = p1 >> 2, s1 = p1 & 3;
        int n0 = (2 * r + (s0 >> 1)) * WWID + ((g0 << 1) | (s0 & 1));
        int n1 = (2 * r + (s1 >> 1)) * WWID + ((g1 << 1) | (s1 & 1));
        size_t b0 = ((size_t)(b * NN + n0)) * CI;
        size_t b1 = ((size_t)(b * NN + n1)) * CI;
#pragma unroll
        for (int nt = 0; nt < 16; nt++) {
            int ci = nt * 8 + 2 * (lane & 3);
            float bi0 = bias[ci], bi1 = bias[ci + 1];
            uint32_t h, l;
            split2(cacc[nt][0] + bi0, cacc[nt][1] + bi1, h, l);
            *(uint32_t*)(d_thh + b0 + ci) = h;
            *(uint32_t*)(d_thl + b0 + ci) = l;
            split2(cacc[nt][2] + bi0, cacc[nt][3] + bi1, h, l);
            *(uint32_t*)(d_thh + b1 + ci) = h;
            *(uint32_t*)(d_thl + b1 + ci) = l;
        }
    } else {
        // phi / g: maxpool over 4 consecutive permuted rows via shfl.
        // c{0,1} rows (lane>>2): groups wid*4 + (lane>>4); c{2,3}: +2.
        int k01 = r * 32 + wid * 4 + (lane >> 4);
        int k23 = k01 + 2;
        bool writer = ((lane >> 2) & 3) == 0;   // lanes 0-3, 16-19
#pragma unroll
        for (int nt = 0; nt < 16; nt++) {
            int ci = nt * 8 + 2 * (lane & 3);
            float m01a = qmax(cacc[nt][0]);
            float m01b = qmax(cacc[nt][1]);
            float m23a = qmax(cacc[nt][2]);
            float m23b = qmax(cacc[nt][3]);
            if (writer) {
                float bi0 = bias[ci], bi1 = bias[ci + 1];
                float v01a = m01a + bi0, v01b = m01b + bi1;
                float v23a = m23a + bi0, v23b = m23b + bi1;
                if (z == 1) {
                    uint32_t h, l;
                    split2(v01a, v01b, h, l);
                    *(uint32_t*)(d_phh + ((size_t)(b * NK + k01)) * CI + ci) = h;
                    *(uint32_t*)(d_phl + ((size_t)(b * NK + k01)) * CI + ci) = l;
                    split2(v23a, v23b, h, l);
                    *(uint32_t*)(d_phh + ((size_t)(b * NK + k23)) * CI + ci) = h;
                    *(uint32_t*)(d_phl + ((size_t)(b * NK + k23)) * CI + ci) = l;
                } else {
                    // g: [B][CI][Nk] — scalar bf16 stores
                    size_t gb = (size_t)b * CI * NK;
                    float h01a = __bfloat162float(__float2bfloat16(v01a));
                    float h01b = __bfloat162float(__float2bfloat16(v01b));
                    float h23a = __bfloat162float(__float2bfloat16(v23a));
                    float h23b = __bfloat162float(__float2bfloat16(v23b));
                    d_gh[gb + (size_t)ci * NK + k01]       = __float2bfloat16(v01a);
                    d_gh[gb + (size_t)(ci + 1) * NK + k01] = __float2bfloat16(v01b);
                    d_gh[gb + (size_t)ci * NK + k23]       = __float2bfloat16(v23a);
                    d_gh[gb + (size_t)(ci + 1) * NK + k23] = __float2bfloat16(v23b);
                    d_gl[gb + (size_t)ci * NK + k01]       = __float2bfloat16(v01a - h01a);
                    d_gl[gb + (size_t)(ci + 1) * NK + k01] = __float2bfloat16(v01b - h01b);
                    d_gl[gb + (size_t)ci * NK + k23]       = __float2bfloat16(v23a - h23a);
                    d_gl[gb + (size_t)(ci + 1) * NK + k23] = __float2bfloat16(v23b - h23b);
                }
            }
        }
    }
}

// =====================================================================
// Kernel 2: warp-MMA bf16 split flash attention (unchanged from R11 PASS).
// =====================================================================
#define SM_QH 0
#define SM_QL 34816
#define SM_BUF 69632
#define BUF_SZ 71680
#define BUF_KH 0
#define BUF_KL 17408
#define BUF_GH 34816
#define BUF_GL 53248
#define ATTN_SMEM_BYTES (SM_BUF + 2 * BUF_SZ)   // 212,992

__device__ __forceinline__ void prefetch_chunk(uint32_t bufb, int b, int c0, int tid)
{
    const __nv_bfloat16* kh = d_phh + (size_t)(b * NK + c0) * CI;
    const __nv_bfloat16* kl = d_phl + (size_t)(b * NK + c0) * CI;
    const __nv_bfloat16* gh = d_gh + (size_t)b * CI * NK + c0;
    const __nv_bfloat16* gl = d_gl + (size_t)b * CI * NK + c0;
#pragma unroll
    for (int it = 0; it < 4; it++) {
        int idx = it * 256 + tid;
        int krow = idx >> 4, c8 = (idx & 15) * 8;
        cp_async16(bufb + BUF_KH + krow * 272 + c8 * 2, kh + (size_t)krow * CI + c8);
        cp_async16(bufb + BUF_KL + krow * 272 + c8 * 2, kl + (size_t)krow * CI + c8);
        int drow = idx >> 3, k8 = (idx & 7) * 8;
        cp_async16(bufb + BUF_GH + drow * 144 + k8 * 2, gh + (size_t)drow * NK + k8);
        cp_async16(bufb + BUF_GL + drow * 144 + k8 * 2, gl + (size_t)drow * NK + k8);
    }
}

__global__ __launch_bounds__(256, 1)
void attn_kernel()
{
    extern __shared__ char smc[];
    const uint32_t sb = smem_u32(smc);
    const int tid  = threadIdx.x;
    const int wid  = tid >> 5;
    const int lane = tid & 31;
    const int b    = blockIdx.y;
    const int q0   = blockIdx.x * 128;

    prefetch_chunk(sb + SM_BUF, b, 0, tid);
    CP_COMMIT();

    {
        const __nv_bfloat16* qh = d_thh + (size_t)(b * NN + q0) * CI;
        const __nv_bfloat16* ql = d_thl + (size_t)(b * NN + q0) * CI;
#pragma unroll
        for (int it = 0; it < 8; it++) {
            int idx = it * 256 + tid;
            int row = idx >> 4, c8 = (idx & 15) * 8;
            *(uint4*)(smc + SM_QH + row * 272 + c8 * 2) =
                *(const uint4*)(qh + (size_t)row * CI + c8);
            *(uint4*)(smc + SM_QL + row * 272 + c8 * 2) =
                *(const uint4*)(ql + (size_t)row * CI + c8);
        }
    }

    const int a_row = (lane & 7) + 8 * ((lane >> 3) & 1);
    const int a_col = 8 * (lane >> 4);
    const int b4_row = 8 * (lane >> 4) + (lane & 7);
    const int b4_col = 8 * ((lane >> 3) & 1);
    const int Rbase = wid * 16;

    float yacc[16][4];
#pragma unroll
    for (int dt = 0; dt < 16; dt++)
#pragma unroll
        for (int j = 0; j < 4; j++) yacc[dt][j] = 0.f;
    float m0 = -1e30f, m1 = -1e30f, l0 = 0.f, l1 = 0.f;

#pragma unroll 1
    for (int ic = 0; ic < 16; ic++) {
        const uint32_t cb_buf = sb + SM_BUF + (uint32_t)(ic & 1) * BUF_SZ;

        if (ic < 15) {
            prefetch_chunk(sb + SM_BUF + (uint32_t)((ic + 1) & 1) * BUF_SZ,
                           b, (ic + 1) * 64, tid);
            CP_COMMIT();
            CP_WAIT(1);
        } else {
            CP_WAIT(0);
        }
        __syncthreads();

        float sacc[8][4];
#pragma unroll
        for (int n = 0; n < 8; n++)
#pragma unroll
            for (int j = 0; j < 4; j++) sacc[n][j] = 0.f;

#pragma unroll
        for (int m = 0; m < 8; m++) {
            int cb = m * 16;
            uint32_t ah0, ah1, ah2, ah3, al0, al1, al2, al3;
            ldsm_x4(ah0, ah1, ah2, ah3,
                    sb + SM_QH + (Rbase + a_row) * 272 + (cb + a_col) * 2);
            ldsm_x4(al0, al1, al2, al3,
                    sb + SM_QL + (Rbase + a_row) * 272 + (cb + a_col) * 2);
#pragma unroll
            for (int n2 = 0; n2 < 4; n2++) {
                uint32_t kh0, kh1, kh2, kh3, kl0, kl1, kl2, kl3;
                uint32_t kaddr = (n2 * 16 + b4_row) * 272 + (cb + b4_col) * 2;
                ldsm_x4(kh0, kh1, kh2, kh3, cb_buf + BUF_KH + kaddr);
                ldsm_x4(kl0, kl1, kl2, kl3, cb_buf + BUF_KL + kaddr);
                mma_bf16(sacc[2*n2],   ah0, ah1, ah2, ah3, kh0, kh1);
                mma_bf16(sacc[2*n2],   ah0, ah1, ah2, ah3, kl0, kl1);
                mma_bf16(sacc[2*n2],   al0, al1, al2, al3, kh0, kh1);
                mma_bf16(sacc[2*n2+1], ah0, ah1, ah2, ah3, kh2, kh3);
                mma_bf16(sacc[2*n2+1], ah0, ah1, ah2, ah3, kl2, kl3);
                mma_bf16(sacc[2*n2+1], al0, al1, al2, al3, kh2, kh3);
            }
        }

        float mc0 = -1e30f, mc1 = -1e30f;
#pragma unroll
        for (int n = 0; n < 8; n++) {
            mc0 = fmaxf(mc0, fmaxf(sacc[n][0], sacc[n][1]));
            mc1 = fmaxf(mc1, fmaxf(sacc[n][2], sacc[n][3]));
        }
        mc0 = fmaxf(mc0, __shfl_xor_sync(0xffffffffu, mc0, 1));
        mc0 = fmaxf(mc0, __shfl_xor_sync(0xffffffffu, mc0, 2));
        mc1 = fmaxf(mc1, __shfl_xor_sync(0xffffffffu, mc1, 1));
        mc1 = fmaxf(mc1, __shfl_xor_sync(0xffffffffu, mc1, 2));
        float mn0 = fmaxf(m0, mc0), mn1 = fmaxf(m1, mc1);
        float sc0 = __expf(m0 - mn0), sc1 = __expf(m1 - mn1);
        m0 = mn0; m1 = mn1;
        l0 *= sc0; l1 *= sc1;
#pragma unroll
        for (int dt = 0; dt < 16; dt++) {
            yacc[dt][0] *= sc0; yacc[dt][1] *= sc0;
            yacc[dt][2] *= sc1; yacc[dt][3] *= sc1;
        }

        uint32_t pa_h[4][4], pa_l[4][4];
#pragma unroll
        for (int n = 0; n < 8; n++) {
            float p0 = __expf(sacc[n][0] - mn0);
            float p1 = __expf(sacc[n][1] - mn0);
            float p2 = __expf(sacc[n][2] - mn1);
            float p3 = __expf(sacc[n][3] - mn1);
            l0 += p0 + p1;
            l1 += p2 + p3;
            float h0 = __bfloat162float(__float2bfloat16(p0));
            float h1 = __bfloat162float(__float2bfloat16(p1));
            float h2 = __bfloat162float(__float2bfloat16(p2));
            float h3 = __bfloat162float(__float2bfloat16(p3));
            uint32_t h01, h23, lo01, lo23;
            CVT_BF16X2(h01, p0, p1);
            CVT_BF16X2(h23, p2, p3);
            CVT_BF16X2(lo01, p0 - h0, p1 - h1);
            CVT_BF16X2(lo23, p2 - h2, p3 - h3);
            int m2 = n >> 1;
            if ((n & 1) == 0) {
                pa_h[m2][0] = h01;  pa_h[m2][1] = h23;
                pa_l[m2][0] = lo01; pa_l[m2][1] = lo23;
            } else {
                pa_h[m2][2] = h01;  pa_h[m2][3] = h23;
                pa_l[m2][2] = lo01; pa_l[m2][3] = lo23;
            }
        }

#pragma unroll
        for (int m2 = 0; m2 < 4; m2++) {
            int kb = m2 * 16;
#pragma unroll
            for (int dt2 = 0; dt2 < 8; dt2++) {
                uint32_t gh0, gh1, gh2, gh3, gl0, gl1, gl2, gl3;
                uint32_t gaddr = (dt2 * 16 + b4_row) * 144 + (kb + b4_col) * 2;
                ldsm_x4(gh0, gh1, gh2, gh3, cb_buf + BUF_GH + gaddr);
                ldsm_x4(gl0, gl1, gl2, gl3, cb_buf + BUF_GL + gaddr);
                mma_bf16(yacc[2*dt2],   pa_h[m2][0], pa_h[m2][1], pa_h[m2][2], pa_h[m2][3], gh0, gh1);
                mma_bf16(yacc[2*dt2],   pa_l[m2][0], pa_l[m2][1], pa_l[m2][2], pa_l[m2][3], gh0, gh1);
                mma_bf16(yacc[2*dt2],   pa_h[m2][0], pa_h[m2][1], pa_h[m2][2], pa_h[m2][3], gl0, gl1);
                mma_bf16(yacc[2*dt2+1], pa_h[m2][0], pa_h[m2][1], pa_h[m2][2], pa_h[m2][3], gh2, gh3);
                mma_bf16(yacc[2*dt2+1], pa_l[m2][0], pa_l[m2][1], pa_l[m2][2], pa_l[m2][3], gh2, gh3);
                mma_bf16(yacc[2*dt2+1], pa_h[m2][0], pa_h[m2][1], pa_h[m2][2], pa_h[m2][3], gl2, gl3);
            }
        }
        __syncthreads();
    }

    l0 += __shfl_xor_sync(0xffffffffu, l0, 1);
    l0 += __shfl_xor_sync(0xffffffffu, l0, 2);
    l1 += __shfl_xor_sync(0xffffffffu, l1, 1);
    l1 += __shfl_xor_sync(0xffffffffu, l1, 2);
    float inv0 = 1.f / l0, inv1 = 1.f / l1;

    int r0 = lane >> 2;
    int cofs = (lane & 3) * 2;
    float* dst0 = d_y + ((size_t)(b * NN + q0 + Rbase + r0)) * CI;
    float* dst1 = d_y + ((size_t)(b * NN + q0 + Rbase + r0 + 8)) * CI;
#pragma unroll
    for (int dt = 0; dt < 16; dt++) {
        *(float2*)&dst0[dt * 8 + cofs] = make_float2(yacc[dt][0] * inv0, yacc[dt][1] * inv0);
        *(float2*)&dst1[dt * 8 + cofs] = make_float2(yacc[dt][2] * inv1, yacc[dt][3] * inv1);
    }
}

// =====================================================================
// Kernel 3: z = BN(conv1x1(y, W)) + fuse -> concat band 1 (unchanged).
// =====================================================================
__global__ __launch_bounds__(256, 2)
void wz_kernel(const float* __restrict__ fuse,
               const float* __restrict__ W_b,
               const float* __restrict__ gamma, const float* __restrict__ beta,
               const float* __restrict__ mean,  const float* __restrict__ var,
               float* __restrict__ out)
{
    __shared__ __align__(16) float ys[32 * 132];
    __shared__ __align__(16) float wsm[32 * 132];

    const int b  = blockIdx.z;
    const int c0 = blockIdx.y * 128;
    const int n0 = blockIdx.x * 128;
    const int tid = threadIdx.x;
    const int ty = tid >> 4;
    const int tx = tid & 15;

    u64 acc2[8][4];
#pragma unroll
    for (int i = 0; i < 8; i++)
#pragma unroll
        for (int j = 0; j < 4; j++) acc2[i][j] = 0ull;

    for (int k0 = 0; k0 < CI; k0 += 32) {
        __syncthreads();
#pragma unroll
        for (int p = 0; p < 4; p++) {
            int idx = p * 256 + tid;
            int n = idx >> 3, c4 = idx & 7;
            float4 v = *(const float4*)&d_y[((size_t)b * NN + n0 + n) * CI + k0 + c4 * 4];
            ys[(c4 * 4 + 0) * 132 + n] = v.x;
            ys[(c4 * 4 + 1) * 132 + n] = v.y;
            ys[(c4 * 4 + 2) * 132 + n] = v.z;
            ys[(c4 * 4 + 3) * 132 + n] = v.w;
            int ci = idx >> 5, g4 = idx & 31;
            *(float4*)&wsm[ci * 132 + g4 * 4] =
                *(const float4*)&d_wT[(size_t)(k0 + ci) * CC + c0 + g4 * 4];
        }
        __syncthreads();
#pragma unroll
        for (int cc = 0; cc < 32; cc++) {
            float4 wlo = *(const float4*)&wsm[cc * 132 + ty * 4];
            float4 whi = *(const float4*)&wsm[cc * 132 + 64 + ty * 4];
            float4 ylo = *(const float4*)&ys[cc * 132 + tx * 4];
            float4 yhi = *(const float4*)&ys[cc * 132 + 64 + tx * 4];
            u64 yp[4] = {pk2(ylo.x, ylo.y), pk2(ylo.z, ylo.w),
                         pk2(yhi.x, yhi.y), pk2(yhi.z, yhi.w)};
            const float wv[8] = {wlo.x, wlo.y, wlo.z, wlo.w,
                                 whi.x, whi.y, whi.z, whi.w};
#pragma unroll
            for (int i = 0; i < 8; i++) {
                u64 wd = dup2(wv[i]);
#pragma unroll
                for (int j = 0; j < 4; j++) fma2(acc2[i][j], wd, yp[j]);
            }
        }
    }

#pragma unroll
    for (int i = 0; i < 8; i++) {
        int c = c0 + ((i < 4) ? (ty * 4 + i) : (64 + ty * 4 + i - 4));
        float inv = gamma[c] * rsqrtf(var[c] + 1e-5f);
        float be  = (W_b[c] - mean[c]) * inv + beta[c];
        float a[8];
        up2(a[0], a[1], acc2[i][0]); up2(a[2], a[3], acc2[i][1]);
        up2(a[4], a[5], acc2[i][2]); up2(a[6], a[7], acc2[i][3]);
        const float* fr = &fuse[((size_t)b * CC + c) * NN + n0];
        float* orow = &out[((size_t)b * 768 + 256 + c) * NN + n0];
        float4 f0 = *(const float4*)&fr[tx * 4];
        float4 f1 = *(const float4*)&fr[64 + tx * 4];
        *(float4*)&orow[tx * 4] = make_float4(a[0]*inv + be + f0.x, a[1]*inv + be + f0.y,
                                              a[2]*inv + be + f0.z, a[3]*inv + be + f0.w);
        *(float4*)&orow[64 + tx * 4] = make_float4(a[4]*inv + be + f1.x, a[5]*inv + be + f1.y,
                                                   a[6]*inv + be + f1.z, a[7]*inv + be + f1.w);
    }
}

// =====================================================================
extern "C" void kernel_launch(void* const* d_in, const int* in_sizes, int n_in,
                              void* d_out, int out_size)
{
    const float* lc      = (const float*)d_in[0];
    const float* fuse    = (const float*)d_in[1];
    const float* gc      = (const float*)d_in[2];
    const float* g_w     = (const float*)d_in[3];
    const float* g_b     = (const float*)d_in[4];
    const float* theta_w = (const float*)d_in[5];
    const float* theta_b = (const float*)d_in[6];
    const float* phi_w   = (const float*)d_in[7];
    const float* phi_b   = (const float*)d_in[8];
    const float* W_w     = (const float*)d_in[9];
    const float* W_b     = (const float*)d_in[10];
    const float* bn_g    = (const float*)d_in[11];
    const float* bn_b    = (const float*)d_in[12];
    const float* bn_m    = (const float*)d_in[13];
    const float* bn_v    = (const float*)d_in[14];
    float* out = (float*)d_out;

    (void)in_sizes; (void)n_in; (void)out_size;

    cudaFuncSetAttribute(attn_kernel, cudaFuncAttributeMaxDynamicSharedMemorySize,
                         ATTN_SMEM_BYTES);
    cudaFuncSetAttribute(proj_mma_kernel, cudaFuncAttributeMaxDynamicSharedMemorySize,
                         PROJ_SMEM_BYTES);

    wt_kernel<<<32, 256>>>(W_w);
    wsplit_kernel<<<96, 256>>>(theta_w, phi_w, g_w);
    splitx_kernel<<<dim3(32, 4, BB), 256>>>(fuse);

    proj_mma_kernel<<<dim3(32, BB, 3), 256, PROJ_SMEM_BYTES>>>(
        g_b, theta_b, phi_b,
        (const float4*)lc, (const float4*)gc, (float4*)out);

    attn_kernel<<<dim3(NN / 128, BB), 256, ATTN_SMEM_BYTES>>>();

    wz_kernel<<<dim3(NN / 128, CC / 128, BB), 256>>>(
        fuse, W_b, bn_g, bn_b, bn_m, bn_v, out);
}

// round 14
// speedup vs baseline: 2.8305x; 1.0851x over previous
#include <cuda_runtime.h>
#include <cuda_bf16.h>
#include <math.h>
#include <cstdint>

#define BB 8
#define CC 256
#define CI 128
#define HH 64
#define WWID 64
#define NN 4096
#define NK 1024

typedef unsigned long long u64;

// ---------------- packed fp32x2 helpers (FFMA2) ----------------
__device__ __forceinline__ u64 pk2(float lo, float hi) {
    u64 r; asm("mov.b64 %0, {%1, %2};" : "=l"(r) : "f"(lo), "f"(hi)); return r;
}
__device__ __forceinline__ u64 dup2(float v) { return pk2(v, v); }
__device__ __forceinline__ void up2(float& lo, float& hi, u64 v) {
    asm("mov.b64 {%0, %1}, %2;" : "=f"(lo), "=f"(hi) : "l"(v));
}
__device__ __forceinline__ void fma2(u64& d, u64 a, u64 b) {
    asm("fma.rn.f32x2 %0, %1, %2, %0;" : "+l"(d) : "l"(a), "l"(b));
}

// ---------------- warp-MMA / async-copy helpers (sm_80-era PTX) ----------------
__device__ __forceinline__ uint32_t smem_u32(const void* p) {
    uint32_t a;
    asm("{ .reg .u64 t; cvta.to.shared.u64 t, %1; cvt.u32.u64 %0, t; }" : "=r"(a) : "l"(p));
    return a;
}
#define CVT_BF16X2(res, a, b) \
    asm("cvt.rn.satfinite.bf16x2.f32 %0, %1, %2;" : "=r"(res) : "f"(b), "f"(a))

__device__ __forceinline__ void ldsm_x4(uint32_t& a0, uint32_t& a1, uint32_t& a2,
                                        uint32_t& a3, uint32_t addr) {
    asm volatile("ldmatrix.sync.aligned.m8n8.x4.shared.b16 {%0,%1,%2,%3}, [%4];"
                 : "=r"(a0), "=r"(a1), "=r"(a2), "=r"(a3) : "r"(addr));
}
__device__ __forceinline__ void mma_bf16(float* c, uint32_t a0, uint32_t a1,
                                         uint32_t a2, uint32_t a3,
                                         uint32_t b0, uint32_t b1) {
    asm volatile("mma.sync.aligned.m16n8k16.row.col.f32.bf16.bf16.f32 "
                 "{%0,%1,%2,%3}, {%4,%5,%6,%7}, {%8,%9}, {%0,%1,%2,%3};"
                 : "+f"(c[0]), "+f"(c[1]), "+f"(c[2]), "+f"(c[3])
                 : "r"(a0), "r"(a1), "r"(a2), "r"(a3), "r"(b0), "r"(b1));
}
__device__ __forceinline__ void cp_async16(uint32_t s, const void* g) {
    asm volatile("cp.async.ca.shared.global [%0], [%1], 16;" :: "r"(s), "l"(g));
}
#define CP_COMMIT() asm volatile("cp.async.commit_group;" ::: "memory")
#define CP_WAIT(n)  asm volatile("cp.async.wait_group %0;" :: "n"(n) : "memory")

// split helpers (fp32 -> bf16 hi + bf16 residue lo)
__device__ __forceinline__ void split4(const float* v, uint2& h, uint2& l) {
    float h0 = __bfloat162float(__float2bfloat16(v[0]));
    float h1 = __bfloat162float(__float2bfloat16(v[1]));
    float h2 = __bfloat162float(__float2bfloat16(v[2]));
    float h3 = __bfloat162float(__float2bfloat16(v[3]));
    CVT_BF16X2(h.x, v[0], v[1]);
    CVT_BF16X2(h.y, v[2], v[3]);
    CVT_BF16X2(l.x, v[0] - h0, v[1] - h1);
    CVT_BF16X2(l.y, v[2] - h2, v[3] - h3);
}
__device__ __forceinline__ void split2(float a, float b, uint32_t& h, uint32_t& l) {
    float ha = __bfloat162float(__float2bfloat16(a));
    float hb = __bfloat162float(__float2bfloat16(b));
    CVT_BF16X2(h, a, b);
    CVT_BF16X2(l, a - ha, b - hb);
}
__device__ __forceinline__ float qmax(float v) {
    v = fmaxf(v, __shfl_xor_sync(0xffffffffu, v, 4));
    v = fmaxf(v, __shfl_xor_sync(0xffffffffu, v, 8));
    return v;
}

// ---------------- scratch (device globals) ----------------
__device__ __align__(16) float d_y[BB * NN * CI];             // [B][N][CI]
__device__ __align__(16) float d_wT[CI * CC];
__device__ __align__(16) __nv_bfloat16 d_thh[BB * NN * CI];   // theta [B][N][CI]
__device__ __align__(16) __nv_bfloat16 d_thl[BB * NN * CI];
__device__ __align__(16) __nv_bfloat16 d_phh[BB * NK * CI];   // phi   [B][Nk][CI]
__device__ __align__(16) __nv_bfloat16 d_phl[BB * NK * CI];
__device__ __align__(16) __nv_bfloat16 d_gh[BB * CI * NK];    // g     [B][CI][Nk]
__device__ __align__(16) __nv_bfloat16 d_gl[BB * CI * NK];
__device__ __align__(16) __nv_bfloat16 d_xh[BB * NN * CC];    // xT    [B][n_perm][C]
__device__ __align__(16) __nv_bfloat16 d_xl[BB * NN * CC];
__device__ __align__(16) __nv_bfloat16 d_wsh[3 * CI * CC];    // w     [z][CI][C]
__device__ __align__(16) __nv_bfloat16 d_wsl[3 * CI * CC];

// =====================================================================
// Kernel 0a: transpose W_w -> d_wT (for wz)
// =====================================================================
__global__ void wt_kernel(const float* __restrict__ Ww)
{
    int idx = blockIdx.x * 256 + threadIdx.x;
    if (idx < CC * (CI / 4)) {
        int c  = idx >> 5;
        int g4 = idx & 31;
        float4 v = ((const float4*)Ww)[idx];
        int ci = g4 * 4;
        d_wT[(ci + 0) * CC + c] = v.x;
        d_wT[(ci + 1) * CC + c] = v.y;
        d_wT[(ci + 2) * CC + c] = v.z;
        d_wT[(ci + 3) * CC + c] = v.w;
    }
}

// =====================================================================
// Kernel 0b: split projection weights -> bf16 hi/lo.  z: 0=theta,1=phi,2=g
// =====================================================================
__global__ void wsplit_kernel(const float* __restrict__ th_w,
                              const float* __restrict__ ph_w,
                              const float* __restrict__ g_w)
{
    const int PER = CI * CC / 4;   // 8192 float4 per matrix
    int idx = blockIdx.x * 256 + threadIdx.x;
    if (idx >= 3 * PER) return;
    int z = idx / PER, off = idx - z * PER;
    const float* src = (z == 0) ? th_w : (z == 1) ? ph_w : g_w;
    float v[4];
    *(float4*)v = ((const float4*)src)[off];
    uint2 h, l;
    split4(v, h, l);
    ((uint2*)(d_wsh + (size_t)z * CI * CC))[off] = h;
    ((uint2*)(d_wsl + (size_t)z * CI * CC))[off] = l;
}

// =====================================================================
// Kernel 0c: split_x — fuse [B][C][N] -> xT bf16 hi/lo [B][n_perm][C].
// grid (32 rowpairs, 4 c-chunks, B), block 256.
// =====================================================================
__global__ __launch_bounds__(256, 2)
void splitx_kernel(const float* __restrict__ x)
{
    __shared__ float tile[64 * 132];   // [c][perm]
    const int r  = blockIdx.x;
    const int c0 = blockIdx.y * 64;
    const int b  = blockIdx.z;
    const int tid = threadIdx.x;

    const float* xb = x + ((size_t)b * CC + c0) * NN + (2 * r) * WWID;
#pragma unroll
    for (int it = 0; it < 8; it++) {
        int id = it * 256 + tid;
        int c = id >> 5, n4 = id & 31;
        float4 v = *(const float4*)&xb[(size_t)c * NN + ((n4 * 4) >> 6) * WWID + ((n4 * 4) & 63)];
        int row = (n4 * 4) >> 6;
#pragma unroll
        for (int e = 0; e < 4; e++) {
            int wcol = (n4 * 4 + e) & 63;
            int perm = ((wcol >> 1) << 2) | (row << 1) | (wcol & 1);
            tile[c * 132 + perm] = ((const float*)&v)[e];
        }
    }
    __syncthreads();

    __nv_bfloat16* oh = d_xh + ((size_t)b * NN + r * 128) * CC + c0;
    __nv_bfloat16* ol = d_xl + ((size_t)b * NN + r * 128) * CC + c0;
#pragma unroll
    for (int it = 0; it < 8; it++) {
        int id = it * 256 + tid;
        int p = id >> 4, cq = (id & 15) * 4;
        float v[4];
        v[0] = tile[(cq + 0) * 132 + p];
        v[1] = tile[(cq + 1) * 132 + p];
        v[2] = tile[(cq + 2) * 132 + p];
        v[3] = tile[(cq + 3) * 132 + p];
        uint2 h, l;
        split4(v, h, l);
        *(uint2*)(oh + (size_t)p * CC + cq) = h;
        *(uint2*)(ol + (size_t)p * CC + cq) = l;
    }
}

// =====================================================================
// Kernel 0d: dedicated lc/gc band copy (float4 grid-stride, high MLP).
// =====================================================================
__global__ void copy_kernel(const float4* __restrict__ lc,
                            const float4* __restrict__ gc,
                            float4* __restrict__ out)
{
    const size_t PER_B = 262144;   // float4 per (batch, 256ch, 4096px)
    const size_t TOT   = BB * PER_B;
    const size_t OUT_B = 786432;
    const size_t stride = (size_t)gridDim.x * blockDim.x;
    for (size_t i = (size_t)blockIdx.x * blockDim.x + threadIdx.x;
         i < TOT; i += stride) {
        size_t bidx = i / PER_B, rem = i % PER_B;
        out[bidx * OUT_B + rem]             = lc[i];
        out[bidx * OUT_B + 2 * PER_B + rem] = gc[i];
    }
}

// =====================================================================
// Kernel 1: tensor-core projections (copy un-folded).
// grid (32 rowpairs, B, 3 proj), block 256 (8 warps x 16 px rows).
// =====================================================================
#define PJ_AH 0
#define PJ_AL 18432
#define PJ_BH 36864
#define PJ_BL 55296
#define PJ_BUF 73728
#define PROJ_SMEM_BYTES (2 * PJ_BUF)

__device__ __forceinline__ void pj_prefetch(uint32_t bufb,
                                            const __nv_bfloat16* xh,
                                            const __nv_bfloat16* xl,
                                            const __nv_bfloat16* wh,
                                            const __nv_bfloat16* wl,
                                            int k0, int tid)
{
#pragma unroll
    for (int it = 0; it < 4; it++) {
        int idx = it * 256 + tid;              // 0..1023
        int row = idx >> 3, c8 = (idx & 7) * 8;
        uint32_t so = row * 144 + c8 * 2;
        cp_async16(bufb + PJ_AH + so, xh + (size_t)row * CC + k0 + c8);
        cp_async16(bufb + PJ_AL + so, xl + (size_t)row * CC + k0 + c8);
        cp_async16(bufb + PJ_BH + so, wh + (size_t)row * CC + k0 + c8);
        cp_async16(bufb + PJ_BL + so, wl + (size_t)row * CC + k0 + c8);
    }
}

__global__ __launch_bounds__(256, 1)
void proj_mma_kernel(const float* __restrict__ g_b,
                     const float* __restrict__ th_b,
                     const float* __restrict__ ph_b)
{
    extern __shared__ char smc[];
    const uint32_t sb = smem_u32(smc);
    const int r    = blockIdx.x;
    const int b    = blockIdx.y;
    const int z    = blockIdx.z;   // 0 theta, 1 phi, 2 g
    const int tid  = threadIdx.x;
    const int wid  = tid >> 5;
    const int lane = tid & 31;

    const __nv_bfloat16* xh = d_xh + ((size_t)b * NN + r * 128) * CC;
    const __nv_bfloat16* xl = d_xl + ((size_t)b * NN + r * 128) * CC;
    const __nv_bfloat16* wh = d_wsh + (size_t)z * CI * CC;
    const __nv_bfloat16* wl = d_wsl + (size_t)z * CI * CC;
    const float* bias = (z == 0) ? th_b : (z == 1) ? ph_b : g_b;

    pj_prefetch(sb, xh, xl, wh, wl, 0, tid);
    CP_COMMIT();

    const int a_row = (lane & 7) + 8 * ((lane >> 3) & 1);
    const int a_col = 8 * (lane >> 4);
    const int b4_row = 8 * (lane >> 4) + (lane & 7);
    const int b4_col = 8 * ((lane >> 3) & 1);
    const int Rbase = wid * 16;

    float cacc[16][4];
#pragma unroll
    for (int nt = 0; nt < 16; nt++)
#pragma unroll
        for (int j = 0; j < 4; j++) cacc[nt][j] = 0.f;

#pragma unroll 1
    for (int ic = 0; ic < 4; ic++) {
        const uint32_t buf = sb + (uint32_t)(ic & 1) * PJ_BUF;
        if (ic < 3) {
            pj_prefetch(sb + (uint32_t)((ic + 1) & 1) * PJ_BUF, xh, xl, wh, wl,
                        (ic + 1) * 64, tid);
            CP_COMMIT();
            CP_WAIT(1);
        } else {
            CP_WAIT(0);
        }
        __syncthreads();

#pragma unroll
        for (int ks = 0; ks < 4; ks++) {
            int cb = ks * 16;
            uint32_t ah0, ah1, ah2, ah3, al0, al1, al2, al3;
            uint32_t aaddr = (Rbase + a_row) * 144 + (cb + a_col) * 2;
            ldsm_x4(ah0, ah1, ah2, ah3, buf + PJ_AH + aaddr);
            ldsm_x4(al0, al1, al2, al3, buf + PJ_AL + aaddr);
#pragma unroll
            for (int n2 = 0; n2 < 8; n2++) {
                uint32_t bh0, bh1, bh2, bh3, bl0, bl1, bl2, bl3;
                uint32_t baddr = (n2 * 16 + b4_row) * 144 + (cb + b4_col) * 2;
                ldsm_x4(bh0, bh1, bh2, bh3, buf + PJ_BH + baddr);
                ldsm_x4(bl0, bl1, bl2, bl3, buf + PJ_BL + baddr);
                mma_bf16(cacc[2*n2],   ah0, ah1, ah2, ah3, bh0, bh1);
                mma_bf16(cacc[2*n2],   ah0, ah1, ah2, ah3, bl0, bl1);
                mma_bf16(cacc[2*n2],   al0, al1, al2, al3, bh0, bh1);
                mma_bf16(cacc[2*n2+1], ah0, ah1, ah2, ah3, bh2, bh3);
                mma_bf16(cacc[2*n2+1], ah0, ah1, ah2, ah3, bl2, bl3);
                mma_bf16(cacc[2*n2+1], al0, al1, al2, al3, bh2, bh3);
            }
        }
        __syncthreads();
    }

    // ---- epilogue ----
    if (z == 0) {
        int p0 = Rbase + (lane >> 2);
        int p1 = p0 + 8;
        int g0 = p0 >> 2, s0 = p0 & 3;
        int g1 = p1 >> 2, s1 = p1 & 3;
        int n0 = (2 * r + (s0 >> 1)) * WWID + ((g0 << 1) | (s0 & 1));
        int n1 = (2 * r + (s1 >> 1)) * WWID + ((g1 << 1) | (s1 & 1));
        size_t b0 = ((size_t)(b * NN + n0)) * CI;
        size_t b1 = ((size_t)(b * NN + n1)) * CI;
#pragma unroll
        for (int nt = 0; nt < 16; nt++) {
            int ci = nt * 8 + 2 * (lane & 3);
            float bi0 = bias[ci], bi1 = bias[ci + 1];
            uint32_t h, l;
            split2(cacc[nt][0] + bi0, cacc[nt][1] + bi1, h, l);
            *(uint32_t*)(d_thh + b0 + ci) = h;
            *(uint32_t*)(d_thl + b0 + ci) = l;
            split2(cacc[nt][2] + bi0, cacc[nt][3] + bi1, h, l);
            *(uint32_t*)(d_thh + b1 + ci) = h;
            *(uint32_t*)(d_thl + b1 + ci) = l;
        }
    } else {
        int k01 = r * 32 + wid * 4 + (lane >> 4);
        int k23 = k01 + 2;
        bool writer = ((lane >> 2) & 3) == 0;
#pragma unroll
        for (int nt = 0; nt < 16; nt++) {
            int ci = nt * 8 + 2 * (lane & 3);
            float m01a = qmax(cacc[nt][0]);
            float m01b = qmax(cacc[nt][1]);
            float m23a = qmax(cacc[nt][2]);
            float m23b = qmax(cacc[nt][3]);
            if (writer) {
                float bi0 = bias[ci], bi1 = bias[ci + 1];
                float v01a = m01a + bi0, v01b = m01b + bi1;
                float v23a = m23a + bi0, v23b = m23b + bi1;
                if (z == 1) {
                    uint32_t h, l;
                    split2(v01a, v01b, h, l);
                    *(uint32_t*)(d_phh + ((size_t)(b * NK + k01)) * CI + ci) = h;
                    *(uint32_t*)(d_phl + ((size_t)(b * NK + k01)) * CI + ci) = l;
                    split2(v23a, v23b, h, l);
                    *(uint32_t*)(d_phh + ((size_t)(b * NK + k23)) * CI + ci) = h;
                    *(uint32_t*)(d_phl + ((size_t)(b * NK + k23)) * CI + ci) = l;
                } else {
                    size_t gb = (size_t)b * CI * NK;
                    float h01a = __bfloat162float(__float2bfloat16(v01a));
                    float h01b = __bfloat162float(__float2bfloat16(v01b));
                    float h23a = __bfloat162float(__float2bfloat16(v23a));
                    float h23b = __bfloat162float(__float2bfloat16(v23b));
                    d_gh[gb + (size_t)ci * NK + k01]       = __float2bfloat16(v01a);
                    d_gh[gb + (size_t)(ci + 1) * NK + k01] = __float2bfloat16(v01b);
                    d_gh[gb + (size_t)ci * NK + k23]       = __float2bfloat16(v23a);
                    d_gh[gb + (size_t)(ci + 1) * NK + k23] = __float2bfloat16(v23b);
                    d_gl[gb + (size_t)ci * NK + k01]       = __float2bfloat16(v01a - h01a);
                    d_gl[gb + (size_t)(ci + 1) * NK + k01] = __float2bfloat16(v01b - h01b);
                    d_gl[gb + (size_t)ci * NK + k23]       = __float2bfloat16(v23a - h23a);
                    d_gl[gb + (size_t)(ci + 1) * NK + k23] = __float2bfloat16(v23b - h23b);
                }
            }
        }
    }
}

// =====================================================================
// Kernel 2: warp-MMA bf16 split flash attention (unchanged, passing).
// =====================================================================
#define SM_QH 0
#define SM_QL 34816
#define SM_BUF 69632
#define BUF_SZ 71680
#define BUF_KH 0
#define BUF_KL 17408
#define BUF_GH 34816
#define BUF_GL 53248
#define ATTN_SMEM_BYTES (SM_BUF + 2 * BUF_SZ)   // 212,992

__device__ __forceinline__ void prefetch_chunk(uint32_t bufb, int b, int c0, int tid)
{
    const __nv_bfloat16* kh = d_phh + (size_t)(b * NK + c0) * CI;
    const __nv_bfloat16* kl = d_phl + (size_t)(b * NK + c0) * CI;
    const __nv_bfloat16* gh = d_gh + (size_t)b * CI * NK + c0;
    const __nv_bfloat16* gl = d_gl + (size_t)b * CI * NK + c0;
#pragma unroll
    for (int it = 0; it < 4; it++) {
        int idx = it * 256 + tid;
        int krow = idx >> 4, c8 = (idx & 15) * 8;
        cp_async16(bufb + BUF_KH + krow * 272 + c8 * 2, kh + (size_t)krow * CI + c8);
        cp_async16(bufb + BUF_KL + krow * 272 + c8 * 2, kl + (size_t)krow * CI + c8);
        int drow = idx >> 3, k8 = (idx & 7) * 8;
        cp_async16(bufb + BUF_GH + drow * 144 + k8 * 2, gh + (size_t)drow * NK + k8);
        cp_async16(bufb + BUF_GL + drow * 144 + k8 * 2, gl + (size_t)drow * NK + k8);
    }
}

__global__ __launch_bounds__(256, 1)
void attn_kernel()
{
    extern __shared__ char smc[];
    const uint32_t sb = smem_u32(smc);
    const int tid  = threadIdx.x;
    const int wid  = tid >> 5;
    const int lane = tid & 31;
    const int b    = blockIdx.y;
    const int q0   = blockIdx.x * 128;

    prefetch_chunk(sb + SM_BUF, b, 0, tid);
    CP_COMMIT();

    {
        const __nv_bfloat16* qh = d_thh + (size_t)(b * NN + q0) * CI;
        const __nv_bfloat16* ql = d_thl + (size_t)(b * NN + q0) * CI;
#pragma unroll
        for (int it = 0; it < 8; it++) {
            int idx = it * 256 + tid;
            int row = idx >> 4, c8 = (idx & 15) * 8;
            *(uint4*)(smc + SM_QH + row * 272 + c8 * 2) =
                *(const uint4*)(qh + (size_t)row * CI + c8);
            *(uint4*)(smc + SM_QL + row * 272 + c8 * 2) =
                *(const uint4*)(ql + (size_t)row * CI + c8);
        }
    }

    const int a_row = (lane & 7) + 8 * ((lane >> 3) & 1);
    const int a_col = 8 * (lane >> 4);
    const int b4_row = 8 * (lane >> 4) + (lane & 7);
    const int b4_col = 8 * ((lane >> 3) & 1);
    const int Rbase = wid * 16;

    float yacc[16][4];
#pragma unroll
    for (int dt = 0; dt < 16; dt++)
#pragma unroll
        for (int j = 0; j < 4; j++) yacc[dt][j] = 0.f;
    float m0 = -1e30f, m1 = -1e30f, l0 = 0.f, l1 = 0.f;

#pragma unroll 1
    for (int ic = 0; ic < 16; ic++) {
        const uint32_t cb_buf = sb + SM_BUF + (uint32_t)(ic & 1) * BUF_SZ;

        if (ic < 15) {
            prefetch_chunk(sb + SM_BUF + (uint32_t)((ic + 1) & 1) * BUF_SZ,
                           b, (ic + 1) * 64, tid);
            CP_COMMIT();
            CP_WAIT(1);
        } else {
            CP_WAIT(0);
        }
        __syncthreads();

        float sacc[8][4];
#pragma unroll
        for (int n = 0; n < 8; n++)
#pragma unroll
            for (int j = 0; j < 4; j++) sacc[n][j] = 0.f;

#pragma unroll
        for (int m = 0; m < 8; m++) {
            int cb = m * 16;
            uint32_t ah0, ah1, ah2, ah3, al0, al1, al2, al3;
            ldsm_x4(ah0, ah1, ah2, ah3,
                    sb + SM_QH + (Rbase + a_row) * 272 + (cb + a_col) * 2);
            ldsm_x4(al0, al1, al2, al3,
                    sb + SM_QL + (Rbase + a_row) * 272 + (cb + a_col) * 2);
#pragma unroll
            for (int n2 = 0; n2 < 4; n2++) {
                uint32_t kh0, kh1, kh2, kh3, kl0, kl1, kl2, kl3;
                uint32_t kaddr = (n2 * 16 + b4_row) * 272 + (cb + b4_col) * 2;
                ldsm_x4(kh0, kh1, kh2, kh3, cb_buf + BUF_KH + kaddr);
                ldsm_x4(kl0, kl1, kl2, kl3, cb_buf + BUF_KL + kaddr);
                mma_bf16(sacc[2*n2],   ah0, ah1, ah2, ah3, kh0, kh1);
                mma_bf16(sacc[2*n2],   ah0, ah1, ah2, ah3, kl0, kl1);
                mma_bf16(sacc[2*n2],   al0, al1, al2, al3, kh0, kh1);
                mma_bf16(sacc[2*n2+1], ah0, ah1, ah2, ah3, kh2, kh3);
                mma_bf16(sacc[2*n2+1], ah0, ah1, ah2, ah3, kl2, kl3);
                mma_bf16(sacc[2*n2+1], al0, al1, al2, al3, kh2, kh3);
            }
        }

        float mc0 = -1e30f, mc1 = -1e30f;
#pragma unroll
        for (int n = 0; n < 8; n++) {
            mc0 = fmaxf(mc0, fmaxf(sacc[n][0], sacc[n][1]));
            mc1 = fmaxf(mc1, fmaxf(sacc[n][2], sacc[n][3]));
        }
        mc0 = fmaxf(mc0, __shfl_xor_sync(0xffffffffu, mc0, 1));
        mc0 = fmaxf(mc0, __shfl_xor_sync(0xffffffffu, mc0, 2));
        mc1 = fmaxf(mc1, __shfl_xor_sync(0xffffffffu, mc1, 1));
        mc1 = fmaxf(mc1, __shfl_xor_sync(0xffffffffu, mc1, 2));
        float mn0 = fmaxf(m0, mc0), mn1 = fmaxf(m1, mc1);
        float sc0 = __expf(m0 - mn0), sc1 = __expf(m1 - mn1);
        m0 = mn0; m1 = mn1;
        l0 *= sc0; l1 *= sc1;
#pragma unroll
        for (int dt = 0; dt < 16; dt++) {
            yacc[dt][0] *= sc0; yacc[dt][1] *= sc0;
            yacc[dt][2] *= sc1; yacc[dt][3] *= sc1;
        }

        uint32_t pa_h[4][4], pa_l[4][4];
#pragma unroll
        for (int n = 0; n < 8; n++) {
            float p0 = __expf(sacc[n][0] - mn0);
            float p1 = __expf(sacc[n][1] - mn0);
            float p2 = __expf(sacc[n][2] - mn1);
            float p3 = __expf(sacc[n][3] - mn1);
            l0 += p0 + p1;
            l1 += p2 + p3;
            float h0 = __bfloat162float(__float2bfloat16(p0));
            float h1 = __bfloat162float(__float2bfloat16(p1));
            float h2 = __bfloat162float(__float2bfloat16(p2));
            float h3 = __bfloat162float(__float2bfloat16(p3));
            uint32_t h01, h23, lo01, lo23;
            CVT_BF16X2(h01, p0, p1);
            CVT_BF16X2(h23, p2, p3);
            CVT_BF16X2(lo01, p0 - h0, p1 - h1);
            CVT_BF16X2(lo23, p2 - h2, p3 - h3);
            int m2 = n >> 1;
            if ((n & 1) == 0) {
                pa_h[m2][0] = h01;  pa_h[m2][1] = h23;
                pa_l[m2][0] = lo01; pa_l[m2][1] = lo23;
            } else {
                pa_h[m2][2] = h01;  pa_h[m2][3] = h23;
                pa_l[m2][2] = lo01; pa_l[m2][3] = lo23;
            }
        }

#pragma unroll
        for (int m2 = 0; m2 < 4; m2++) {
            int kb = m2 * 16;
#pragma unroll
            for (int dt2 = 0; dt2 < 8; dt2++) {
                uint32_t gh0, gh1, gh2, gh3, gl0, gl1, gl2, gl3;
                uint32_t gaddr = (dt2 * 16 + b4_row) * 144 + (kb + b4_col) * 2;
                ldsm_x4(gh0, gh1, gh2, gh3, cb_buf + BUF_GH + gaddr);
                ldsm_x4(gl0, gl1, gl2, gl3, cb_buf + BUF_GL + gaddr);
                mma_bf16(yacc[2*dt2],   pa_h[m2][0], pa_h[m2][1], pa_h[m2][2], pa_h[m2][3], gh0, gh1);
                mma_bf16(yacc[2*dt2],   pa_l[m2][0], pa_l[m2][1], pa_l[m2][2], pa_l[m2][3], gh0, gh1);
                mma_bf16(yacc[2*dt2],   pa_h[m2][0], pa_h[m2][1], pa_h[m2][2], pa_h[m2][3], gl0, gl1);
                mma_bf16(yacc[2*dt2+1], pa_h[m2][0], pa_h[m2][1], pa_h[m2][2], pa_h[m2][3], gh2, gh3);
                mma_bf16(yacc[2*dt2+1], pa_l[m2][0], pa_l[m2][1], pa_l[m2][2], pa_l[m2][3], gh2, gh3);
                mma_bf16(yacc[2*dt2+1], pa_h[m2][0], pa_h[m2][1], pa_h[m2][2], pa_h[m2][3], gl2, gl3);
            }
        }
        __syncthreads();
    }

    l0 += __shfl_xor_sync(0xffffffffu, l0, 1);
    l0 += __shfl_xor_sync(0xffffffffu, l0, 2);
    l1 += __shfl_xor_sync(0xffffffffu, l1, 1);
    l1 += __shfl_xor_sync(0xffffffffu, l1, 2);
    float inv0 = 1.f / l0, inv1 = 1.f / l1;

    int r0 = lane >> 2;
    int cofs = (lane & 3) * 2;
    float* dst0 = d_y + ((size_t)(b * NN + q0 + Rbase + r0)) * CI;
    float* dst1 = d_y + ((size_t)(b * NN + q0 + Rbase + r0 + 8)) * CI;
#pragma unroll
    for (int dt = 0; dt < 16; dt++) {
        *(float2*)&dst0[dt * 8 + cofs] = make_float2(yacc[dt][0] * inv0, yacc[dt][1] * inv0);
        *(float2*)&dst1[dt * 8 + cofs] = make_float2(yacc[dt][2] * inv1, yacc[dt][3] * inv1);
    }
}

// =====================================================================
// Kernel 3: z = BN(conv1x1(y, W)) + fuse -> concat band 1 (unchanged).
// =====================================================================
__global__ __launch_bounds__(256, 2)
void wz_kernel(const float* __restrict__ fuse,
               const float* __restrict__ W_b,
               const float* __restrict__ gamma, const float* __restrict__ beta,
               const float* __restrict__ mean,  const float* __restrict__ var,
               float* __restrict__ out)
{
    __shared__ __align__(16) float ys[32 * 132];
    __shared__ __align__(16) float wsm[32 * 132];

    const int b  = blockIdx.z;
    const int c0 = blockIdx.y * 128;
    const int n0 = blockIdx.x * 128;
    const int tid = threadIdx.x;
    const int ty = tid >> 4;
    const int tx = tid & 15;

    u64 acc2[8][4];
#pragma unroll
    for (int i = 0; i < 8; i++)
#pragma unroll
        for (int j = 0; j < 4; j++) acc2[i][j] = 0ull;

    for (int k0 = 0; k0 < CI; k0 += 32) {
        __syncthreads();
#pragma unroll
        for (int p = 0; p < 4; p++) {
            int idx = p * 256 + tid;
            int n = idx >> 3, c4 = idx & 7;
            float4 v = *(const float4*)&d_y[((size_t)b * NN + n0 + n) * CI + k0 + c4 * 4];
            ys[(c4 * 4 + 0) * 132 + n] = v.x;
            ys[(c4 * 4 + 1) * 132 + n] = v.y;
            ys[(c4 * 4 + 2) * 132 + n] = v.z;
            ys[(c4 * 4 + 3) * 132 + n] = v.w;
            int ci = idx >> 5, g4 = idx & 31;
            *(float4*)&wsm[ci * 132 + g4 * 4] =
                *(const float4*)&d_wT[(size_t)(k0 + ci) * CC + c0 + g4 * 4];
        }
        __syncthreads();
#pragma unroll
        for (int cc = 0; cc < 32; cc++) {
            float4 wlo = *(const float4*)&wsm[cc * 132 + ty * 4];
            float4 whi = *(const float4*)&wsm[cc * 132 + 64 + ty * 4];
            float4 ylo = *(const float4*)&ys[cc * 132 + tx * 4];
            float4 yhi = *(const float4*)&ys[cc * 132 + 64 + tx * 4];
            u64 yp[4] = {pk2(ylo.x, ylo.y), pk2(ylo.z, ylo.w),
                         pk2(yhi.x, yhi.y), pk2(yhi.z, yhi.w)};
            const float wv[8] = {wlo.x, wlo.y, wlo.z, wlo.w,
                                 whi.x, whi.y, whi.z, whi.w};
#pragma unroll
            for (int i = 0; i < 8; i++) {
                u64 wd = dup2(wv[i]);
#pragma unroll
                for (int j = 0; j < 4; j++) fma2(acc2[i][j], wd, yp[j]);
            }
        }
    }

#pragma unroll
    for (int i = 0; i < 8; i++) {
        int c = c0 + ((i < 4) ? (ty * 4 + i) : (64 + ty * 4 + i - 4));
        float inv = gamma[c] * rsqrtf(var[c] + 1e-5f);
        float be  = (W_b[c] - mean[c]) * inv + beta[c];
        float a[8];
        up2(a[0], a[1], acc2[i][0]); up2(a[2], a[3], acc2[i][1]);
        up2(a[4], a[5], acc2[i][2]); up2(a[6], a[7], acc2[i][3]);
        const float* fr = &fuse[((size_t)b * CC + c) * NN + n0];
        float* orow = &out[((size_t)b * 768 + 256 + c) * NN + n0];
        float4 f0 = *(const float4*)&fr[tx * 4];
        float4 f1 = *(const float4*)&fr[64 + tx * 4];
        *(float4*)&orow[tx * 4] = make_float4(a[0]*inv + be + f0.x, a[1]*inv + be + f0.y,
                                              a[2]*inv + be + f0.z, a[3]*inv + be + f0.w);
        *(float4*)&orow[64 + tx * 4] = make_float4(a[4]*inv + be + f1.x, a[5]*inv + be + f1.y,
                                                   a[6]*inv + be + f1.z, a[7]*inv + be + f1.w);
    }
}

// =====================================================================
extern "C" void kernel_launch(void* const* d_in, const int* in_sizes, int n_in,
                              void* d_out, int out_size)
{
    const float* lc      = (const float*)d_in[0];
    const float* fuse    = (const float*)d_in[1];
    const float* gc      = (const float*)d_in[2];
    const float* g_w     = (const float*)d_in[3];
    const float* g_b     = (const float*)d_in[4];
    const float* theta_w = (const float*)d_in[5];
    const float* theta_b = (const float*)d_in[6];
    const float* phi_w   = (const float*)d_in[7];
    const float* phi_b   = (const float*)d_in[8];
    const float* W_w     = (const float*)d_in[9];
    const float* W_b     = (const float*)d_in[10];
    const float* bn_g    = (const float*)d_in[11];
    const float* bn_b    = (const float*)d_in[12];
    const float* bn_m    = (const float*)d_in[13];
    const float* bn_v    = (const float*)d_in[14];
    float* out = (float*)d_out;

    (void)in_sizes; (void)n_in; (void)out_size;

    cudaFuncSetAttribute(attn_kernel, cudaFuncAttributeMaxDynamicSharedMemorySize,
                         ATTN_SMEM_BYTES);
    cudaFuncSetAttribute(proj_mma_kernel, cudaFuncAttributeMaxDynamicSharedMemorySize,
                         PROJ_SMEM_BYTES);

    wt_kernel<<<32, 256>>>(W_w);
    wsplit_kernel<<<96, 256>>>(theta_w, phi_w, g_w);
    splitx_kernel<<<dim3(32, 4, BB), 256>>>(fuse);

    // dedicated high-MLP band copy (was serialized inside proj_mma: 1.4 TB/s)
    copy_kernel<<<8192, 256>>>((const float4*)lc, (const float4*)gc, (float4*)out);

    proj_mma_kernel<<<dim3(32, BB, 3), 256, PROJ_SMEM_BYTES>>>(g_b, theta_b, phi_b);

    attn_kernel<<<dim3(NN / 128, BB), 256, ATTN_SMEM_BYTES>>>();

    wz_kernel<<<dim3(NN / 128, CC / 128, BB), 256>>>(
        fuse, W_b, bn_g, bn_b, bn_m, bn_v, out);
}